// round 4
// baseline (speedup 1.0000x reference)
#include <cuda_runtime.h>
#include <math.h>
#include <stdint.h>

#define NTOK 1024
#define CQ   768
#define CZ   128
#define NH   16
#define DH   48
#define HD   768
#define EPSV 1e-5f
#define INFV 1.0e9f

// ------------- static device scratch (no allocations allowed) -------------
__device__ float g_an[NTOK * CQ];
__device__ float g_q [NTOK * HD];
__device__ float g_k [NTOK * HD];
__device__ float g_v [NTOK * HD];
__device__ float g_g [NTOK * HD];
__device__ float g_og[NTOK * HD];
__device__ float g_bias[(size_t)NH * NTOK * NTOK];   // [h][i][j] 64 MB

// ===========================================================================
// Kernel 1: LayerNorm(a) -> g_an.   1024 blocks x 256 threads.
// ===========================================================================
__global__ __launch_bounds__(256) void ln_a_kernel(const float* __restrict__ a,
                                                   const float* __restrict__ ga,
                                                   const float* __restrict__ ba)
{
    int row = blockIdx.x;
    int tid = threadIdx.x;
    const float* x = a + row * CQ;
    float v0 = x[tid], v1 = x[tid + 256], v2 = x[tid + 512];
    float s = v0 + v1 + v2;
    float q = v0 * v0 + v1 * v1 + v2 * v2;
#pragma unroll
    for (int o = 16; o > 0; o >>= 1) {
        s += __shfl_xor_sync(0xffffffffu, s, o);
        q += __shfl_xor_sync(0xffffffffu, q, o);
    }
    __shared__ float sw[8], qw[8];
    __shared__ float smu, srv;
    if ((tid & 31) == 0) { sw[tid >> 5] = s; qw[tid >> 5] = q; }
    __syncthreads();
    if (tid == 0) {
        float S = 0.f, Q = 0.f;
#pragma unroll
        for (int w = 0; w < 8; w++) { S += sw[w]; Q += qw[w]; }
        float mu = S * (1.f / (float)CQ);
        float var = Q * (1.f / (float)CQ) - mu * mu;
        smu = mu;
        srv = rsqrtf(fmaxf(var, 0.f) + EPSV);
    }
    __syncthreads();
    float mu = smu, r = srv;
    float* o = g_an + row * CQ;
    o[tid]       = (v0 - mu) * r * ga[tid]       + ba[tid];
    o[tid + 256] = (v1 - mu) * r * ga[tid + 256] + ba[tid + 256];
    o[tid + 512] = (v2 - mu) * r * ga[tid + 512] + ba[tid + 512];
}

// ===========================================================================
// Kernel 2: fused QKVG projections. BM=128, BN=128, BK=16, 8x8 microtile.
// grid (24, 8), 256 threads.
// ===========================================================================
__global__ __launch_bounds__(256, 2) void proj_kernel(const float* __restrict__ Wq,
                                                      const float* __restrict__ Wk,
                                                      const float* __restrict__ Wv,
                                                      const float* __restrict__ Wg,
                                                      const float* __restrict__ bg)
{
    const int BK = 16, BN = 128;
    int n0 = blockIdx.x * BN;
    int sel  = n0 / HD;
    int ncol = n0 - sel * HD;
    const float* W = (sel == 0) ? Wq : (sel == 1) ? Wk : (sel == 2) ? Wv : Wg;
    float*       O = (sel == 0) ? g_q : (sel == 1) ? g_k : (sel == 2) ? g_v : g_g;

    __shared__ __align__(16) float As[BK][132];
    __shared__ __align__(16) float Bs[BK][BN];
    int tid = threadIdx.x;
    int tx = tid & 15, ty = tid >> 4;
    int m0 = blockIdx.y * 128;

    float acc[8][8];
#pragma unroll
    for (int i = 0; i < 8; i++)
#pragma unroll
        for (int j = 0; j < 8; j++) acc[i][j] = 0.f;

    for (int k0 = 0; k0 < CQ; k0 += BK) {
#pragma unroll
        for (int t = 0; t < 2; t++) {
            int f = tid + t * 256;
            int m = f >> 2, kq = (f & 3) * 4;
            float4 av = *(const float4*)&g_an[(m0 + m) * CQ + k0 + kq];
            As[kq + 0][m] = av.x; As[kq + 1][m] = av.y;
            As[kq + 2][m] = av.z; As[kq + 3][m] = av.w;
        }
#pragma unroll
        for (int t = 0; t < 2; t++) {
            int f = tid + t * 256;
            int r = f >> 5, c = (f & 31) * 4;
            *(float4*)&Bs[r][c] = *(const float4*)&W[(k0 + r) * HD + ncol + c];
        }
        __syncthreads();
#pragma unroll
        for (int k = 0; k < BK; k++) {
            float a[8], b[8];
            *(float4*)(a)     = *(const float4*)&As[k][ty * 8];
            *(float4*)(a + 4) = *(const float4*)&As[k][ty * 8 + 4];
            *(float4*)(b)     = *(const float4*)&Bs[k][tx * 8];
            *(float4*)(b + 4) = *(const float4*)&Bs[k][tx * 8 + 4];
#pragma unroll
            for (int i = 0; i < 8; i++)
#pragma unroll
                for (int j = 0; j < 8; j++)
                    acc[i][j] = fmaf(a[i], b[j], acc[i][j]);
        }
        __syncthreads();
    }

    const float scaleq = 0.14433756729740643f;   // 1/sqrt(48)
#pragma unroll
    for (int i = 0; i < 8; i++) {
        int m = m0 + ty * 8 + i;
#pragma unroll
        for (int j0 = 0; j0 < 8; j0 += 4) {
            float v[4];
#pragma unroll
            for (int u = 0; u < 4; u++) {
                float val = acc[i][j0 + u];
                int c = ncol + tx * 8 + j0 + u;
                if (sel == 0) val *= scaleq;
                else if (sel == 3) val = 1.f / (1.f + __expf(-(val + bg[c])));
                v[u] = val;
            }
            float4 o4; o4.x = v[0]; o4.y = v[1]; o4.z = v[2]; o4.w = v[3];
            *(float4*)&O[m * HD + ncol + tx * 8 + j0] = o4;
        }
    }
}

// ===========================================================================
// Kernel 3: pair bias with fused LayerNorm (algebraic).
//   bias[h][i][j] = r_ij*(dot(z_ij, wg_h) - mu_ij*S_h) + Bc_h
// 128 threads (4 warps); microtile 4h (tx*4) x 2j (rows ty, ty+32).
// Grid (16 j-tiles, 1024 i). smem ~42KB -> 5 blocks/SM = 20 warps/SM.
// ===========================================================================
__global__ __launch_bounds__(128) void pairbias_kernel(const float* __restrict__ z,
                                                       const float* __restrict__ gz,
                                                       const float* __restrict__ bz,
                                                       const float* __restrict__ wz)
{
    __shared__ __align__(16) float4 zs4[32 * 65];      // [cq][row], stride 65
    __shared__ __align__(16) float wgs[CZ][NH];
    __shared__ float Ssh[NH], Bcsh[NH], mus[64], rvs[64];
    int tid = threadIdx.x;
    int i = blockIdx.y;
    int j0 = blockIdx.x * 64;

    for (int t = tid; t < CZ * NH; t += 128) {
        int c = t >> 4, h = t & 15;
        wgs[c][h] = gz[c] * wz[c * NH + h];
    }
    const float4* zb4 = (const float4*)(z + ((size_t)i * NTOK + j0) * CZ);
    for (int t = tid; t < 2048; t += 128) {
        int r = t >> 5, cq = t & 31;
        zs4[cq * 65 + r] = zb4[r * 32 + cq];
    }
    __syncthreads();
    if (tid < NH) {
        float S = 0.f, Bc = 0.f;
        for (int c = 0; c < CZ; c++) { S += wgs[c][tid]; Bc += bz[c] * wz[c * NH + tid]; }
        Ssh[tid] = S; Bcsh[tid] = Bc;
    }
    if (tid < 64) {   // per-row stats
        float s = 0.f, sq = 0.f;
        for (int cq = 0; cq < 32; cq++) {
            float4 v = zs4[cq * 65 + tid];
            s += v.x + v.y + v.z + v.w;
            sq = fmaf(v.x, v.x, sq); sq = fmaf(v.y, v.y, sq);
            sq = fmaf(v.z, v.z, sq); sq = fmaf(v.w, v.w, sq);
        }
        float mu = s * (1.f / (float)CZ);
        mus[tid] = mu;
        rvs[tid] = rsqrtf(fmaxf(sq * (1.f / (float)CZ) - mu * mu, 0.f) + EPSV);
    }
    __syncthreads();

    int tx = tid & 3, ty = tid >> 2;     // tx: head quad, ty: base row (0..31)
    int h0 = tx * 4;
    float acc[2][4];                     // [row u][head w]
#pragma unroll
    for (int u = 0; u < 2; u++)
#pragma unroll
        for (int w = 0; w < 4; w++) acc[u][w] = 0.f;

    for (int cq = 0; cq < 32; cq++) {
        float za[2][4];
        *(float4*)za[0] = zs4[cq * 65 + ty];
        *(float4*)za[1] = zs4[cq * 65 + ty + 32];
#pragma unroll
        for (int k = 0; k < 4; k++) {
            float4 w4 = *(const float4*)&wgs[cq * 4 + k][h0];
#pragma unroll
            for (int u = 0; u < 2; u++) {
                acc[u][0] = fmaf(za[u][k], w4.x, acc[u][0]);
                acc[u][1] = fmaf(za[u][k], w4.y, acc[u][1]);
                acc[u][2] = fmaf(za[u][k], w4.z, acc[u][2]);
                acc[u][3] = fmaf(za[u][k], w4.w, acc[u][3]);
            }
        }
    }
#pragma unroll
    for (int u = 0; u < 2; u++) {
        int r = ty + 32 * u;
        float mu = mus[r], rv = rvs[r];
#pragma unroll
        for (int w = 0; w < 4; w++) {
            int h = h0 + w;
            g_bias[((size_t)h * NTOK + i) * NTOK + j0 + r] =
                rv * (acc[u][w] - mu * Ssh[h]) + Bcsh[h];
        }
    }
}

// ===========================================================================
// Kernel 4: flash attention with bias + gating.
// Block = (64-query tile, 1 head). 512 threads: tx 0..15 (j quad),
// ty 0..31 (2 q rows each). K and V both staged transposed at tile start
// (3 barriers per KV tile). 27 warps/SM resident.
// ===========================================================================
__global__ __launch_bounds__(512) void attn_kernel(const float* __restrict__ mask)
{
    int h  = blockIdx.y;
    int qb = blockIdx.x * 64;
    int tid = threadIdx.x;
    int tx = tid & 15, ty = tid >> 4;
    int r0 = ty * 2;

    __shared__ __align__(16) float qs[64][52];
    __shared__ __align__(16) float ks[DH][68];      // K^T
    __shared__ __align__(16) float vs[DH][68];      // V^T
    __shared__ __align__(16) float ps[64][68];

    for (int t = tid; t < 64 * 12; t += 512) {
        int r = t / 12, c4 = (t % 12) * 4;
        *(float4*)&qs[r][c4] = *(const float4*)&g_q[(qb + r) * HD + h * DH + c4];
    }

    float mrow[2], lrow[2], o[2][3];
#pragma unroll
    for (int i = 0; i < 2; i++) {
        mrow[i] = -1e30f; lrow[i] = 0.f;
        o[i][0] = o[i][1] = o[i][2] = 0.f;
    }
    float mq[2];
#pragma unroll
    for (int i = 0; i < 2; i++) mq[i] = mask[qb + r0 + i];

    for (int jt = 0; jt < 16; jt++) {
        int j0 = jt * 64;
        __syncthreads();                      // prev-iter ps/vs reads done
        for (int t = tid; t < 64 * 12; t += 512) {
            int j = t & 63, d4 = (t >> 6) * 4;
            float4 v = *(const float4*)&g_k[(j0 + j) * HD + h * DH + d4];
            ks[d4 + 0][j] = v.x; ks[d4 + 1][j] = v.y;
            ks[d4 + 2][j] = v.z; ks[d4 + 3][j] = v.w;
        }
        for (int t = tid; t < 64 * 12; t += 512) {
            int j = t & 63, d4 = (t >> 6) * 4;
            float4 v = *(const float4*)&g_v[(j0 + j) * HD + h * DH + d4];
            vs[d4 + 0][j] = v.x; vs[d4 + 1][j] = v.y;
            vs[d4 + 2][j] = v.z; vs[d4 + 3][j] = v.w;
        }
        __syncthreads();

        float s[2][4];
#pragma unroll
        for (int i = 0; i < 2; i++)
#pragma unroll
            for (int u = 0; u < 4; u++) s[i][u] = 0.f;

#pragma unroll
        for (int d = 0; d < DH; d += 4) {
            float qa[2][4];
            *(float4*)qa[0] = *(const float4*)&qs[r0][d];
            *(float4*)qa[1] = *(const float4*)&qs[r0 + 1][d];
#pragma unroll
            for (int dd = 0; dd < 4; dd++) {
                float4 b4 = *(const float4*)&ks[d + dd][tx * 4];
#pragma unroll
                for (int i = 0; i < 2; i++) {
                    float a = qa[i][dd];
                    s[i][0] = fmaf(a, b4.x, s[i][0]);
                    s[i][1] = fmaf(a, b4.y, s[i][1]);
                    s[i][2] = fmaf(a, b4.z, s[i][2]);
                    s[i][3] = fmaf(a, b4.w, s[i][3]);
                }
            }
        }
        float mk[4];
#pragma unroll
        for (int u = 0; u < 4; u++) mk[u] = mask[j0 + tx * 4 + u];
#pragma unroll
        for (int i = 0; i < 2; i++) {
            const float* bp = g_bias + ((size_t)h * NTOK + qb + r0 + i) * NTOK + j0 + tx * 4;
            float4 b4 = *(const float4*)bp;
            s[i][0] += b4.x + INFV * (mq[i] * mk[0] - 1.f);
            s[i][1] += b4.y + INFV * (mq[i] * mk[1] - 1.f);
            s[i][2] += b4.z + INFV * (mq[i] * mk[2] - 1.f);
            s[i][3] += b4.w + INFV * (mq[i] * mk[3] - 1.f);
        }
        // online softmax; row state replicated across the 16 tx lanes
#pragma unroll
        for (int i = 0; i < 2; i++) {
            float mx = fmaxf(fmaxf(s[i][0], s[i][1]), fmaxf(s[i][2], s[i][3]));
#pragma unroll
            for (int off = 1; off < 16; off <<= 1)
                mx = fmaxf(mx, __shfl_xor_sync(0xffffffffu, mx, off));
            float mnew = fmaxf(mrow[i], mx);
            float scale = __expf(mrow[i] - mnew);
            float psum = 0.f;
#pragma unroll
            for (int u = 0; u < 4; u++) { s[i][u] = __expf(s[i][u] - mnew); psum += s[i][u]; }
#pragma unroll
            for (int off = 1; off < 16; off <<= 1)
                psum += __shfl_xor_sync(0xffffffffu, psum, off);
            lrow[i] = lrow[i] * scale + psum;
            mrow[i] = mnew;
            o[i][0] *= scale; o[i][1] *= scale; o[i][2] *= scale;
            *(float4*)&ps[r0 + i][tx * 4] = make_float4(s[i][0], s[i][1], s[i][2], s[i][3]);
        }
        __syncthreads();                      // ks reads done, ps visible

        int d0 = tx * 3;
        for (int j = 0; j < 64; j += 4) {
            float pa[2][4], va[3][4];
            *(float4*)pa[0] = *(const float4*)&ps[r0][j];
            *(float4*)pa[1] = *(const float4*)&ps[r0 + 1][j];
            *(float4*)va[0] = *(const float4*)&vs[d0][j];
            *(float4*)va[1] = *(const float4*)&vs[d0 + 1][j];
            *(float4*)va[2] = *(const float4*)&vs[d0 + 2][j];
#pragma unroll
            for (int jj = 0; jj < 4; jj++)
#pragma unroll
                for (int i = 0; i < 2; i++) {
                    float p = pa[i][jj];
                    o[i][0] = fmaf(p, va[0][jj], o[i][0]);
                    o[i][1] = fmaf(p, va[1][jj], o[i][1]);
                    o[i][2] = fmaf(p, va[2][jj], o[i][2]);
                }
        }
    }
#pragma unroll
    for (int i = 0; i < 2; i++) {
        int q = qb + r0 + i;
        float inv = 1.f / lrow[i];
        int base = q * HD + h * DH + tx * 3;
#pragma unroll
        for (int u = 0; u < 3; u++)
            g_og[base + u] = o[i][u] * inv * g_g[base + u];
    }
}

// ===========================================================================
// Kernel 5: output projection.  og[1024,768] @ w_o[768,768] + b_o -> out.
// 64x64 tiles -> grid (12,16) = 192 blocks. 256 threads, 4x4 microtile.
// ===========================================================================
__global__ __launch_bounds__(256, 4) void outproj_kernel(const float* __restrict__ W,
                                                         const float* __restrict__ bo,
                                                         float* __restrict__ out)
{
    const int BK = 16;
    int n0 = blockIdx.x * 64;
    int m0 = blockIdx.y * 64;

    __shared__ __align__(16) float As[BK][68];
    __shared__ __align__(16) float Bs[BK][64];
    int tid = threadIdx.x;
    int tx = tid & 15, ty = tid >> 4;

    float acc[4][4];
#pragma unroll
    for (int i = 0; i < 4; i++)
#pragma unroll
        for (int j = 0; j < 4; j++) acc[i][j] = 0.f;

    for (int k0 = 0; k0 < HD; k0 += BK) {
        {
            int m = tid >> 2, kq = (tid & 3) * 4;
            float4 av = *(const float4*)&g_og[(m0 + m) * HD + k0 + kq];
            As[kq + 0][m] = av.x; As[kq + 1][m] = av.y;
            As[kq + 2][m] = av.z; As[kq + 3][m] = av.w;
        }
        {
            int r = tid >> 4, c = (tid & 15) * 4;
            *(float4*)&Bs[r][c] = *(const float4*)&W[(k0 + r) * CQ + n0 + c];
        }
        __syncthreads();
#pragma unroll
        for (int k = 0; k < BK; k++) {
            float a[4], b[4];
            *(float4*)a = *(const float4*)&As[k][ty * 4];
            *(float4*)b = *(const float4*)&Bs[k][tx * 4];
#pragma unroll
            for (int i = 0; i < 4; i++)
#pragma unroll
                for (int j = 0; j < 4; j++)
                    acc[i][j] = fmaf(a[i], b[j], acc[i][j]);
        }
        __syncthreads();
    }
#pragma unroll
    for (int i = 0; i < 4; i++) {
        int m = m0 + ty * 4 + i;
        int c = n0 + tx * 4;
        float4 o4;
        o4.x = acc[i][0] + bo[c + 0];
        o4.y = acc[i][1] + bo[c + 1];
        o4.z = acc[i][2] + bo[c + 2];
        o4.w = acc[i][3] + bo[c + 3];
        *(float4*)&out[m * CQ + c] = o4;
    }
}

// ===========================================================================
extern "C" void kernel_launch(void* const* d_in, const int* in_sizes, int n_in,
                              void* d_out, int out_size)
{
    const float* a    = (const float*)d_in[0];
    const float* z    = (const float*)d_in[1];
    const float* mask = (const float*)d_in[2];
    const float* g_a  = (const float*)d_in[3];
    const float* b_a  = (const float*)d_in[4];
    const float* g_z  = (const float*)d_in[5];
    const float* b_z  = (const float*)d_in[6];
    const float* w_z  = (const float*)d_in[7];
    const float* w_q  = (const float*)d_in[8];
    const float* w_k  = (const float*)d_in[9];
    const float* w_v  = (const float*)d_in[10];
    const float* w_g  = (const float*)d_in[11];
    const float* b_g  = (const float*)d_in[12];
    const float* w_o  = (const float*)d_in[13];
    const float* b_o  = (const float*)d_in[14];
    float* out = (float*)d_out;

    ln_a_kernel<<<NTOK, 256>>>(a, g_a, b_a);
    proj_kernel<<<dim3(24, 8), 256>>>(w_q, w_k, w_v, w_g, b_g);
    pairbias_kernel<<<dim3(16, NTOK), 128>>>(z, g_z, b_z, w_z);
    attn_kernel<<<dim3(16, NH), 512>>>(mask);
    outproj_kernel<<<dim3(12, 16), 256>>>(w_o, b_o, out);
}

// round 5
// speedup vs baseline: 1.1976x; 1.1976x over previous
#include <cuda_runtime.h>
#include <math.h>
#include <stdint.h>

#define NTOK 1024
#define CQ   768
#define CZ   128
#define NH   16
#define DH   48
#define HD   768
#define EPSV 1e-5f
#define INFV 1.0e9f
#define NSPLIT 2

// ------------- static device scratch (no allocations allowed) -------------
__device__ float g_an[NTOK * CQ];
__device__ float g_q [NTOK * HD];
__device__ float g_k [NTOK * HD];
__device__ float g_v [NTOK * HD];
__device__ float g_g [NTOK * HD];
__device__ float g_og[NTOK * HD];
__device__ float g_bias[(size_t)NH * NTOK * NTOK];          // [h][i][j] 64 MB
__device__ float g_po[NSPLIT * NH * NTOK * DH];             // unnormalized o partials
__device__ float g_pm[NSPLIT * NH * NTOK];                  // running max partials
__device__ float g_pl[NSPLIT * NH * NTOK];                  // running sum partials

// ===========================================================================
// Kernel 1: LayerNorm(a) -> g_an.   1024 blocks x 256 threads.
// ===========================================================================
__global__ __launch_bounds__(256) void ln_a_kernel(const float* __restrict__ a,
                                                   const float* __restrict__ ga,
                                                   const float* __restrict__ ba)
{
    int row = blockIdx.x;
    int tid = threadIdx.x;
    const float* x = a + row * CQ;
    float v0 = x[tid], v1 = x[tid + 256], v2 = x[tid + 512];
    float s = v0 + v1 + v2;
    float q = v0 * v0 + v1 * v1 + v2 * v2;
#pragma unroll
    for (int o = 16; o > 0; o >>= 1) {
        s += __shfl_xor_sync(0xffffffffu, s, o);
        q += __shfl_xor_sync(0xffffffffu, q, o);
    }
    __shared__ float sw[8], qw[8];
    __shared__ float smu, srv;
    if ((tid & 31) == 0) { sw[tid >> 5] = s; qw[tid >> 5] = q; }
    __syncthreads();
    if (tid == 0) {
        float S = 0.f, Q = 0.f;
#pragma unroll
        for (int w = 0; w < 8; w++) { S += sw[w]; Q += qw[w]; }
        float mu = S * (1.f / (float)CQ);
        float var = Q * (1.f / (float)CQ) - mu * mu;
        smu = mu;
        srv = rsqrtf(fmaxf(var, 0.f) + EPSV);
    }
    __syncthreads();
    float mu = smu, r = srv;
    float* o = g_an + row * CQ;
    o[tid]       = (v0 - mu) * r * ga[tid]       + ba[tid];
    o[tid + 256] = (v1 - mu) * r * ga[tid + 256] + ba[tid + 256];
    o[tid + 512] = (v2 - mu) * r * ga[tid + 512] + ba[tid + 512];
}

// ===========================================================================
// Kernel 2: fused QKVG projections. BM=128, BN=128, BK=16, 8x8 microtile.
// grid (24, 8), 256 threads.   (R2 configuration — unchanged)
// ===========================================================================
__global__ __launch_bounds__(256, 2) void proj_kernel(const float* __restrict__ Wq,
                                                      const float* __restrict__ Wk,
                                                      const float* __restrict__ Wv,
                                                      const float* __restrict__ Wg,
                                                      const float* __restrict__ bg)
{
    const int BK = 16, BN = 128;
    int n0 = blockIdx.x * BN;
    int sel  = n0 / HD;
    int ncol = n0 - sel * HD;
    const float* W = (sel == 0) ? Wq : (sel == 1) ? Wk : (sel == 2) ? Wv : Wg;
    float*       O = (sel == 0) ? g_q : (sel == 1) ? g_k : (sel == 2) ? g_v : g_g;

    __shared__ __align__(16) float As[BK][132];
    __shared__ __align__(16) float Bs[BK][BN];
    int tid = threadIdx.x;
    int tx = tid & 15, ty = tid >> 4;
    int m0 = blockIdx.y * 128;

    float acc[8][8];
#pragma unroll
    for (int i = 0; i < 8; i++)
#pragma unroll
        for (int j = 0; j < 8; j++) acc[i][j] = 0.f;

    for (int k0 = 0; k0 < CQ; k0 += BK) {
#pragma unroll
        for (int t = 0; t < 2; t++) {
            int f = tid + t * 256;
            int m = f >> 2, kq = (f & 3) * 4;
            float4 av = *(const float4*)&g_an[(m0 + m) * CQ + k0 + kq];
            As[kq + 0][m] = av.x; As[kq + 1][m] = av.y;
            As[kq + 2][m] = av.z; As[kq + 3][m] = av.w;
        }
#pragma unroll
        for (int t = 0; t < 2; t++) {
            int f = tid + t * 256;
            int r = f >> 5, c = (f & 31) * 4;
            *(float4*)&Bs[r][c] = *(const float4*)&W[(k0 + r) * HD + ncol + c];
        }
        __syncthreads();
#pragma unroll
        for (int k = 0; k < BK; k++) {
            float a[8], b[8];
            *(float4*)(a)     = *(const float4*)&As[k][ty * 8];
            *(float4*)(a + 4) = *(const float4*)&As[k][ty * 8 + 4];
            *(float4*)(b)     = *(const float4*)&Bs[k][tx * 8];
            *(float4*)(b + 4) = *(const float4*)&Bs[k][tx * 8 + 4];
#pragma unroll
            for (int i = 0; i < 8; i++)
#pragma unroll
                for (int j = 0; j < 8; j++)
                    acc[i][j] = fmaf(a[i], b[j], acc[i][j]);
        }
        __syncthreads();
    }

    const float scaleq = 0.14433756729740643f;   // 1/sqrt(48)
#pragma unroll
    for (int i = 0; i < 8; i++) {
        int m = m0 + ty * 8 + i;
#pragma unroll
        for (int j0 = 0; j0 < 8; j0 += 4) {
            float v[4];
#pragma unroll
            for (int u = 0; u < 4; u++) {
                float val = acc[i][j0 + u];
                int c = ncol + tx * 8 + j0 + u;
                if (sel == 0) val *= scaleq;
                else if (sel == 3) val = 1.f / (1.f + __expf(-(val + bg[c])));
                v[u] = val;
            }
            float4 o4; o4.x = v[0]; o4.y = v[1]; o4.z = v[2]; o4.w = v[3];
            *(float4*)&O[m * HD + ncol + tx * 8 + j0] = o4;
        }
    }
}

// ===========================================================================
// Kernel 3: pair bias with fused LayerNorm (algebraic).  (R2 configuration)
// 64 threads; microtile 4h x 4j (rows ty + 16u). Grid (16 j-tiles, 1024 i).
// ===========================================================================
__global__ __launch_bounds__(64) void pairbias_kernel(const float* __restrict__ z,
                                                      const float* __restrict__ gz,
                                                      const float* __restrict__ bz,
                                                      const float* __restrict__ wz)
{
    __shared__ __align__(16) float4 zs4[32 * 65];      // [cq][row], stride 65
    __shared__ __align__(16) float wgs[CZ][NH];
    __shared__ float Ssh[NH], Bcsh[NH], mus[64], rvs[64];
    int tid = threadIdx.x;
    int i = blockIdx.y;
    int j0 = blockIdx.x * 64;

    for (int t = tid; t < CZ * NH; t += 64) {
        int c = t >> 4, h = t & 15;
        wgs[c][h] = gz[c] * wz[c * NH + h];
    }
    const float4* zb4 = (const float4*)(z + ((size_t)i * NTOK + j0) * CZ);
    for (int t = tid; t < 2048; t += 64) {
        int r = t >> 5, cq = t & 31;
        zs4[cq * 65 + r] = zb4[r * 32 + cq];
    }
    __syncthreads();
    if (tid < NH) {
        float S = 0.f, Bc = 0.f;
        for (int c = 0; c < CZ; c++) { S += wgs[c][tid]; Bc += bz[c] * wz[c * NH + tid]; }
        Ssh[tid] = S; Bcsh[tid] = Bc;
    }
    {   // per-row stats: one thread per j row
        float s = 0.f, sq = 0.f;
        for (int cq = 0; cq < 32; cq++) {
            float4 v = zs4[cq * 65 + tid];
            s += v.x + v.y + v.z + v.w;
            sq = fmaf(v.x, v.x, sq); sq = fmaf(v.y, v.y, sq);
            sq = fmaf(v.z, v.z, sq); sq = fmaf(v.w, v.w, sq);
        }
        float mu = s * (1.f / (float)CZ);
        mus[tid] = mu;
        rvs[tid] = rsqrtf(fmaxf(sq * (1.f / (float)CZ) - mu * mu, 0.f) + EPSV);
    }
    __syncthreads();

    int tx = tid & 3, ty = tid >> 2;     // tx: head quad, ty: base row (0..15)
    int h0 = tx * 4;
    float acc[4][4];                     // [row u][head w]
#pragma unroll
    for (int u = 0; u < 4; u++)
#pragma unroll
        for (int w = 0; w < 4; w++) acc[u][w] = 0.f;

    for (int cq = 0; cq < 32; cq++) {
        float za[4][4];
        *(float4*)za[0] = zs4[cq * 65 + ty];
        *(float4*)za[1] = zs4[cq * 65 + ty + 16];
        *(float4*)za[2] = zs4[cq * 65 + ty + 32];
        *(float4*)za[3] = zs4[cq * 65 + ty + 48];
#pragma unroll
        for (int k = 0; k < 4; k++) {
            float4 w4 = *(const float4*)&wgs[cq * 4 + k][h0];
#pragma unroll
            for (int u = 0; u < 4; u++) {
                acc[u][0] = fmaf(za[u][k], w4.x, acc[u][0]);
                acc[u][1] = fmaf(za[u][k], w4.y, acc[u][1]);
                acc[u][2] = fmaf(za[u][k], w4.z, acc[u][2]);
                acc[u][3] = fmaf(za[u][k], w4.w, acc[u][3]);
            }
        }
    }
#pragma unroll
    for (int u = 0; u < 4; u++) {
        int r = ty + 16 * u;
        float mu = mus[r], rv = rvs[r];
#pragma unroll
        for (int w = 0; w < 4; w++) {
            int h = h0 + w;
            g_bias[((size_t)h * NTOK + i) * NTOK + j0 + r] =
                rv * (acc[u][w] - mu * Ssh[h]) + Bcsh[h];
        }
    }
}

// ===========================================================================
// Kernel 4: flash attention, split-KV x2, bias added, partials out.
// Block = (64-q tile, head, split). 256 threads: tx 0..15 (j quad),
// ty 0..15 (4 q rows). K^T and V^T staged together (3 barriers / KV tile).
// Score microtile 4q x 4j (16 FMA / LDS.128), PV 4q x 3d on V^T.
// ===========================================================================
__global__ __launch_bounds__(256) void attn_kernel(const float* __restrict__ mask)
{
    int h     = blockIdx.y;
    int qb    = blockIdx.x * 64;
    int split = blockIdx.z;
    int tid = threadIdx.x;
    int tx = tid & 15, ty = tid >> 4;
    int r0 = ty * 4;

    __shared__ __align__(16) float qs[64][52];
    __shared__ __align__(16) float ks[DH][68];      // K^T
    __shared__ __align__(16) float vs[DH][68];      // V^T
    __shared__ __align__(16) float ps[64][68];

    for (int t = tid; t < 64 * 12; t += 256) {
        int r = t / 12, c4 = (t % 12) * 4;
        *(float4*)&qs[r][c4] = *(const float4*)&g_q[(qb + r) * HD + h * DH + c4];
    }

    float mrow[4], lrow[4], o[4][3];
#pragma unroll
    for (int i = 0; i < 4; i++) {
        mrow[i] = -1e30f; lrow[i] = 0.f;
        o[i][0] = o[i][1] = o[i][2] = 0.f;
    }
    float mq[4];
#pragma unroll
    for (int i = 0; i < 4; i++) mq[i] = mask[qb + r0 + i];

    for (int jt = split * 8; jt < split * 8 + 8; jt++) {
        int j0 = jt * 64;
        __syncthreads();                      // prev-iter ps/vs/ks reads done
        for (int t = tid; t < 64 * 12; t += 256) {
            int j = t & 63, d4 = (t >> 6) * 4;
            float4 v = *(const float4*)&g_k[(j0 + j) * HD + h * DH + d4];
            ks[d4 + 0][j] = v.x; ks[d4 + 1][j] = v.y;
            ks[d4 + 2][j] = v.z; ks[d4 + 3][j] = v.w;
        }
        for (int t = tid; t < 64 * 12; t += 256) {
            int j = t & 63, d4 = (t >> 6) * 4;
            float4 v = *(const float4*)&g_v[(j0 + j) * HD + h * DH + d4];
            vs[d4 + 0][j] = v.x; vs[d4 + 1][j] = v.y;
            vs[d4 + 2][j] = v.z; vs[d4 + 3][j] = v.w;
        }
        __syncthreads();

        float s[4][4];
#pragma unroll
        for (int i = 0; i < 4; i++)
#pragma unroll
            for (int u = 0; u < 4; u++) s[i][u] = 0.f;

        for (int d = 0; d < DH; d += 4) {
            float qa[4][4];
#pragma unroll
            for (int i = 0; i < 4; i++)
                *(float4*)qa[i] = *(const float4*)&qs[r0 + i][d];
#pragma unroll
            for (int dd = 0; dd < 4; dd++) {
                float4 b4 = *(const float4*)&ks[d + dd][tx * 4];
#pragma unroll
                for (int i = 0; i < 4; i++) {
                    float a = qa[i][dd];
                    s[i][0] = fmaf(a, b4.x, s[i][0]);
                    s[i][1] = fmaf(a, b4.y, s[i][1]);
                    s[i][2] = fmaf(a, b4.z, s[i][2]);
                    s[i][3] = fmaf(a, b4.w, s[i][3]);
                }
            }
        }
        float mk[4];
#pragma unroll
        for (int u = 0; u < 4; u++) mk[u] = mask[j0 + tx * 4 + u];
#pragma unroll
        for (int i = 0; i < 4; i++) {
            const float* bp = g_bias + ((size_t)h * NTOK + qb + r0 + i) * NTOK + j0 + tx * 4;
            float4 b4 = *(const float4*)bp;
            s[i][0] += b4.x + INFV * (mq[i] * mk[0] - 1.f);
            s[i][1] += b4.y + INFV * (mq[i] * mk[1] - 1.f);
            s[i][2] += b4.z + INFV * (mq[i] * mk[2] - 1.f);
            s[i][3] += b4.w + INFV * (mq[i] * mk[3] - 1.f);
        }
        // online softmax; row state replicated across the 16 tx lanes
#pragma unroll
        for (int i = 0; i < 4; i++) {
            float mx = fmaxf(fmaxf(s[i][0], s[i][1]), fmaxf(s[i][2], s[i][3]));
#pragma unroll
            for (int off = 1; off < 16; off <<= 1)
                mx = fmaxf(mx, __shfl_xor_sync(0xffffffffu, mx, off));
            float mnew = fmaxf(mrow[i], mx);
            float scale = __expf(mrow[i] - mnew);
            float psum = 0.f;
#pragma unroll
            for (int u = 0; u < 4; u++) { s[i][u] = __expf(s[i][u] - mnew); psum += s[i][u]; }
#pragma unroll
            for (int off = 1; off < 16; off <<= 1)
                psum += __shfl_xor_sync(0xffffffffu, psum, off);
            lrow[i] = lrow[i] * scale + psum;
            mrow[i] = mnew;
            o[i][0] *= scale; o[i][1] *= scale; o[i][2] *= scale;
            *(float4*)&ps[r0 + i][tx * 4] = make_float4(s[i][0], s[i][1], s[i][2], s[i][3]);
        }
        __syncthreads();                      // ks/vs reads pending, ps visible

        int d0 = tx * 3;
        for (int j = 0; j < 64; j += 4) {
            float pa[4][4], va[3][4];
#pragma unroll
            for (int i = 0; i < 4; i++)
                *(float4*)pa[i] = *(const float4*)&ps[r0 + i][j];
            *(float4*)va[0] = *(const float4*)&vs[d0][j];
            *(float4*)va[1] = *(const float4*)&vs[d0 + 1][j];
            *(float4*)va[2] = *(const float4*)&vs[d0 + 2][j];
#pragma unroll
            for (int jj = 0; jj < 4; jj++)
#pragma unroll
                for (int i = 0; i < 4; i++) {
                    float p = pa[i][jj];
                    o[i][0] = fmaf(p, va[0][jj], o[i][0]);
                    o[i][1] = fmaf(p, va[1][jj], o[i][1]);
                    o[i][2] = fmaf(p, va[2][jj], o[i][2]);
                }
        }
    }
    // write partials (unnormalized o, running m, running l)
#pragma unroll
    for (int i = 0; i < 4; i++) {
        int q = qb + r0 + i;
        int base = ((split * NH + h) * NTOK + q) * DH + tx * 3;
#pragma unroll
        for (int u = 0; u < 3; u++)
            g_po[base + u] = o[i][u];
        if (tx == 0) {
            g_pm[(split * NH + h) * NTOK + q] = mrow[i];
            g_pl[(split * NH + h) * NTOK + q] = lrow[i];
        }
    }
}

// ===========================================================================
// Kernel 4b: merge the two KV splits, normalize, apply gate -> g_og.
// Grid 1024 (one q per block), 256 threads (3 elements each: h = t/16,
// d0 = (t%16)*3).
// ===========================================================================
__global__ __launch_bounds__(256) void merge_kernel()
{
    int q = blockIdx.x;
    int t = threadIdx.x;
    int h = t >> 4;
    int d0 = (t & 15) * 3;

    float m1 = g_pm[(0 * NH + h) * NTOK + q];
    float m2 = g_pm[(1 * NH + h) * NTOK + q];
    float l1 = g_pl[(0 * NH + h) * NTOK + q];
    float l2 = g_pl[(1 * NH + h) * NTOK + q];
    float M  = fmaxf(m1, m2);
    float w1 = __expf(m1 - M), w2 = __expf(m2 - M);
    float inv = 1.f / (l1 * w1 + l2 * w2);

    int b1 = ((0 * NH + h) * NTOK + q) * DH + d0;
    int b2 = ((1 * NH + h) * NTOK + q) * DH + d0;
    int go = q * HD + h * DH + d0;
#pragma unroll
    for (int u = 0; u < 3; u++) {
        float val = (g_po[b1 + u] * w1 + g_po[b2 + u] * w2) * inv;
        g_og[go + u] = val * g_g[go + u];
    }
}

// ===========================================================================
// Kernel 5: output projection.  og[1024,768] @ w_o[768,768] + b_o -> out.
// 64x64 tiles -> grid (12,16) = 192 blocks. 256 threads, 4x4 microtile.
// ===========================================================================
__global__ __launch_bounds__(256, 4) void outproj_kernel(const float* __restrict__ W,
                                                         const float* __restrict__ bo,
                                                         float* __restrict__ out)
{
    const int BK = 16;
    int n0 = blockIdx.x * 64;
    int m0 = blockIdx.y * 64;

    __shared__ __align__(16) float As[BK][68];
    __shared__ __align__(16) float Bs[BK][64];
    int tid = threadIdx.x;
    int tx = tid & 15, ty = tid >> 4;

    float acc[4][4];
#pragma unroll
    for (int i = 0; i < 4; i++)
#pragma unroll
        for (int j = 0; j < 4; j++) acc[i][j] = 0.f;

    for (int k0 = 0; k0 < HD; k0 += BK) {
        {
            int m = tid >> 2, kq = (tid & 3) * 4;
            float4 av = *(const float4*)&g_og[(m0 + m) * HD + k0 + kq];
            As[kq + 0][m] = av.x; As[kq + 1][m] = av.y;
            As[kq + 2][m] = av.z; As[kq + 3][m] = av.w;
        }
        {
            int r = tid >> 4, c = (tid & 15) * 4;
            *(float4*)&Bs[r][c] = *(const float4*)&W[(k0 + r) * CQ + n0 + c];
        }
        __syncthreads();
#pragma unroll
        for (int k = 0; k < BK; k++) {
            float a[4], b[4];
            *(float4*)a = *(const float4*)&As[k][ty * 4];
            *(float4*)b = *(const float4*)&Bs[k][tx * 4];
#pragma unroll
            for (int i = 0; i < 4; i++)
#pragma unroll
                for (int j = 0; j < 4; j++)
                    acc[i][j] = fmaf(a[i], b[j], acc[i][j]);
        }
        __syncthreads();
    }
#pragma unroll
    for (int i = 0; i < 4; i++) {
        int m = m0 + ty * 4 + i;
        int c = n0 + tx * 4;
        float4 o4;
        o4.x = acc[i][0] + bo[c + 0];
        o4.y = acc[i][1] + bo[c + 1];
        o4.z = acc[i][2] + bo[c + 2];
        o4.w = acc[i][3] + bo[c + 3];
        *(float4*)&out[m * CQ + c] = o4;
    }
}

// ===========================================================================
extern "C" void kernel_launch(void* const* d_in, const int* in_sizes, int n_in,
                              void* d_out, int out_size)
{
    const float* a    = (const float*)d_in[0];
    const float* z    = (const float*)d_in[1];
    const float* mask = (const float*)d_in[2];
    const float* g_a  = (const float*)d_in[3];
    const float* b_a  = (const float*)d_in[4];
    const float* g_z  = (const float*)d_in[5];
    const float* b_z  = (const float*)d_in[6];
    const float* w_z  = (const float*)d_in[7];
    const float* w_q  = (const float*)d_in[8];
    const float* w_k  = (const float*)d_in[9];
    const float* w_v  = (const float*)d_in[10];
    const float* w_g  = (const float*)d_in[11];
    const float* b_g  = (const float*)d_in[12];
    const float* w_o  = (const float*)d_in[13];
    const float* b_o  = (const float*)d_in[14];
    float* out = (float*)d_out;

    ln_a_kernel<<<NTOK, 256>>>(a, g_a, b_a);
    proj_kernel<<<dim3(24, 8), 256>>>(w_q, w_k, w_v, w_g, b_g);
    pairbias_kernel<<<dim3(16, NTOK), 64>>>(z, g_z, b_z, w_z);
    attn_kernel<<<dim3(16, NH, NSPLIT), 256>>>(mask);
    merge_kernel<<<NTOK, 256>>>();
    outproj_kernel<<<dim3(12, 16), 256>>>(w_o, b_o, out);
}

// round 6
// speedup vs baseline: 1.4844x; 1.2395x over previous
#include <cuda_runtime.h>
#include <math.h>
#include <stdint.h>

#define NTOK 1024
#define CQ   768
#define CZ   128
#define NH   16
#define DH   48
#define HD   768
#define EPSV 1e-5f
#define INFV 1.0e9f

// ------------- static device scratch (no allocations allowed) -------------
__device__ float g_an[NTOK * CQ];
__device__ float g_q [NTOK * HD];
__device__ float g_k [NTOK * HD];
__device__ float g_v [NTOK * HD];
__device__ float g_g [NTOK * HD];
__device__ float g_og[NTOK * HD];
__device__ float g_bias[(size_t)NH * NTOK * NTOK];   // [h][i][j] 64 MB

// ------------------------- tf32 mma helpers -------------------------------
__device__ __forceinline__ uint32_t f2tf32(float f) {
    uint32_t r;
    asm("cvt.rna.tf32.f32 %0, %1;" : "=r"(r) : "f"(f));
    return r;
}
__device__ __forceinline__ void mma_tf32(float* d, const uint32_t* a, const uint32_t* b) {
    asm("mma.sync.aligned.m16n8k8.row.col.f32.tf32.tf32.f32 "
        "{%0,%1,%2,%3}, {%4,%5,%6,%7}, {%8,%9}, {%0,%1,%2,%3};"
        : "+f"(d[0]), "+f"(d[1]), "+f"(d[2]), "+f"(d[3])
        : "r"(a[0]), "r"(a[1]), "r"(a[2]), "r"(a[3]), "r"(b[0]), "r"(b[1]));
}

// ===========================================================================
// Kernel 1: LayerNorm(a) -> g_an.   1024 blocks x 256 threads.
// ===========================================================================
__global__ __launch_bounds__(256) void ln_a_kernel(const float* __restrict__ a,
                                                   const float* __restrict__ ga,
                                                   const float* __restrict__ ba)
{
    int row = blockIdx.x;
    int tid = threadIdx.x;
    const float* x = a + row * CQ;
    float v0 = x[tid], v1 = x[tid + 256], v2 = x[tid + 512];
    float s = v0 + v1 + v2;
    float q = v0 * v0 + v1 * v1 + v2 * v2;
#pragma unroll
    for (int o = 16; o > 0; o >>= 1) {
        s += __shfl_xor_sync(0xffffffffu, s, o);
        q += __shfl_xor_sync(0xffffffffu, q, o);
    }
    __shared__ float sw[8], qw[8];
    __shared__ float smu, srv;
    if ((tid & 31) == 0) { sw[tid >> 5] = s; qw[tid >> 5] = q; }
    __syncthreads();
    if (tid == 0) {
        float S = 0.f, Q = 0.f;
#pragma unroll
        for (int w = 0; w < 8; w++) { S += sw[w]; Q += qw[w]; }
        float mu = S * (1.f / (float)CQ);
        float var = Q * (1.f / (float)CQ) - mu * mu;
        smu = mu;
        srv = rsqrtf(fmaxf(var, 0.f) + EPSV);
    }
    __syncthreads();
    float mu = smu, r = srv;
    float* o = g_an + row * CQ;
    o[tid]       = (v0 - mu) * r * ga[tid]       + ba[tid];
    o[tid + 256] = (v1 - mu) * r * ga[tid + 256] + ba[tid + 256];
    o[tid + 512] = (v2 - mu) * r * ga[tid + 512] + ba[tid + 512];
}

// ===========================================================================
// Kernel 2: fused QKVG projections via tf32 mma.sync.
// BM=128, BN=128, BK=32. 256 threads = 8 warps (4m x 2n), warp tile m32n64.
// A smem stride 36, B stride 136 -> fragment LDS conflict-free.
// grid (24 n-blocks, 8 m-blocks).
// ===========================================================================
__global__ __launch_bounds__(256) void proj_kernel(const float* __restrict__ Wq,
                                                   const float* __restrict__ Wk,
                                                   const float* __restrict__ Wv,
                                                   const float* __restrict__ Wg,
                                                   const float* __restrict__ bg)
{
    int n0 = blockIdx.x * 128;
    int sel  = n0 / HD;                  // tile never straddles a weight
    int ncol = n0 - sel * HD;
    const float* W = (sel == 0) ? Wq : (sel == 1) ? Wk : (sel == 2) ? Wv : Wg;
    float*       O = (sel == 0) ? g_q : (sel == 1) ? g_k : (sel == 2) ? g_v : g_g;
    int m0 = blockIdx.y * 128;

    __shared__ uint32_t As[128 * 36];    // tf32 [m][k], stride 36
    __shared__ uint32_t Bs[32 * 136];    // tf32 [k][n], stride 136

    int tid  = threadIdx.x;
    int lane = tid & 31;
    int warp = tid >> 5;
    int wm = warp >> 1, wn = warp & 1;   // 4 x 2 warp grid
    int mw0 = wm * 32, nw0 = wn * 64;
    int lr = lane >> 2, lc = lane & 3;

    float acc[2][8][4];
#pragma unroll
    for (int mt = 0; mt < 2; mt++)
#pragma unroll
        for (int nt = 0; nt < 8; nt++)
#pragma unroll
            for (int u = 0; u < 4; u++) acc[mt][nt][u] = 0.f;

    for (int k0 = 0; k0 < CQ; k0 += 32) {
        // stage A (128x32) and B (32x128) as tf32
#pragma unroll
        for (int it = 0; it < 4; it++) {
            int t = tid + it * 256;
            int r = t >> 3, c4 = t & 7;
            float4 v = *(const float4*)&g_an[(m0 + r) * CQ + k0 + c4 * 4];
            uint32_t* d = &As[r * 36 + c4 * 4];
            d[0] = f2tf32(v.x); d[1] = f2tf32(v.y);
            d[2] = f2tf32(v.z); d[3] = f2tf32(v.w);
        }
#pragma unroll
        for (int it = 0; it < 4; it++) {
            int t = tid + it * 256;
            int r = t >> 5, c4 = t & 31;
            float4 v = *(const float4*)&W[(k0 + r) * HD + ncol + c4 * 4];
            uint32_t* d = &Bs[r * 136 + c4 * 4];
            d[0] = f2tf32(v.x); d[1] = f2tf32(v.y);
            d[2] = f2tf32(v.z); d[3] = f2tf32(v.w);
        }
        __syncthreads();
#pragma unroll
        for (int ks = 0; ks < 4; ks++) {
            int kk = ks * 8;
            uint32_t a[2][4];
#pragma unroll
            for (int mt = 0; mt < 2; mt++) {
                int ar = mw0 + mt * 16 + lr;
                int ac = kk + lc;
                a[mt][0] = As[ar * 36 + ac];
                a[mt][1] = As[(ar + 8) * 36 + ac];
                a[mt][2] = As[ar * 36 + ac + 4];
                a[mt][3] = As[(ar + 8) * 36 + ac + 4];
            }
#pragma unroll
            for (int nt = 0; nt < 8; nt++) {
                uint32_t b[2];
                int bk = kk + lc;
                int bn = nw0 + nt * 8 + lr;
                b[0] = Bs[bk * 136 + bn];
                b[1] = Bs[(bk + 4) * 136 + bn];
                mma_tf32(acc[0][nt], a[0], b);
                mma_tf32(acc[1][nt], a[1], b);
            }
        }
        __syncthreads();
    }

    const float scaleq = 0.14433756729740643f;   // 1/sqrt(48)
#pragma unroll
    for (int mt = 0; mt < 2; mt++) {
#pragma unroll
        for (int nt = 0; nt < 8; nt++) {
            int cc = ncol + nw0 + nt * 8 + 2 * lc;
#pragma unroll
            for (int half = 0; half < 2; half++) {
                int r = m0 + mw0 + mt * 16 + lr + half * 8;
                float v0 = acc[mt][nt][half * 2 + 0];
                float v1 = acc[mt][nt][half * 2 + 1];
                if (sel == 0) { v0 *= scaleq; v1 *= scaleq; }
                else if (sel == 3) {
                    v0 = 1.f / (1.f + __expf(-(v0 + bg[cc])));
                    v1 = 1.f / (1.f + __expf(-(v1 + bg[cc + 1])));
                }
                float2 o2; o2.x = v0; o2.y = v1;
                *(float2*)&O[r * HD + cc] = o2;
            }
        }
    }
}

// ===========================================================================
// Kernel 3: pair bias via tf32 mma with fused LayerNorm (algebraic).
//   bias[h][i][j] = rv_ij*(dot_tf32(z_ij, wg_h) - mu_ij*S_h) + Bc_h
// 128 threads = 4 warps, each warp one m16 row-tile (64 rows total),
// N=16 (2 n-tiles), K=128 (16 k-steps). LN stats warp-reduced in fp32
// during the coalesced z load. Grid (16 j-tiles, 1024 i).
// ===========================================================================
__global__ __launch_bounds__(128) void pairbias_kernel(const float* __restrict__ z,
                                                       const float* __restrict__ gz,
                                                       const float* __restrict__ bz,
                                                       const float* __restrict__ wz)
{
    __shared__ uint32_t zt[64 * 132];     // tf32 [row][c], stride 132
    __shared__ uint32_t wgt[CZ * 24];     // tf32 [c][h], stride 24
    __shared__ float ssum[64], ssq[64];
    __shared__ float Ssh[NH], Bcsh[NH], mus[64], rvs[64];

    int tid  = threadIdx.x;
    int lane = tid & 31;
    int warp = tid >> 5;
    int i  = blockIdx.y;
    int j0 = blockIdx.x * 64;

    // wg = g_z .* w_z -> tf32 smem
    for (int t = tid; t < CZ * NH; t += 128) {
        int c = t >> 4, h = t & 15;
        wgt[c * 24 + h] = f2tf32(gz[c] * wz[c * NH + h]);
    }
    if (tid < NH) {
        float S = 0.f, Bc = 0.f;
        for (int c = 0; c < CZ; c++) {
            S  += gz[c] * wz[c * NH + tid];
            Bc += bz[c] * wz[c * NH + tid];
        }
        Ssh[tid] = S; Bcsh[tid] = Bc;
    }

    // stream z: fully coalesced; warp w owns row 4*it + w each iter
    const float4* zb = (const float4*)(z + ((size_t)i * NTOK + j0) * CZ);
#pragma unroll 4
    for (int it = 0; it < 16; it++) {
        int idx = tid + 128 * it;
        int r = idx >> 5;                 // = 4*it + warp
        float4 v = zb[idx];
        float s  = v.x + v.y + v.z + v.w;
        float sq = v.x * v.x + v.y * v.y + v.z * v.z + v.w * v.w;
#pragma unroll
        for (int o = 16; o > 0; o >>= 1) {
            s  += __shfl_xor_sync(0xffffffffu, s, o);
            sq += __shfl_xor_sync(0xffffffffu, sq, o);
        }
        if (lane == 0) { ssum[r] = s; ssq[r] = sq; }
        uint32_t* d = &zt[r * 132 + lane * 4];
        d[0] = f2tf32(v.x); d[1] = f2tf32(v.y);
        d[2] = f2tf32(v.z); d[3] = f2tf32(v.w);
    }
    __syncthreads();

    if (tid < 64) {
        float mu  = ssum[tid] * (1.f / (float)CZ);
        float var = ssq[tid] * (1.f / (float)CZ) - mu * mu;
        mus[tid] = mu;
        rvs[tid] = rsqrtf(fmaxf(var, 0.f) + EPSV);
    }

    // mma: warp handles rows [warp*16, warp*16+16), N=16, K=128
    int m0 = warp * 16;
    int lr = lane >> 2, lc = lane & 3;
    float acc[2][4];
#pragma unroll
    for (int n = 0; n < 2; n++)
#pragma unroll
        for (int u = 0; u < 4; u++) acc[n][u] = 0.f;

#pragma unroll
    for (int k = 0; k < 16; k++) {
        int kk = k * 8;
        uint32_t a[4];
        int ar = m0 + lr, ac = kk + lc;
        a[0] = zt[ar * 132 + ac];
        a[1] = zt[(ar + 8) * 132 + ac];
        a[2] = zt[ar * 132 + ac + 4];
        a[3] = zt[(ar + 8) * 132 + ac + 4];
#pragma unroll
        for (int n = 0; n < 2; n++) {
            uint32_t b[2];
            int bk = kk + lc, bn = n * 8 + lr;
            b[0] = wgt[bk * 24 + bn];
            b[1] = wgt[(bk + 4) * 24 + bn];
            mma_tf32(acc[n], a, b);
        }
    }
    __syncthreads();   // mus/rvs visible to all

    // epilogue: affine LN correction + scatter to g_bias[h][i][j]
#pragma unroll
    for (int n = 0; n < 2; n++) {
        int h0 = n * 8 + 2 * lc;
#pragma unroll
        for (int half = 0; half < 2; half++) {
            int r = m0 + lr + half * 8;
            float mu = mus[r], rv = rvs[r];
            float v0 = rv * (acc[n][half * 2 + 0] - mu * Ssh[h0])     + Bcsh[h0];
            float v1 = rv * (acc[n][half * 2 + 1] - mu * Ssh[h0 + 1]) + Bcsh[h0 + 1];
            g_bias[((size_t)h0 * NTOK + i) * NTOK + j0 + r] = v0;
            g_bias[((size_t)(h0 + 1) * NTOK + i) * NTOK + j0 + r] = v1;
        }
    }
}

// ===========================================================================
// Kernel 4: flash attention with bias + gating (R2 config, known 157.5us).
// Block = (64-query tile, 1 head). 256 threads: tx 0..15, ty 0..15.
// ===========================================================================
__global__ __launch_bounds__(256) void attn_kernel(const float* __restrict__ mask)
{
    int h  = blockIdx.y;
    int qb = blockIdx.x * 64;
    int tid = threadIdx.x;
    int tx = tid & 15, ty = tid >> 4;
    int r0 = ty * 4;

    __shared__ __align__(16) float qs[64][52];
    __shared__ __align__(16) float kv[64 * 52];     // union: ks_t[48][68] / vs[64][52]
    __shared__ __align__(16) float ps[64][68];

    for (int t = tid; t < 64 * 12; t += 256) {
        int r = t / 12, c4 = (t % 12) * 4;
        *(float4*)&qs[r][c4] = *(const float4*)&g_q[(qb + r) * HD + h * DH + c4];
    }

    float mrow[4], lrow[4], o[4][3];
#pragma unroll
    for (int i = 0; i < 4; i++) {
        mrow[i] = -1e30f; lrow[i] = 0.f;
        o[i][0] = o[i][1] = o[i][2] = 0.f;
    }
    float mq[4];
#pragma unroll
    for (int i = 0; i < 4; i++) mq[i] = mask[qb + r0 + i];

    for (int jt = 0; jt < 16; jt++) {
        int j0 = jt * 64;
        __syncthreads();                      // prev-iter v reads done
        for (int t = tid; t < 64 * 12; t += 256) {
            int j = t & 63, d4 = (t >> 6) * 4;
            float4 v = *(const float4*)&g_k[(j0 + j) * HD + h * DH + d4];
            kv[(d4 + 0) * 68 + j] = v.x;
            kv[(d4 + 1) * 68 + j] = v.y;
            kv[(d4 + 2) * 68 + j] = v.z;
            kv[(d4 + 3) * 68 + j] = v.w;
        }
        __syncthreads();

        float s[4][4];
#pragma unroll
        for (int i = 0; i < 4; i++)
#pragma unroll
            for (int u = 0; u < 4; u++) s[i][u] = 0.f;

        for (int d = 0; d < DH; d += 4) {
            float qa[4][4];
#pragma unroll
            for (int i = 0; i < 4; i++)
                *(float4*)qa[i] = *(const float4*)&qs[r0 + i][d];
#pragma unroll
            for (int dd = 0; dd < 4; dd++) {
                float4 b4 = *(const float4*)&kv[(d + dd) * 68 + tx * 4];
#pragma unroll
                for (int i = 0; i < 4; i++) {
                    float a = qa[i][dd];
                    s[i][0] = fmaf(a, b4.x, s[i][0]);
                    s[i][1] = fmaf(a, b4.y, s[i][1]);
                    s[i][2] = fmaf(a, b4.z, s[i][2]);
                    s[i][3] = fmaf(a, b4.w, s[i][3]);
                }
            }
        }
        float mk[4];
#pragma unroll
        for (int u = 0; u < 4; u++) mk[u] = mask[j0 + tx * 4 + u];
#pragma unroll
        for (int i = 0; i < 4; i++) {
            const float* bp = g_bias + ((size_t)h * NTOK + qb + r0 + i) * NTOK + j0 + tx * 4;
            float4 b4 = *(const float4*)bp;
            s[i][0] += b4.x + INFV * (mq[i] * mk[0] - 1.f);
            s[i][1] += b4.y + INFV * (mq[i] * mk[1] - 1.f);
            s[i][2] += b4.z + INFV * (mq[i] * mk[2] - 1.f);
            s[i][3] += b4.w + INFV * (mq[i] * mk[3] - 1.f);
        }
#pragma unroll
        for (int i = 0; i < 4; i++) {
            float mx = fmaxf(fmaxf(s[i][0], s[i][1]), fmaxf(s[i][2], s[i][3]));
#pragma unroll
            for (int off = 1; off < 16; off <<= 1)
                mx = fmaxf(mx, __shfl_xor_sync(0xffffffffu, mx, off));
            float mnew = fmaxf(mrow[i], mx);
            float scale = __expf(mrow[i] - mnew);
            float psum = 0.f;
#pragma unroll
            for (int u = 0; u < 4; u++) { s[i][u] = __expf(s[i][u] - mnew); psum += s[i][u]; }
#pragma unroll
            for (int off = 1; off < 16; off <<= 1)
                psum += __shfl_xor_sync(0xffffffffu, psum, off);
            lrow[i] = lrow[i] * scale + psum;
            mrow[i] = mnew;
            o[i][0] *= scale; o[i][1] *= scale; o[i][2] *= scale;
            *(float4*)&ps[r0 + i][tx * 4] = make_float4(s[i][0], s[i][1], s[i][2], s[i][3]);
        }
        __syncthreads();                      // k reads done, ps visible
        for (int t = tid; t < 64 * 12; t += 256) {
            int r = t / 12, c4 = (t % 12) * 4;
            float4 v = *(const float4*)&g_v[(j0 + r) * HD + h * DH + c4];
            *(float4*)&kv[r * 52 + c4] = v;
        }
        __syncthreads();
        int d0 = tx * 3;
        for (int j = 0; j < 64; j += 4) {
            float pa[4][4];
#pragma unroll
            for (int i = 0; i < 4; i++)
                *(float4*)pa[i] = *(const float4*)&ps[r0 + i][j];
#pragma unroll
            for (int jj = 0; jj < 4; jj++) {
                int jr = j + jj;
                float b0 = kv[jr * 52 + d0];
                float b1 = kv[jr * 52 + d0 + 1];
                float b2 = kv[jr * 52 + d0 + 2];
#pragma unroll
                for (int i = 0; i < 4; i++) {
                    float p = pa[i][jj];
                    o[i][0] = fmaf(p, b0, o[i][0]);
                    o[i][1] = fmaf(p, b1, o[i][1]);
                    o[i][2] = fmaf(p, b2, o[i][2]);
                }
            }
        }
    }
#pragma unroll
    for (int i = 0; i < 4; i++) {
        int q = qb + r0 + i;
        float inv = 1.f / lrow[i];
        int base = q * HD + h * DH + tx * 3;
#pragma unroll
        for (int u = 0; u < 3; u++)
            g_og[base + u] = o[i][u] * inv * g_g[base + u];
    }
}

// ===========================================================================
// Kernel 5: output projection (scalar, R2 config).
// 64x64 tiles -> grid (12,16) = 192 blocks. 256 threads, 4x4 microtile.
// ===========================================================================
__global__ __launch_bounds__(256, 4) void outproj_kernel(const float* __restrict__ W,
                                                         const float* __restrict__ bo,
                                                         float* __restrict__ out)
{
    const int BK = 16;
    int n0 = blockIdx.x * 64;
    int m0 = blockIdx.y * 64;

    __shared__ __align__(16) float As[BK][68];
    __shared__ __align__(16) float Bs[BK][64];
    int tid = threadIdx.x;
    int tx = tid & 15, ty = tid >> 4;

    float acc[4][4];
#pragma unroll
    for (int i = 0; i < 4; i++)
#pragma unroll
        for (int j = 0; j < 4; j++) acc[i][j] = 0.f;

    for (int k0 = 0; k0 < HD; k0 += BK) {
        {
            int m = tid >> 2, kq = (tid & 3) * 4;
            float4 av = *(const float4*)&g_og[(m0 + m) * HD + k0 + kq];
            As[kq + 0][m] = av.x; As[kq + 1][m] = av.y;
            As[kq + 2][m] = av.z; As[kq + 3][m] = av.w;
        }
        {
            int r = tid >> 4, c = (tid & 15) * 4;
            *(float4*)&Bs[r][c] = *(const float4*)&W[(k0 + r) * CQ + n0 + c];
        }
        __syncthreads();
#pragma unroll
        for (int k = 0; k < BK; k++) {
            float a[4], b[4];
            *(float4*)a = *(const float4*)&As[k][ty * 4];
            *(float4*)b = *(const float4*)&Bs[k][tx * 4];
#pragma unroll
            for (int i = 0; i < 4; i++)
#pragma unroll
                for (int j = 0; j < 4; j++)
                    acc[i][j] = fmaf(a[i], b[j], acc[i][j]);
        }
        __syncthreads();
    }
#pragma unroll
    for (int i = 0; i < 4; i++) {
        int m = m0 + ty * 4 + i;
        int c = n0 + tx * 4;
        float4 o4;
        o4.x = acc[i][0] + bo[c + 0];
        o4.y = acc[i][1] + bo[c + 1];
        o4.z = acc[i][2] + bo[c + 2];
        o4.w = acc[i][3] + bo[c + 3];
        *(float4*)&out[m * CQ + c] = o4;
    }
}

// ===========================================================================
extern "C" void kernel_launch(void* const* d_in, const int* in_sizes, int n_in,
                              void* d_out, int out_size)
{
    const float* a    = (const float*)d_in[0];
    const float* z    = (const float*)d_in[1];
    const float* mask = (const float*)d_in[2];
    const float* g_a  = (const float*)d_in[3];
    const float* b_a  = (const float*)d_in[4];
    const float* g_z  = (const float*)d_in[5];
    const float* b_z  = (const float*)d_in[6];
    const float* w_z  = (const float*)d_in[7];
    const float* w_q  = (const float*)d_in[8];
    const float* w_k  = (const float*)d_in[9];
    const float* w_v  = (const float*)d_in[10];
    const float* w_g  = (const float*)d_in[11];
    const float* b_g  = (const float*)d_in[12];
    const float* w_o  = (const float*)d_in[13];
    const float* b_o  = (const float*)d_in[14];
    float* out = (float*)d_out;

    ln_a_kernel<<<NTOK, 256>>>(a, g_a, b_a);
    proj_kernel<<<dim3(24, 8), 256>>>(w_q, w_k, w_v, w_g, b_g);
    pairbias_kernel<<<dim3(16, NTOK), 128>>>(z, g_z, b_z, w_z);
    attn_kernel<<<dim3(16, NH), 256>>>(mask);
    outproj_kernel<<<dim3(12, 16), 256>>>(w_o, b_o, out);
}

// round 7
// speedup vs baseline: 1.5590x; 1.0502x over previous
#include <cuda_runtime.h>
#include <math.h>
#include <stdint.h>

#define NTOK 1024
#define CQ   768
#define CZ   128
#define NH   16
#define DH   48
#define HD   768
#define EPSV 1e-5f
#define INFV 1.0e9f

// ------------- static device scratch (no allocations allowed) -------------
__device__ float g_an[NTOK * CQ];
__device__ float g_q [NTOK * HD];
__device__ float g_k [NTOK * HD];
__device__ float g_v [NTOK * HD];
__device__ float g_g [NTOK * HD];
__device__ float g_og[NTOK * HD];
__device__ float g_bias[(size_t)NH * NTOK * NTOK];   // [h][i][j] 64 MB

// ------------------------- tf32 mma helpers -------------------------------
__device__ __forceinline__ uint32_t f2tf32(float f) {
    uint32_t r;
    asm("cvt.rna.tf32.f32 %0, %1;" : "=r"(r) : "f"(f));
    return r;
}
__device__ __forceinline__ void mma_tf32(float* d, const uint32_t* a, const uint32_t* b) {
    asm("mma.sync.aligned.m16n8k8.row.col.f32.tf32.tf32.f32 "
        "{%0,%1,%2,%3}, {%4,%5,%6,%7}, {%8,%9}, {%0,%1,%2,%3};"
        : "+f"(d[0]), "+f"(d[1]), "+f"(d[2]), "+f"(d[3])
        : "r"(a[0]), "r"(a[1]), "r"(a[2]), "r"(a[3]), "r"(b[0]), "r"(b[1]));
}

// ===========================================================================
// Kernel 1: LayerNorm(a) -> g_an.   1024 blocks x 256 threads.
// ===========================================================================
__global__ __launch_bounds__(256) void ln_a_kernel(const float* __restrict__ a,
                                                   const float* __restrict__ ga,
                                                   const float* __restrict__ ba)
{
    int row = blockIdx.x;
    int tid = threadIdx.x;
    const float* x = a + row * CQ;
    float v0 = x[tid], v1 = x[tid + 256], v2 = x[tid + 512];
    float s = v0 + v1 + v2;
    float q = v0 * v0 + v1 * v1 + v2 * v2;
#pragma unroll
    for (int o = 16; o > 0; o >>= 1) {
        s += __shfl_xor_sync(0xffffffffu, s, o);
        q += __shfl_xor_sync(0xffffffffu, q, o);
    }
    __shared__ float sw[8], qw[8];
    __shared__ float smu, srv;
    if ((tid & 31) == 0) { sw[tid >> 5] = s; qw[tid >> 5] = q; }
    __syncthreads();
    if (tid == 0) {
        float S = 0.f, Q = 0.f;
#pragma unroll
        for (int w = 0; w < 8; w++) { S += sw[w]; Q += qw[w]; }
        float mu = S * (1.f / (float)CQ);
        float var = Q * (1.f / (float)CQ) - mu * mu;
        smu = mu;
        srv = rsqrtf(fmaxf(var, 0.f) + EPSV);
    }
    __syncthreads();
    float mu = smu, r = srv;
    float* o = g_an + row * CQ;
    o[tid]       = (v0 - mu) * r * ga[tid]       + ba[tid];
    o[tid + 256] = (v1 - mu) * r * ga[tid + 256] + ba[tid + 256];
    o[tid + 512] = (v2 - mu) * r * ga[tid + 512] + ba[tid + 512];
}

// ===========================================================================
// Kernel 2: fused QKVG projections via tf32 mma.sync.  (unchanged, R5)
// ===========================================================================
__global__ __launch_bounds__(256) void proj_kernel(const float* __restrict__ Wq,
                                                   const float* __restrict__ Wk,
                                                   const float* __restrict__ Wv,
                                                   const float* __restrict__ Wg,
                                                   const float* __restrict__ bg)
{
    int n0 = blockIdx.x * 128;
    int sel  = n0 / HD;
    int ncol = n0 - sel * HD;
    const float* W = (sel == 0) ? Wq : (sel == 1) ? Wk : (sel == 2) ? Wv : Wg;
    float*       O = (sel == 0) ? g_q : (sel == 1) ? g_k : (sel == 2) ? g_v : g_g;
    int m0 = blockIdx.y * 128;

    __shared__ uint32_t As[128 * 36];
    __shared__ uint32_t Bs[32 * 136];

    int tid  = threadIdx.x;
    int lane = tid & 31;
    int warp = tid >> 5;
    int wm = warp >> 1, wn = warp & 1;
    int mw0 = wm * 32, nw0 = wn * 64;
    int lr = lane >> 2, lc = lane & 3;

    float acc[2][8][4];
#pragma unroll
    for (int mt = 0; mt < 2; mt++)
#pragma unroll
        for (int nt = 0; nt < 8; nt++)
#pragma unroll
            for (int u = 0; u < 4; u++) acc[mt][nt][u] = 0.f;

    for (int k0 = 0; k0 < CQ; k0 += 32) {
#pragma unroll
        for (int it = 0; it < 4; it++) {
            int t = tid + it * 256;
            int r = t >> 3, c4 = t & 7;
            float4 v = *(const float4*)&g_an[(m0 + r) * CQ + k0 + c4 * 4];
            uint32_t* d = &As[r * 36 + c4 * 4];
            d[0] = f2tf32(v.x); d[1] = f2tf32(v.y);
            d[2] = f2tf32(v.z); d[3] = f2tf32(v.w);
        }
#pragma unroll
        for (int it = 0; it < 4; it++) {
            int t = tid + it * 256;
            int r = t >> 5, c4 = t & 31;
            float4 v = *(const float4*)&W[(k0 + r) * HD + ncol + c4 * 4];
            uint32_t* d = &Bs[r * 136 + c4 * 4];
            d[0] = f2tf32(v.x); d[1] = f2tf32(v.y);
            d[2] = f2tf32(v.z); d[3] = f2tf32(v.w);
        }
        __syncthreads();
#pragma unroll
        for (int ks = 0; ks < 4; ks++) {
            int kk = ks * 8;
            uint32_t a[2][4];
#pragma unroll
            for (int mt = 0; mt < 2; mt++) {
                int ar = mw0 + mt * 16 + lr;
                int ac = kk + lc;
                a[mt][0] = As[ar * 36 + ac];
                a[mt][1] = As[(ar + 8) * 36 + ac];
                a[mt][2] = As[ar * 36 + ac + 4];
                a[mt][3] = As[(ar + 8) * 36 + ac + 4];
            }
#pragma unroll
            for (int nt = 0; nt < 8; nt++) {
                uint32_t b[2];
                int bk = kk + lc;
                int bn = nw0 + nt * 8 + lr;
                b[0] = Bs[bk * 136 + bn];
                b[1] = Bs[(bk + 4) * 136 + bn];
                mma_tf32(acc[0][nt], a[0], b);
                mma_tf32(acc[1][nt], a[1], b);
            }
        }
        __syncthreads();
    }

    const float scaleq = 0.14433756729740643f;
#pragma unroll
    for (int mt = 0; mt < 2; mt++) {
#pragma unroll
        for (int nt = 0; nt < 8; nt++) {
            int cc = ncol + nw0 + nt * 8 + 2 * lc;
#pragma unroll
            for (int half = 0; half < 2; half++) {
                int r = m0 + mw0 + mt * 16 + lr + half * 8;
                float v0 = acc[mt][nt][half * 2 + 0];
                float v1 = acc[mt][nt][half * 2 + 1];
                if (sel == 0) { v0 *= scaleq; v1 *= scaleq; }
                else if (sel == 3) {
                    v0 = 1.f / (1.f + __expf(-(v0 + bg[cc])));
                    v1 = 1.f / (1.f + __expf(-(v1 + bg[cc + 1])));
                }
                float2 o2; o2.x = v0; o2.y = v1;
                *(float2*)&O[r * HD + cc] = o2;
            }
        }
    }
}

// ===========================================================================
// Kernel 3: pair bias via tf32 mma + fused LN.  NEW: smem-staged coalesced
// float4 output writes (was: 4B scattered STG, 8x write amplification).
// ===========================================================================
__global__ __launch_bounds__(128) void pairbias_kernel(const float* __restrict__ z,
                                                       const float* __restrict__ gz,
                                                       const float* __restrict__ bz,
                                                       const float* __restrict__ wz)
{
    __shared__ uint32_t zt[64 * 132];     // tf32 [row][c]; reused as out stage
    __shared__ uint32_t wgt[CZ * 24];
    __shared__ float ssum[64], ssq[64];
    __shared__ float Ssh[NH], Bcsh[NH], mus[64], rvs[64];

    int tid  = threadIdx.x;
    int lane = tid & 31;
    int warp = tid >> 5;
    int i  = blockIdx.y;
    int j0 = blockIdx.x * 64;

    for (int t = tid; t < CZ * NH; t += 128) {
        int c = t >> 4, h = t & 15;
        wgt[c * 24 + h] = f2tf32(gz[c] * wz[c * NH + h]);
    }
    if (tid < NH) {
        float S = 0.f, Bc = 0.f;
        for (int c = 0; c < CZ; c++) {
            S  += gz[c] * wz[c * NH + tid];
            Bc += bz[c] * wz[c * NH + tid];
        }
        Ssh[tid] = S; Bcsh[tid] = Bc;
    }

    const float4* zb = (const float4*)(z + ((size_t)i * NTOK + j0) * CZ);
#pragma unroll 4
    for (int it = 0; it < 16; it++) {
        int idx = tid + 128 * it;
        int r = idx >> 5;
        float4 v = zb[idx];
        float s  = v.x + v.y + v.z + v.w;
        float sq = v.x * v.x + v.y * v.y + v.z * v.z + v.w * v.w;
#pragma unroll
        for (int o = 16; o > 0; o >>= 1) {
            s  += __shfl_xor_sync(0xffffffffu, s, o);
            sq += __shfl_xor_sync(0xffffffffu, sq, o);
        }
        if (lane == 0) { ssum[r] = s; ssq[r] = sq; }
        uint32_t* d = &zt[r * 132 + lane * 4];
        d[0] = f2tf32(v.x); d[1] = f2tf32(v.y);
        d[2] = f2tf32(v.z); d[3] = f2tf32(v.w);
    }
    __syncthreads();

    if (tid < 64) {
        float mu  = ssum[tid] * (1.f / (float)CZ);
        float var = ssq[tid] * (1.f / (float)CZ) - mu * mu;
        mus[tid] = mu;
        rvs[tid] = rsqrtf(fmaxf(var, 0.f) + EPSV);
    }

    int m0 = warp * 16;
    int lr = lane >> 2, lc = lane & 3;
    float acc[2][4];
#pragma unroll
    for (int n = 0; n < 2; n++)
#pragma unroll
        for (int u = 0; u < 4; u++) acc[n][u] = 0.f;

#pragma unroll
    for (int k = 0; k < 16; k++) {
        int kk = k * 8;
        uint32_t a[4];
        int ar = m0 + lr, ac = kk + lc;
        a[0] = zt[ar * 132 + ac];
        a[1] = zt[(ar + 8) * 132 + ac];
        a[2] = zt[ar * 132 + ac + 4];
        a[3] = zt[(ar + 8) * 132 + ac + 4];
#pragma unroll
        for (int n = 0; n < 2; n++) {
            uint32_t b[2];
            int bk = kk + lc, bn = n * 8 + lr;
            b[0] = wgt[bk * 24 + bn];
            b[1] = wgt[(bk + 4) * 24 + bn];
            mma_tf32(acc[n], a, b);
        }
    }
    __syncthreads();   // mus/rvs visible; all zt mma reads done

    // stage epilogue values into smem tile outs[h][j] (stride 68), then
    // write g_bias with coalesced float4 stores.
    float* outs = (float*)zt;
#pragma unroll
    for (int n = 0; n < 2; n++) {
        int h0 = n * 8 + 2 * lc;
#pragma unroll
        for (int half = 0; half < 2; half++) {
            int r = m0 + lr + half * 8;
            float mu = mus[r], rv = rvs[r];
            outs[h0 * 68 + r]       = rv * (acc[n][half * 2 + 0] - mu * Ssh[h0])     + Bcsh[h0];
            outs[(h0 + 1) * 68 + r] = rv * (acc[n][half * 2 + 1] - mu * Ssh[h0 + 1]) + Bcsh[h0 + 1];
        }
    }
    __syncthreads();
#pragma unroll
    for (int it = 0; it < 2; it++) {
        int idx = tid + 128 * it;          // 0..255
        int h = idx >> 4, j4 = (idx & 15) * 4;
        float4 o4;
        o4.x = outs[h * 68 + j4 + 0];
        o4.y = outs[h * 68 + j4 + 1];
        o4.z = outs[h * 68 + j4 + 2];
        o4.w = outs[h * 68 + j4 + 3];
        *(float4*)&g_bias[((size_t)h * NTOK + i) * NTOK + j0 + j4] = o4;
    }
}

// ===========================================================================
// Kernel 4: flash attention via tf32 mma.sync, online softmax, gating.
// Block = (64-q tile, 1 head), 128 threads = 4 warps, warp owns 16 q-rows.
// QK^T: A=q (smem stride 52), B=K^T (stride 72). PV: A=P (stride 68),
// B=V[j][d] (stride 56). All fragment LDS patterns bank-conflict-free.
// ===========================================================================
__global__ __launch_bounds__(128) void attn_kernel(const float* __restrict__ mask)
{
    int h  = blockIdx.y;
    int qb = blockIdx.x * 64;
    int tid  = threadIdx.x;
    int lane = tid & 31;
    int warp = tid >> 5;
    int lr = lane >> 2, lc = lane & 3;
    int m0 = warp * 16;

    __shared__ uint32_t qs[64 * 52];
    __shared__ uint32_t kv[64 * 56];      // union: K^T[48][72] / V[64][56]
    __shared__ uint32_t ps[64 * 68];

    // stage Q as tf32
    for (int t = tid; t < 768; t += 128) {
        int r = t / 12, c4 = (t % 12) * 4;
        float4 v = *(const float4*)&g_q[(qb + r) * HD + h * DH + c4];
        uint32_t* d = &qs[r * 52 + c4];
        d[0] = f2tf32(v.x); d[1] = f2tf32(v.y);
        d[2] = f2tf32(v.z); d[3] = f2tf32(v.w);
    }

    float mrow0 = -1e30f, mrow1 = -1e30f, lrow0 = 0.f, lrow1 = 0.f;
    float oacc[6][4];
#pragma unroll
    for (int vt = 0; vt < 6; vt++)
#pragma unroll
        for (int u = 0; u < 4; u++) oacc[vt][u] = 0.f;

    float mq0 = mask[qb + m0 + lr];
    float mq1 = mask[qb + m0 + lr + 8];

    for (int jt = 0; jt < 16; jt++) {
        int j0 = jt * 64;
        __syncthreads();                  // prev PV reads (and Q staging) done
        // stage K^T [d][j], stride 72
        for (int t = tid; t < 768; t += 128) {
            int j = t & 63, dq = t >> 6;
            float4 v = *(const float4*)&g_k[(j0 + j) * HD + h * DH + dq * 4];
            kv[(dq * 4 + 0) * 72 + j] = f2tf32(v.x);
            kv[(dq * 4 + 1) * 72 + j] = f2tf32(v.y);
            kv[(dq * 4 + 2) * 72 + j] = f2tf32(v.z);
            kv[(dq * 4 + 3) * 72 + j] = f2tf32(v.w);
        }
        __syncthreads();

        // scores S[16 x 64] per warp
        float sacc[8][4];
#pragma unroll
        for (int nt = 0; nt < 8; nt++)
#pragma unroll
            for (int u = 0; u < 4; u++) sacc[nt][u] = 0.f;
#pragma unroll
        for (int k = 0; k < 6; k++) {
            int kk = k * 8;
            uint32_t a[4];
            int ar = m0 + lr, ac = kk + lc;
            a[0] = qs[ar * 52 + ac];
            a[1] = qs[(ar + 8) * 52 + ac];
            a[2] = qs[ar * 52 + ac + 4];
            a[3] = qs[(ar + 8) * 52 + ac + 4];
#pragma unroll
            for (int nt = 0; nt < 8; nt++) {
                uint32_t b[2];
                b[0] = kv[(kk + lc) * 72 + nt * 8 + lr];
                b[1] = kv[(kk + lc + 4) * 72 + nt * 8 + lr];
                mma_tf32(sacc[nt], a, b);
            }
        }

        // bias + mask, running row max
        float rmax0 = -1e30f, rmax1 = -1e30f;
#pragma unroll
        for (int nt = 0; nt < 8; nt++) {
            int jc = j0 + nt * 8 + 2 * lc;
            float2 b0 = *(const float2*)&g_bias[((size_t)h * NTOK + qb + m0 + lr) * NTOK + jc];
            float2 b1 = *(const float2*)&g_bias[((size_t)h * NTOK + qb + m0 + lr + 8) * NTOK + jc];
            float mk0 = mask[jc], mk1 = mask[jc + 1];
            sacc[nt][0] += b0.x + INFV * (mq0 * mk0 - 1.f);
            sacc[nt][1] += b0.y + INFV * (mq0 * mk1 - 1.f);
            sacc[nt][2] += b1.x + INFV * (mq1 * mk0 - 1.f);
            sacc[nt][3] += b1.y + INFV * (mq1 * mk1 - 1.f);
            rmax0 = fmaxf(rmax0, fmaxf(sacc[nt][0], sacc[nt][1]));
            rmax1 = fmaxf(rmax1, fmaxf(sacc[nt][2], sacc[nt][3]));
        }
#pragma unroll
        for (int off = 1; off < 4; off <<= 1) {
            rmax0 = fmaxf(rmax0, __shfl_xor_sync(0xffffffffu, rmax0, off));
            rmax1 = fmaxf(rmax1, __shfl_xor_sync(0xffffffffu, rmax1, off));
        }
        float mnew0 = fmaxf(mrow0, rmax0);
        float mnew1 = fmaxf(mrow1, rmax1);
        float scale0 = __expf(mrow0 - mnew0);
        float scale1 = __expf(mrow1 - mnew1);

        float sum0 = 0.f, sum1 = 0.f;
#pragma unroll
        for (int nt = 0; nt < 8; nt++) {
            sacc[nt][0] = __expf(sacc[nt][0] - mnew0);
            sacc[nt][1] = __expf(sacc[nt][1] - mnew0);
            sacc[nt][2] = __expf(sacc[nt][2] - mnew1);
            sacc[nt][3] = __expf(sacc[nt][3] - mnew1);
            sum0 += sacc[nt][0] + sacc[nt][1];
            sum1 += sacc[nt][2] + sacc[nt][3];
            uint2 p0, p1;
            p0.x = f2tf32(sacc[nt][0]); p0.y = f2tf32(sacc[nt][1]);
            p1.x = f2tf32(sacc[nt][2]); p1.y = f2tf32(sacc[nt][3]);
            *(uint2*)&ps[(m0 + lr) * 68 + nt * 8 + 2 * lc]     = p0;
            *(uint2*)&ps[(m0 + lr + 8) * 68 + nt * 8 + 2 * lc] = p1;
        }
#pragma unroll
        for (int off = 1; off < 4; off <<= 1) {
            sum0 += __shfl_xor_sync(0xffffffffu, sum0, off);
            sum1 += __shfl_xor_sync(0xffffffffu, sum1, off);
        }
        lrow0 = lrow0 * scale0 + sum0;  mrow0 = mnew0;
        lrow1 = lrow1 * scale1 + sum1;  mrow1 = mnew1;
#pragma unroll
        for (int vt = 0; vt < 6; vt++) {
            oacc[vt][0] *= scale0; oacc[vt][1] *= scale0;
            oacc[vt][2] *= scale1; oacc[vt][3] *= scale1;
        }

        __syncthreads();                  // all warps done reading K^T
        // stage V [j][d], stride 56
        for (int t = tid; t < 768; t += 128) {
            int r = t / 12, c4 = (t % 12) * 4;
            float4 v = *(const float4*)&g_v[(j0 + r) * HD + h * DH + c4];
            uint32_t* d = &kv[r * 56 + c4];
            d[0] = f2tf32(v.x); d[1] = f2tf32(v.y);
            d[2] = f2tf32(v.z); d[3] = f2tf32(v.w);
        }
        __syncthreads();

        // O += P @ V   (A = P rows of this warp, written by this warp)
#pragma unroll
        for (int k = 0; k < 8; k++) {
            int kk = k * 8;
            uint32_t a[4];
            int ar = m0 + lr, ac = kk + lc;
            a[0] = ps[ar * 68 + ac];
            a[1] = ps[(ar + 8) * 68 + ac];
            a[2] = ps[ar * 68 + ac + 4];
            a[3] = ps[(ar + 8) * 68 + ac + 4];
#pragma unroll
            for (int vt = 0; vt < 6; vt++) {
                uint32_t b[2];
                b[0] = kv[(kk + lc) * 56 + vt * 8 + lr];
                b[1] = kv[(kk + lc + 4) * 56 + vt * 8 + lr];
                mma_tf32(oacc[vt], a, b);
            }
        }
    }

    // epilogue: normalize, gate, write
    float inv0 = 1.f / lrow0;
    float inv1 = 1.f / lrow1;
#pragma unroll
    for (int vt = 0; vt < 6; vt++) {
        int d = vt * 8 + 2 * lc;
        int g0 = (qb + m0 + lr) * HD + h * DH + d;
        int g1 = (qb + m0 + lr + 8) * HD + h * DH + d;
        g_og[g0]     = oacc[vt][0] * inv0 * g_g[g0];
        g_og[g0 + 1] = oacc[vt][1] * inv0 * g_g[g0 + 1];
        g_og[g1]     = oacc[vt][2] * inv1 * g_g[g1];
        g_og[g1 + 1] = oacc[vt][3] * inv1 * g_g[g1 + 1];
    }
}

// ===========================================================================
// Kernel 5: output projection (scalar, unchanged).
// ===========================================================================
__global__ __launch_bounds__(256, 4) void outproj_kernel(const float* __restrict__ W,
                                                         const float* __restrict__ bo,
                                                         float* __restrict__ out)
{
    const int BK = 16;
    int n0 = blockIdx.x * 64;
    int m0 = blockIdx.y * 64;

    __shared__ __align__(16) float As[BK][68];
    __shared__ __align__(16) float Bs[BK][64];
    int tid = threadIdx.x;
    int tx = tid & 15, ty = tid >> 4;

    float acc[4][4];
#pragma unroll
    for (int i = 0; i < 4; i++)
#pragma unroll
        for (int j = 0; j < 4; j++) acc[i][j] = 0.f;

    for (int k0 = 0; k0 < HD; k0 += BK) {
        {
            int m = tid >> 2, kq = (tid & 3) * 4;
            float4 av = *(const float4*)&g_og[(m0 + m) * HD + k0 + kq];
            As[kq + 0][m] = av.x; As[kq + 1][m] = av.y;
            As[kq + 2][m] = av.z; As[kq + 3][m] = av.w;
        }
        {
            int r = tid >> 4, c = (tid & 15) * 4;
            *(float4*)&Bs[r][c] = *(const float4*)&W[(k0 + r) * CQ + n0 + c];
        }
        __syncthreads();
#pragma unroll
        for (int k = 0; k < BK; k++) {
            float a[4], b[4];
            *(float4*)a = *(const float4*)&As[k][ty * 4];
            *(float4*)b = *(const float4*)&Bs[k][tx * 4];
#pragma unroll
            for (int i = 0; i < 4; i++)
#pragma unroll
                for (int j = 0; j < 4; j++)
                    acc[i][j] = fmaf(a[i], b[j], acc[i][j]);
        }
        __syncthreads();
    }
#pragma unroll
    for (int i = 0; i < 4; i++) {
        int m = m0 + ty * 4 + i;
        int c = n0 + tx * 4;
        float4 o4;
        o4.x = acc[i][0] + bo[c + 0];
        o4.y = acc[i][1] + bo[c + 1];
        o4.z = acc[i][2] + bo[c + 2];
        o4.w = acc[i][3] + bo[c + 3];
        *(float4*)&out[m * CQ + c] = o4;
    }
}

// ===========================================================================
extern "C" void kernel_launch(void* const* d_in, const int* in_sizes, int n_in,
                              void* d_out, int out_size)
{
    const float* a    = (const float*)d_in[0];
    const float* z    = (const float*)d_in[1];
    const float* mask = (const float*)d_in[2];
    const float* g_a  = (const float*)d_in[3];
    const float* b_a  = (const float*)d_in[4];
    const float* g_z  = (const float*)d_in[5];
    const float* b_z  = (const float*)d_in[6];
    const float* w_z  = (const float*)d_in[7];
    const float* w_q  = (const float*)d_in[8];
    const float* w_k  = (const float*)d_in[9];
    const float* w_v  = (const float*)d_in[10];
    const float* w_g  = (const float*)d_in[11];
    const float* b_g  = (const float*)d_in[12];
    const float* w_o  = (const float*)d_in[13];
    const float* b_o  = (const float*)d_in[14];
    float* out = (float*)d_out;

    ln_a_kernel<<<NTOK, 256>>>(a, g_a, b_a);
    proj_kernel<<<dim3(24, 8), 256>>>(w_q, w_k, w_v, w_g, b_g);
    pairbias_kernel<<<dim3(16, NTOK), 128>>>(z, g_z, b_z, w_z);
    attn_kernel<<<dim3(16, NH), 128>>>(mask);
    outproj_kernel<<<dim3(12, 16), 256>>>(w_o, b_o, out);
}

// round 8
// speedup vs baseline: 2.1581x; 1.3843x over previous
#include <cuda_runtime.h>
#include <math.h>
#include <stdint.h>

#define NTOK 1024
#define CQ   768
#define CZ   128
#define NH   16
#define DH   48
#define HD   768
#define EPSV 1e-5f
#define INFV 1.0e9f
#define NSPLIT 4

// ------------- static device scratch (no allocations allowed) -------------
__device__ float g_an[NTOK * CQ];
__device__ float g_q [NTOK * HD];
__device__ float g_k [NTOK * HD];
__device__ float g_v [NTOK * HD];
__device__ float g_g [NTOK * HD];
__device__ float g_og[NTOK * HD];
__device__ float g_bias[(size_t)NH * NTOK * NTOK];   // [h][i][j] 64 MB
__device__ float g_po[NSPLIT * NH * NTOK * DH];      // unnormalized o partials
__device__ float g_pm[NSPLIT * NH * NTOK];
__device__ float g_pl[NSPLIT * NH * NTOK];
__device__ uint32_t g_wgt[CZ * 20];                  // tf32 (g_z .* w_z), padded [c][20]
__device__ float g_Svec[NH], g_Bcvec[NH];

// ------------------------- tf32 mma helpers -------------------------------
__device__ __forceinline__ uint32_t f2tf32(float f) {
    uint32_t r;
    asm("cvt.rna.tf32.f32 %0, %1;" : "=r"(r) : "f"(f));
    return r;
}
__device__ __forceinline__ void mma_tf32(float* d, const uint32_t* a, const uint32_t* b) {
    asm("mma.sync.aligned.m16n8k8.row.col.f32.tf32.tf32.f32 "
        "{%0,%1,%2,%3}, {%4,%5,%6,%7}, {%8,%9}, {%0,%1,%2,%3};"
        : "+f"(d[0]), "+f"(d[1]), "+f"(d[2]), "+f"(d[3])
        : "r"(a[0]), "r"(a[1]), "r"(a[2]), "r"(a[3]), "r"(b[0]), "r"(b[1]));
}

// ===========================================================================
// Kernel 0: pair-bias setup (1 block): wg = g_z.*w_z (tf32, padded),
// S_h = sum_c wg, Bc_h = sum_c b_z*w_z.
// ===========================================================================
__global__ __launch_bounds__(128) void pb_setup_kernel(const float* __restrict__ gz,
                                                       const float* __restrict__ bz,
                                                       const float* __restrict__ wz)
{
    int t = threadIdx.x;
    for (int i = t; i < CZ * NH; i += 128) {
        int c = i >> 4, h = i & 15;
        g_wgt[c * 20 + h] = f2tf32(gz[c] * wz[c * NH + h]);
    }
    if (t < NH) {
        float S = 0.f, Bc = 0.f;
        for (int c = 0; c < CZ; c++) {
            S  += gz[c] * wz[c * NH + t];
            Bc += bz[c] * wz[c * NH + t];
        }
        g_Svec[t] = S; g_Bcvec[t] = Bc;
    }
}

// ===========================================================================
// Kernel 1: LayerNorm(a) -> g_an.   1024 blocks x 256 threads.
// ===========================================================================
__global__ __launch_bounds__(256) void ln_a_kernel(const float* __restrict__ a,
                                                   const float* __restrict__ ga,
                                                   const float* __restrict__ ba)
{
    int row = blockIdx.x;
    int tid = threadIdx.x;
    const float* x = a + row * CQ;
    float v0 = x[tid], v1 = x[tid + 256], v2 = x[tid + 512];
    float s = v0 + v1 + v2;
    float q = v0 * v0 + v1 * v1 + v2 * v2;
#pragma unroll
    for (int o = 16; o > 0; o >>= 1) {
        s += __shfl_xor_sync(0xffffffffu, s, o);
        q += __shfl_xor_sync(0xffffffffu, q, o);
    }
    __shared__ float sw[8], qw[8];
    __shared__ float smu, srv;
    if ((tid & 31) == 0) { sw[tid >> 5] = s; qw[tid >> 5] = q; }
    __syncthreads();
    if (tid == 0) {
        float S = 0.f, Q = 0.f;
#pragma unroll
        for (int w = 0; w < 8; w++) { S += sw[w]; Q += qw[w]; }
        float mu = S * (1.f / (float)CQ);
        float var = Q * (1.f / (float)CQ) - mu * mu;
        smu = mu;
        srv = rsqrtf(fmaxf(var, 0.f) + EPSV);
    }
    __syncthreads();
    float mu = smu, r = srv;
    float* o = g_an + row * CQ;
    o[tid]       = (v0 - mu) * r * ga[tid]       + ba[tid];
    o[tid + 256] = (v1 - mu) * r * ga[tid + 256] + ba[tid + 256];
    o[tid + 512] = (v2 - mu) * r * ga[tid + 512] + ba[tid + 512];
}

// ===========================================================================
// Kernel 2: fused QKVG projections via tf32 mma. BM=64, BN=128, BK=32.
// 128 threads = 4 warps (2m x 2n), warp tile m32n64. grid (24, 16).
// ===========================================================================
__global__ __launch_bounds__(128) void proj_kernel(const float* __restrict__ Wq,
                                                   const float* __restrict__ Wk,
                                                   const float* __restrict__ Wv,
                                                   const float* __restrict__ Wg,
                                                   const float* __restrict__ bg)
{
    int n0 = blockIdx.x * 128;
    int sel  = n0 / HD;
    int ncol = n0 - sel * HD;
    const float* W = (sel == 0) ? Wq : (sel == 1) ? Wk : (sel == 2) ? Wv : Wg;
    float*       O = (sel == 0) ? g_q : (sel == 1) ? g_k : (sel == 2) ? g_v : g_g;
    int m0 = blockIdx.y * 64;

    __shared__ uint32_t As[64 * 36];
    __shared__ uint32_t Bs[32 * 136];

    int tid  = threadIdx.x;
    int lane = tid & 31;
    int warp = tid >> 5;
    int wm = warp >> 1, wn = warp & 1;
    int mw0 = wm * 32, nw0 = wn * 64;
    int lr = lane >> 2, lc = lane & 3;

    float acc[2][8][4];
#pragma unroll
    for (int mt = 0; mt < 2; mt++)
#pragma unroll
        for (int nt = 0; nt < 8; nt++)
#pragma unroll
            for (int u = 0; u < 4; u++) acc[mt][nt][u] = 0.f;

    for (int k0 = 0; k0 < CQ; k0 += 32) {
#pragma unroll
        for (int it = 0; it < 4; it++) {
            int t = tid + it * 128;
            int r = t >> 3, c4 = t & 7;
            float4 v = *(const float4*)&g_an[(m0 + r) * CQ + k0 + c4 * 4];
            uint32_t* d = &As[r * 36 + c4 * 4];
            d[0] = f2tf32(v.x); d[1] = f2tf32(v.y);
            d[2] = f2tf32(v.z); d[3] = f2tf32(v.w);
        }
#pragma unroll
        for (int it = 0; it < 8; it++) {
            int t = tid + it * 128;
            int r = t >> 5, c4 = t & 31;
            float4 v = *(const float4*)&W[(k0 + r) * HD + ncol + c4 * 4];
            uint32_t* d = &Bs[r * 136 + c4 * 4];
            d[0] = f2tf32(v.x); d[1] = f2tf32(v.y);
            d[2] = f2tf32(v.z); d[3] = f2tf32(v.w);
        }
        __syncthreads();
#pragma unroll
        for (int ks = 0; ks < 4; ks++) {
            int kk = ks * 8;
            uint32_t a[2][4];
#pragma unroll
            for (int mt = 0; mt < 2; mt++) {
                int ar = mw0 + mt * 16 + lr;
                int ac = kk + lc;
                a[mt][0] = As[ar * 36 + ac];
                a[mt][1] = As[(ar + 8) * 36 + ac];
                a[mt][2] = As[ar * 36 + ac + 4];
                a[mt][3] = As[(ar + 8) * 36 + ac + 4];
            }
#pragma unroll
            for (int nt = 0; nt < 8; nt++) {
                uint32_t b[2];
                int bk = kk + lc;
                int bn = nw0 + nt * 8 + lr;
                b[0] = Bs[bk * 136 + bn];
                b[1] = Bs[(bk + 4) * 136 + bn];
                mma_tf32(acc[0][nt], a[0], b);
                mma_tf32(acc[1][nt], a[1], b);
            }
        }
        __syncthreads();
    }

    const float scaleq = 0.14433756729740643f;
#pragma unroll
    for (int mt = 0; mt < 2; mt++) {
#pragma unroll
        for (int nt = 0; nt < 8; nt++) {
            int cc = ncol + nw0 + nt * 8 + 2 * lc;
#pragma unroll
            for (int half = 0; half < 2; half++) {
                int r = m0 + mw0 + mt * 16 + lr + half * 8;
                float v0 = acc[mt][nt][half * 2 + 0];
                float v1 = acc[mt][nt][half * 2 + 1];
                if (sel == 0) { v0 *= scaleq; v1 *= scaleq; }
                else if (sel == 3) {
                    v0 = 1.f / (1.f + __expf(-(v0 + bg[cc])));
                    v1 = 1.f / (1.f + __expf(-(v1 + bg[cc + 1])));
                }
                float2 o2; o2.x = v0; o2.y = v1;
                *(float2*)&O[r * HD + cc] = o2;
            }
        }
    }
}

// ===========================================================================
// Kernel 3: pair bias via tf32 mma + fused LN; wg/S/Bc precomputed.
// smem ~45KB -> 5 blocks/SM. Grid (16 j-tiles, 1024 i), 128 threads.
// ===========================================================================
__global__ __launch_bounds__(128) void pairbias_kernel(const float* __restrict__ z)
{
    __shared__ uint32_t zt[64 * 132];     // tf32 [row][c]; reused as out stage
    __shared__ uint32_t wgt[CZ * 20];
    __shared__ float ssum[64], ssq[64];
    __shared__ float Ssh[NH], Bcsh[NH], mus[64], rvs[64];

    int tid  = threadIdx.x;
    int lane = tid & 31;
    int i  = blockIdx.y;
    int j0 = blockIdx.x * 64;

    // stage precomputed wg (already padded/tf32) + S/Bc
    {
        const uint4* src = (const uint4*)g_wgt;
        uint4* dst = (uint4*)wgt;
#pragma unroll
        for (int it = 0; it < 5; it++) dst[tid + it * 128] = src[tid + it * 128];
    }
    if (tid < NH) { Ssh[tid] = g_Svec[tid]; Bcsh[tid] = g_Bcvec[tid]; }

    const float4* zb = (const float4*)(z + ((size_t)i * NTOK + j0) * CZ);
#pragma unroll 4
    for (int it = 0; it < 16; it++) {
        int idx = tid + 128 * it;
        int r = idx >> 5;
        float4 v = zb[idx];
        float s  = v.x + v.y + v.z + v.w;
        float sq = v.x * v.x + v.y * v.y + v.z * v.z + v.w * v.w;
#pragma unroll
        for (int o = 16; o > 0; o >>= 1) {
            s  += __shfl_xor_sync(0xffffffffu, s, o);
            sq += __shfl_xor_sync(0xffffffffu, sq, o);
        }
        if (lane == 0) { ssum[r] = s; ssq[r] = sq; }
        uint32_t* d = &zt[r * 132 + lane * 4];
        d[0] = f2tf32(v.x); d[1] = f2tf32(v.y);
        d[2] = f2tf32(v.z); d[3] = f2tf32(v.w);
    }
    __syncthreads();

    if (tid < 64) {
        float mu  = ssum[tid] * (1.f / (float)CZ);
        float var = ssq[tid] * (1.f / (float)CZ) - mu * mu;
        mus[tid] = mu;
        rvs[tid] = rsqrtf(fmaxf(var, 0.f) + EPSV);
    }

    int warp = tid >> 5;
    int m0 = warp * 16;
    int lr = lane >> 2, lc = lane & 3;
    float acc[2][4];
#pragma unroll
    for (int n = 0; n < 2; n++)
#pragma unroll
        for (int u = 0; u < 4; u++) acc[n][u] = 0.f;

#pragma unroll
    for (int k = 0; k < 16; k++) {
        int kk = k * 8;
        uint32_t a[4];
        int ar = m0 + lr, ac = kk + lc;
        a[0] = zt[ar * 132 + ac];
        a[1] = zt[(ar + 8) * 132 + ac];
        a[2] = zt[ar * 132 + ac + 4];
        a[3] = zt[(ar + 8) * 132 + ac + 4];
#pragma unroll
        for (int n = 0; n < 2; n++) {
            uint32_t b[2];
            int bk = kk + lc, bn = n * 8 + lr;
            b[0] = wgt[bk * 20 + bn];
            b[1] = wgt[(bk + 4) * 20 + bn];
            mma_tf32(acc[n], a, b);
        }
    }
    __syncthreads();

    float* outs = (float*)zt;             // [h][j], stride 68
#pragma unroll
    for (int n = 0; n < 2; n++) {
        int h0 = n * 8 + 2 * lc;
#pragma unroll
        for (int half = 0; half < 2; half++) {
            int r = m0 + lr + half * 8;
            float mu = mus[r], rv = rvs[r];
            outs[h0 * 68 + r]       = rv * (acc[n][half * 2 + 0] - mu * Ssh[h0])     + Bcsh[h0];
            outs[(h0 + 1) * 68 + r] = rv * (acc[n][half * 2 + 1] - mu * Ssh[h0 + 1]) + Bcsh[h0 + 1];
        }
    }
    __syncthreads();
#pragma unroll
    for (int it = 0; it < 2; it++) {
        int idx = tid + 128 * it;
        int h = idx >> 4, j4 = (idx & 15) * 4;
        float4 o4;
        o4.x = outs[h * 68 + j4 + 0];
        o4.y = outs[h * 68 + j4 + 1];
        o4.z = outs[h * 68 + j4 + 2];
        o4.w = outs[h * 68 + j4 + 3];
        *(float4*)&g_bias[((size_t)h * NTOK + i) * NTOK + j0 + j4] = o4;
    }
}

// ===========================================================================
// Kernel 4: flash attention via tf32 mma, split-KV x4, partials out.
// Block = (64-q tile, head, split), 128 threads = 4 warps.
// Grid (16, 16, 4) = 1024 blocks.
// ===========================================================================
__global__ __launch_bounds__(128) void attn_kernel(const float* __restrict__ mask)
{
    int h     = blockIdx.y;
    int qb    = blockIdx.x * 64;
    int split = blockIdx.z;
    int tid  = threadIdx.x;
    int lane = tid & 31;
    int warp = tid >> 5;
    int lr = lane >> 2, lc = lane & 3;
    int m0 = warp * 16;

    __shared__ uint32_t qs[64 * 52];
    __shared__ uint32_t kv[64 * 56];      // union: K^T[48][72] / V[64][56]
    __shared__ uint32_t ps[64 * 68];

    for (int t = tid; t < 768; t += 128) {
        int r = t / 12, c4 = (t % 12) * 4;
        float4 v = *(const float4*)&g_q[(qb + r) * HD + h * DH + c4];
        uint32_t* d = &qs[r * 52 + c4];
        d[0] = f2tf32(v.x); d[1] = f2tf32(v.y);
        d[2] = f2tf32(v.z); d[3] = f2tf32(v.w);
    }

    float mrow0 = -1e30f, mrow1 = -1e30f, lrow0 = 0.f, lrow1 = 0.f;
    float oacc[6][4];
#pragma unroll
    for (int vt = 0; vt < 6; vt++)
#pragma unroll
        for (int u = 0; u < 4; u++) oacc[vt][u] = 0.f;

    float mq0 = mask[qb + m0 + lr];
    float mq1 = mask[qb + m0 + lr + 8];

    for (int jt = split * 4; jt < split * 4 + 4; jt++) {
        int j0 = jt * 64;
        __syncthreads();
        for (int t = tid; t < 768; t += 128) {
            int j = t & 63, dq = t >> 6;
            float4 v = *(const float4*)&g_k[(j0 + j) * HD + h * DH + dq * 4];
            kv[(dq * 4 + 0) * 72 + j] = f2tf32(v.x);
            kv[(dq * 4 + 1) * 72 + j] = f2tf32(v.y);
            kv[(dq * 4 + 2) * 72 + j] = f2tf32(v.z);
            kv[(dq * 4 + 3) * 72 + j] = f2tf32(v.w);
        }
        __syncthreads();

        float sacc[8][4];
#pragma unroll
        for (int nt = 0; nt < 8; nt++)
#pragma unroll
            for (int u = 0; u < 4; u++) sacc[nt][u] = 0.f;
#pragma unroll
        for (int k = 0; k < 6; k++) {
            int kk = k * 8;
            uint32_t a[4];
            int ar = m0 + lr, ac = kk + lc;
            a[0] = qs[ar * 52 + ac];
            a[1] = qs[(ar + 8) * 52 + ac];
            a[2] = qs[ar * 52 + ac + 4];
            a[3] = qs[(ar + 8) * 52 + ac + 4];
#pragma unroll
            for (int nt = 0; nt < 8; nt++) {
                uint32_t b[2];
                b[0] = kv[(kk + lc) * 72 + nt * 8 + lr];
                b[1] = kv[(kk + lc + 4) * 72 + nt * 8 + lr];
                mma_tf32(sacc[nt], a, b);
            }
        }

        float rmax0 = -1e30f, rmax1 = -1e30f;
#pragma unroll
        for (int nt = 0; nt < 8; nt++) {
            int jc = j0 + nt * 8 + 2 * lc;
            float2 b0 = *(const float2*)&g_bias[((size_t)h * NTOK + qb + m0 + lr) * NTOK + jc];
            float2 b1 = *(const float2*)&g_bias[((size_t)h * NTOK + qb + m0 + lr + 8) * NTOK + jc];
            float mk0 = mask[jc], mk1 = mask[jc + 1];
            sacc[nt][0] += b0.x + INFV * (mq0 * mk0 - 1.f);
            sacc[nt][1] += b0.y + INFV * (mq0 * mk1 - 1.f);
            sacc[nt][2] += b1.x + INFV * (mq1 * mk0 - 1.f);
            sacc[nt][3] += b1.y + INFV * (mq1 * mk1 - 1.f);
            rmax0 = fmaxf(rmax0, fmaxf(sacc[nt][0], sacc[nt][1]));
            rmax1 = fmaxf(rmax1, fmaxf(sacc[nt][2], sacc[nt][3]));
        }
#pragma unroll
        for (int off = 1; off < 4; off <<= 1) {
            rmax0 = fmaxf(rmax0, __shfl_xor_sync(0xffffffffu, rmax0, off));
            rmax1 = fmaxf(rmax1, __shfl_xor_sync(0xffffffffu, rmax1, off));
        }
        float mnew0 = fmaxf(mrow0, rmax0);
        float mnew1 = fmaxf(mrow1, rmax1);
        float scale0 = __expf(mrow0 - mnew0);
        float scale1 = __expf(mrow1 - mnew1);

        float sum0 = 0.f, sum1 = 0.f;
#pragma unroll
        for (int nt = 0; nt < 8; nt++) {
            sacc[nt][0] = __expf(sacc[nt][0] - mnew0);
            sacc[nt][1] = __expf(sacc[nt][1] - mnew0);
            sacc[nt][2] = __expf(sacc[nt][2] - mnew1);
            sacc[nt][3] = __expf(sacc[nt][3] - mnew1);
            sum0 += sacc[nt][0] + sacc[nt][1];
            sum1 += sacc[nt][2] + sacc[nt][3];
            uint2 p0, p1;
            p0.x = f2tf32(sacc[nt][0]); p0.y = f2tf32(sacc[nt][1]);
            p1.x = f2tf32(sacc[nt][2]); p1.y = f2tf32(sacc[nt][3]);
            *(uint2*)&ps[(m0 + lr) * 68 + nt * 8 + 2 * lc]     = p0;
            *(uint2*)&ps[(m0 + lr + 8) * 68 + nt * 8 + 2 * lc] = p1;
        }
#pragma unroll
        for (int off = 1; off < 4; off <<= 1) {
            sum0 += __shfl_xor_sync(0xffffffffu, sum0, off);
            sum1 += __shfl_xor_sync(0xffffffffu, sum1, off);
        }
        lrow0 = lrow0 * scale0 + sum0;  mrow0 = mnew0;
        lrow1 = lrow1 * scale1 + sum1;  mrow1 = mnew1;
#pragma unroll
        for (int vt = 0; vt < 6; vt++) {
            oacc[vt][0] *= scale0; oacc[vt][1] *= scale0;
            oacc[vt][2] *= scale1; oacc[vt][3] *= scale1;
        }

        __syncthreads();
        for (int t = tid; t < 768; t += 128) {
            int r = t / 12, c4 = (t % 12) * 4;
            float4 v = *(const float4*)&g_v[(j0 + r) * HD + h * DH + c4];
            uint32_t* d = &kv[r * 56 + c4];
            d[0] = f2tf32(v.x); d[1] = f2tf32(v.y);
            d[2] = f2tf32(v.z); d[3] = f2tf32(v.w);
        }
        __syncthreads();

#pragma unroll
        for (int k = 0; k < 8; k++) {
            int kk = k * 8;
            uint32_t a[4];
            int ar = m0 + lr, ac = kk + lc;
            a[0] = ps[ar * 68 + ac];
            a[1] = ps[(ar + 8) * 68 + ac];
            a[2] = ps[ar * 68 + ac + 4];
            a[3] = ps[(ar + 8) * 68 + ac + 4];
#pragma unroll
            for (int vt = 0; vt < 6; vt++) {
                uint32_t b[2];
                b[0] = kv[(kk + lc) * 56 + vt * 8 + lr];
                b[1] = kv[(kk + lc + 4) * 56 + vt * 8 + lr];
                mma_tf32(oacc[vt], a, b);
            }
        }
    }

    // write partials
    int q0 = qb + m0 + lr, q1 = q0 + 8;
    int pb0 = ((split * NH + h) * NTOK + q0) * DH;
    int pb1 = ((split * NH + h) * NTOK + q1) * DH;
#pragma unroll
    for (int vt = 0; vt < 6; vt++) {
        int d = vt * 8 + 2 * lc;
        *(float2*)&g_po[pb0 + d] = make_float2(oacc[vt][0], oacc[vt][1]);
        *(float2*)&g_po[pb1 + d] = make_float2(oacc[vt][2], oacc[vt][3]);
    }
    if (lc == 0) {
        g_pm[(split * NH + h) * NTOK + q0] = mrow0;
        g_pl[(split * NH + h) * NTOK + q0] = lrow0;
        g_pm[(split * NH + h) * NTOK + q1] = mrow1;
        g_pl[(split * NH + h) * NTOK + q1] = lrow1;
    }
}

// ===========================================================================
// Kernel 4b: merge 4 splits, normalize, apply gate -> g_og.
// Grid 1024, 256 threads (h = t/16, d0 = (t%16)*3).
// ===========================================================================
__global__ __launch_bounds__(256) void merge_kernel()
{
    int q = blockIdx.x;
    int t = threadIdx.x;
    int h = t >> 4;
    int d0 = (t & 15) * 3;

    float m[NSPLIT], l[NSPLIT];
    float M = -1e30f;
#pragma unroll
    for (int s = 0; s < NSPLIT; s++) {
        m[s] = g_pm[(s * NH + h) * NTOK + q];
        l[s] = g_pl[(s * NH + h) * NTOK + q];
        M = fmaxf(M, m[s]);
    }
    float w[NSPLIT], ltot = 0.f;
#pragma unroll
    for (int s = 0; s < NSPLIT; s++) {
        w[s] = __expf(m[s] - M);
        ltot += l[s] * w[s];
    }
    float inv = 1.f / ltot;
    int go = q * HD + h * DH + d0;
#pragma unroll
    for (int u = 0; u < 3; u++) {
        float val = 0.f;
#pragma unroll
        for (int s = 0; s < NSPLIT; s++)
            val += g_po[((s * NH + h) * NTOK + q) * DH + d0 + u] * w[s];
        g_og[go + u] = val * inv * g_g[go + u];
    }
}

// ===========================================================================
// Kernel 5: output projection via tf32 mma. BM=64, BN=64, BK=32.
// 128 threads = 4 warps (2m x 2n), warp tile m32n32. grid (12, 16).
// ===========================================================================
__global__ __launch_bounds__(128) void outproj_kernel(const float* __restrict__ W,
                                                      const float* __restrict__ bo,
                                                      float* __restrict__ out)
{
    int n0 = blockIdx.x * 64;
    int m0 = blockIdx.y * 64;

    __shared__ uint32_t As[64 * 36];
    __shared__ uint32_t Bs[32 * 72];

    int tid  = threadIdx.x;
    int lane = tid & 31;
    int warp = tid >> 5;
    int wm = warp >> 1, wn = warp & 1;
    int mw0 = wm * 32, nw0 = wn * 32;
    int lr = lane >> 2, lc = lane & 3;

    float acc[2][4][4];
#pragma unroll
    for (int mt = 0; mt < 2; mt++)
#pragma unroll
        for (int nt = 0; nt < 4; nt++)
#pragma unroll
            for (int u = 0; u < 4; u++) acc[mt][nt][u] = 0.f;

    for (int k0 = 0; k0 < HD; k0 += 32) {
#pragma unroll
        for (int it = 0; it < 4; it++) {
            int t = tid + it * 128;
            int r = t >> 3, c4 = t & 7;
            float4 v = *(const float4*)&g_og[(m0 + r) * HD + k0 + c4 * 4];
            uint32_t* d = &As[r * 36 + c4 * 4];
            d[0] = f2tf32(v.x); d[1] = f2tf32(v.y);
            d[2] = f2tf32(v.z); d[3] = f2tf32(v.w);
        }
#pragma unroll
        for (int it = 0; it < 4; it++) {
            int t = tid + it * 128;
            int r = t >> 4, c4 = t & 15;
            float4 v = *(const float4*)&W[(k0 + r) * CQ + n0 + c4 * 4];
            uint32_t* d = &Bs[r * 72 + c4 * 4];
            d[0] = f2tf32(v.x); d[1] = f2tf32(v.y);
            d[2] = f2tf32(v.z); d[3] = f2tf32(v.w);
        }
        __syncthreads();
#pragma unroll
        for (int ks = 0; ks < 4; ks++) {
            int kk = ks * 8;
            uint32_t a[2][4];
#pragma unroll
            for (int mt = 0; mt < 2; mt++) {
                int ar = mw0 + mt * 16 + lr;
                int ac = kk + lc;
                a[mt][0] = As[ar * 36 + ac];
                a[mt][1] = As[(ar + 8) * 36 + ac];
                a[mt][2] = As[ar * 36 + ac + 4];
                a[mt][3] = As[(ar + 8) * 36 + ac + 4];
            }
#pragma unroll
            for (int nt = 0; nt < 4; nt++) {
                uint32_t b[2];
                int bk = kk + lc;
                int bn = nw0 + nt * 8 + lr;
                b[0] = Bs[bk * 72 + bn];
                b[1] = Bs[(bk + 4) * 72 + bn];
                mma_tf32(acc[0][nt], a[0], b);
                mma_tf32(acc[1][nt], a[1], b);
            }
        }
        __syncthreads();
    }

#pragma unroll
    for (int mt = 0; mt < 2; mt++) {
#pragma unroll
        for (int nt = 0; nt < 4; nt++) {
            int cc = n0 + nw0 + nt * 8 + 2 * lc;
            float b0 = bo[cc], b1 = bo[cc + 1];
#pragma unroll
            for (int half = 0; half < 2; half++) {
                int r = m0 + mw0 + mt * 16 + lr + half * 8;
                float2 o2;
                o2.x = acc[mt][nt][half * 2 + 0] + b0;
                o2.y = acc[mt][nt][half * 2 + 1] + b1;
                *(float2*)&out[r * CQ + cc] = o2;
            }
        }
    }
}

// ===========================================================================
extern "C" void kernel_launch(void* const* d_in, const int* in_sizes, int n_in,
                              void* d_out, int out_size)
{
    const float* a    = (const float*)d_in[0];
    const float* z    = (const float*)d_in[1];
    const float* mask = (const float*)d_in[2];
    const float* g_a  = (const float*)d_in[3];
    const float* b_a  = (const float*)d_in[4];
    const float* g_z  = (const float*)d_in[5];
    const float* b_z  = (const float*)d_in[6];
    const float* w_z  = (const float*)d_in[7];
    const float* w_q  = (const float*)d_in[8];
    const float* w_k  = (const float*)d_in[9];
    const float* w_v  = (const float*)d_in[10];
    const float* w_g  = (const float*)d_in[11];
    const float* b_g  = (const float*)d_in[12];
    const float* w_o  = (const float*)d_in[13];
    const float* b_o  = (const float*)d_in[14];
    float* out = (float*)d_out;

    pb_setup_kernel<<<1, 128>>>(g_z, b_z, w_z);
    ln_a_kernel<<<NTOK, 256>>>(a, g_a, b_a);
    proj_kernel<<<dim3(24, 16), 128>>>(w_q, w_k, w_v, w_g, b_g);
    pairbias_kernel<<<dim3(16, NTOK), 128>>>(z);
    attn_kernel<<<dim3(16, NH, NSPLIT), 128>>>(mask);
    merge_kernel<<<NTOK, 256>>>();
    outproj_kernel<<<dim3(12, 16), 128>>>(w_o, b_o, out);
}

// round 9
// speedup vs baseline: 2.3976x; 1.1110x over previous
#include <cuda_runtime.h>
#include <math.h>
#include <stdint.h>

#define NTOK 1024
#define CQ   768
#define CZ   128
#define NH   16
#define DH   48
#define HD   768
#define EPSV 1e-5f
#define INFV 1.0e9f
#define NSPLIT 4

// ------------- static device scratch (no allocations allowed) -------------
__device__ float g_an[NTOK * CQ];
__device__ float g_q [NTOK * HD];
__device__ float g_k [NTOK * HD];
__device__ float g_v [NTOK * HD];
__device__ float g_g [NTOK * HD];
__device__ float g_og[NTOK * HD];
__device__ float g_bias[(size_t)NH * NTOK * NTOK];   // [h][i][j] 64 MB
__device__ float g_po[NSPLIT * NH * NTOK * DH];      // unnormalized o partials
__device__ float g_pm[NSPLIT * NH * NTOK];
__device__ float g_pl[NSPLIT * NH * NTOK];
__device__ uint32_t g_wgt[NH * 132];                 // tf32 (g_z .* w_z), [h][c] stride 132
__device__ float g_Svec[NH], g_Bcvec[NH];

// ------------------------- tf32 mma helpers -------------------------------
__device__ __forceinline__ uint32_t f2tf32(float f) {
    uint32_t r;
    asm("cvt.rna.tf32.f32 %0, %1;" : "=r"(r) : "f"(f));
    return r;
}
__device__ __forceinline__ void mma_tf32(float* d, const uint32_t* a, const uint32_t* b) {
    asm("mma.sync.aligned.m16n8k8.row.col.f32.tf32.tf32.f32 "
        "{%0,%1,%2,%3}, {%4,%5,%6,%7}, {%8,%9}, {%0,%1,%2,%3};"
        : "+f"(d[0]), "+f"(d[1]), "+f"(d[2]), "+f"(d[3])
        : "r"(a[0]), "r"(a[1]), "r"(a[2]), "r"(a[3]), "r"(b[0]), "r"(b[1]));
}

// ===========================================================================
// Kernel 0: pair-bias setup (1 block): wg = g_z.*w_z (tf32, [h][c] layout),
// S_h = sum_c wg, Bc_h = sum_c b_z*w_z.
// ===========================================================================
__global__ __launch_bounds__(128) void pb_setup_kernel(const float* __restrict__ gz,
                                                       const float* __restrict__ bz,
                                                       const float* __restrict__ wz)
{
    int t = threadIdx.x;
    for (int i = t; i < NH * 132; i += 128) {
        int h = i / 132, c = i - h * 132;
        float v = (c < CZ) ? gz[c] * wz[c * NH + h] : 0.f;
        g_wgt[i] = f2tf32(v);
    }
    if (t < NH) {
        float S = 0.f, Bc = 0.f;
        for (int c = 0; c < CZ; c++) {
            S  += gz[c] * wz[c * NH + t];
            Bc += bz[c] * wz[c * NH + t];
        }
        g_Svec[t] = S; g_Bcvec[t] = Bc;
    }
}

// ===========================================================================
// Kernel 1: LayerNorm(a) -> g_an.   1024 blocks x 256 threads.
// ===========================================================================
__global__ __launch_bounds__(256) void ln_a_kernel(const float* __restrict__ a,
                                                   const float* __restrict__ ga,
                                                   const float* __restrict__ ba)
{
    int row = blockIdx.x;
    int tid = threadIdx.x;
    const float* x = a + row * CQ;
    float v0 = x[tid], v1 = x[tid + 256], v2 = x[tid + 512];
    float s = v0 + v1 + v2;
    float q = v0 * v0 + v1 * v1 + v2 * v2;
#pragma unroll
    for (int o = 16; o > 0; o >>= 1) {
        s += __shfl_xor_sync(0xffffffffu, s, o);
        q += __shfl_xor_sync(0xffffffffu, q, o);
    }
    __shared__ float sw[8], qw[8];
    __shared__ float smu, srv;
    if ((tid & 31) == 0) { sw[tid >> 5] = s; qw[tid >> 5] = q; }
    __syncthreads();
    if (tid == 0) {
        float S = 0.f, Q = 0.f;
#pragma unroll
        for (int w = 0; w < 8; w++) { S += sw[w]; Q += qw[w]; }
        float mu = S * (1.f / (float)CQ);
        float var = Q * (1.f / (float)CQ) - mu * mu;
        smu = mu;
        srv = rsqrtf(fmaxf(var, 0.f) + EPSV);
    }
    __syncthreads();
    float mu = smu, r = srv;
    float* o = g_an + row * CQ;
    o[tid]       = (v0 - mu) * r * ga[tid]       + ba[tid];
    o[tid + 256] = (v1 - mu) * r * ga[tid + 256] + ba[tid + 256];
    o[tid + 512] = (v2 - mu) * r * ga[tid + 512] + ba[tid + 512];
}

// ===========================================================================
// Kernel 2: fused QKVG projections via tf32 mma. BM=64, BN=128, BK=32.
// 128 threads = 4 warps (2m x 2n), warp tile m32n64. grid (24, 16). (R7)
// ===========================================================================
__global__ __launch_bounds__(128) void proj_kernel(const float* __restrict__ Wq,
                                                   const float* __restrict__ Wk,
                                                   const float* __restrict__ Wv,
                                                   const float* __restrict__ Wg,
                                                   const float* __restrict__ bg)
{
    int n0 = blockIdx.x * 128;
    int sel  = n0 / HD;
    int ncol = n0 - sel * HD;
    const float* W = (sel == 0) ? Wq : (sel == 1) ? Wk : (sel == 2) ? Wv : Wg;
    float*       O = (sel == 0) ? g_q : (sel == 1) ? g_k : (sel == 2) ? g_v : g_g;
    int m0 = blockIdx.y * 64;

    __shared__ uint32_t As[64 * 36];
    __shared__ uint32_t Bs[32 * 136];

    int tid  = threadIdx.x;
    int lane = tid & 31;
    int warp = tid >> 5;
    int wm = warp >> 1, wn = warp & 1;
    int mw0 = wm * 32, nw0 = wn * 64;
    int lr = lane >> 2, lc = lane & 3;

    float acc[2][8][4];
#pragma unroll
    for (int mt = 0; mt < 2; mt++)
#pragma unroll
        for (int nt = 0; nt < 8; nt++)
#pragma unroll
            for (int u = 0; u < 4; u++) acc[mt][nt][u] = 0.f;

    for (int k0 = 0; k0 < CQ; k0 += 32) {
#pragma unroll
        for (int it = 0; it < 4; it++) {
            int t = tid + it * 128;
            int r = t >> 3, c4 = t & 7;
            float4 v = *(const float4*)&g_an[(m0 + r) * CQ + k0 + c4 * 4];
            uint32_t* d = &As[r * 36 + c4 * 4];
            d[0] = f2tf32(v.x); d[1] = f2tf32(v.y);
            d[2] = f2tf32(v.z); d[3] = f2tf32(v.w);
        }
#pragma unroll
        for (int it = 0; it < 8; it++) {
            int t = tid + it * 128;
            int r = t >> 5, c4 = t & 31;
            float4 v = *(const float4*)&W[(k0 + r) * HD + ncol + c4 * 4];
            uint32_t* d = &Bs[r * 136 + c4 * 4];
            d[0] = f2tf32(v.x); d[1] = f2tf32(v.y);
            d[2] = f2tf32(v.z); d[3] = f2tf32(v.w);
        }
        __syncthreads();
#pragma unroll
        for (int ks = 0; ks < 4; ks++) {
            int kk = ks * 8;
            uint32_t a[2][4];
#pragma unroll
            for (int mt = 0; mt < 2; mt++) {
                int ar = mw0 + mt * 16 + lr;
                int ac = kk + lc;
                a[mt][0] = As[ar * 36 + ac];
                a[mt][1] = As[(ar + 8) * 36 + ac];
                a[mt][2] = As[ar * 36 + ac + 4];
                a[mt][3] = As[(ar + 8) * 36 + ac + 4];
            }
#pragma unroll
            for (int nt = 0; nt < 8; nt++) {
                uint32_t b[2];
                int bk = kk + lc;
                int bn = nw0 + nt * 8 + lr;
                b[0] = Bs[bk * 136 + bn];
                b[1] = Bs[(bk + 4) * 136 + bn];
                mma_tf32(acc[0][nt], a[0], b);
                mma_tf32(acc[1][nt], a[1], b);
            }
        }
        __syncthreads();
    }

    const float scaleq = 0.14433756729740643f;
#pragma unroll
    for (int mt = 0; mt < 2; mt++) {
#pragma unroll
        for (int nt = 0; nt < 8; nt++) {
            int cc = ncol + nw0 + nt * 8 + 2 * lc;
#pragma unroll
            for (int half = 0; half < 2; half++) {
                int r = m0 + mw0 + mt * 16 + lr + half * 8;
                float v0 = acc[mt][nt][half * 2 + 0];
                float v1 = acc[mt][nt][half * 2 + 1];
                if (sel == 0) { v0 *= scaleq; v1 *= scaleq; }
                else if (sel == 3) {
                    v0 = 1.f / (1.f + __expf(-(v0 + bg[cc])));
                    v1 = 1.f / (1.f + __expf(-(v1 + bg[cc + 1])));
                }
                float2 o2; o2.x = v0; o2.y = v1;
                *(float2*)&O[r * HD + cc] = o2;
            }
        }
    }
}

// ===========================================================================
// Kernel 3: pair bias via tf32 mma + fused LN.  L1-traffic rebuild:
//  - z streamed with 4-deep load groups, no in-loop reductions, STS.128
//  - LN stats computed from tf32 smem by warps 0-1 (no shuffles)
//  - wgt in [h][c] stride-132 layout: B-fragment loads conflict-free
// smem ~42.9KB -> 5 blocks/SM. Grid (16 j-tiles, 1024 i), 128 threads.
// ===========================================================================
__global__ __launch_bounds__(128) void pairbias_kernel(const float* __restrict__ z)
{
    __shared__ uint32_t zt[64 * 132];     // tf32 [row][c]; reused as out stage
    __shared__ uint32_t wgt[NH * 132];    // tf32 [h][c]
    __shared__ float Ssh[NH], Bcsh[NH], mus[64], rvs[64];

    int tid  = threadIdx.x;
    int lane = tid & 31;
    int warp = tid >> 5;
    int i  = blockIdx.y;
    int j0 = blockIdx.x * 64;

    // stage precomputed wgt (2112 words = 528 uint4) + S/Bc
    {
        const uint4* src = (const uint4*)g_wgt;
        uint4* dst = (uint4*)wgt;
        for (int t2 = tid; t2 < 528; t2 += 128) dst[t2] = src[t2];
    }
    if (tid < NH) { Ssh[tid] = g_Svec[tid]; Bcsh[tid] = g_Bcvec[tid]; }

    // stream z: 4 groups of 4 independent LDG.128 each; cvt + STS.128 only
    const float4* zb = (const float4*)(z + ((size_t)i * NTOK + j0) * CZ);
#pragma unroll
    for (int g = 0; g < 4; g++) {
        float4 vv[4];
#pragma unroll
        for (int u = 0; u < 4; u++) vv[u] = zb[tid + 128 * (g * 4 + u)];
#pragma unroll
        for (int u = 0; u < 4; u++) {
            int r = (tid + 128 * (g * 4 + u)) >> 5;
            uint4 tv;
            tv.x = f2tf32(vv[u].x); tv.y = f2tf32(vv[u].y);
            tv.z = f2tf32(vv[u].z); tv.w = f2tf32(vv[u].w);
            *(uint4*)&zt[r * 132 + lane * 4] = tv;
        }
    }
    __syncthreads();

    // LN stats from tf32 smem: warps 0-1, one row per thread
    if (tid < 64) {
        float s = 0.f, sq = 0.f;
        const uint32_t* zr = &zt[tid * 132];
#pragma unroll
        for (int cq = 0; cq < 32; cq++) {
            uint4 w = *(const uint4*)&zr[cq * 4];
            float x0 = __uint_as_float(w.x), x1 = __uint_as_float(w.y);
            float x2 = __uint_as_float(w.z), x3 = __uint_as_float(w.w);
            s += x0 + x1 + x2 + x3;
            sq = fmaf(x0, x0, sq); sq = fmaf(x1, x1, sq);
            sq = fmaf(x2, x2, sq); sq = fmaf(x3, x3, sq);
        }
        float mu  = s * (1.f / (float)CZ);
        float var = sq * (1.f / (float)CZ) - mu * mu;
        mus[tid] = mu;
        rvs[tid] = rsqrtf(fmaxf(var, 0.f) + EPSV);
    }

    // mma: warp owns rows [warp*16, warp*16+16), N=16, K=128
    int m0 = warp * 16;
    int lr = lane >> 2, lc = lane & 3;
    float acc[2][4];
#pragma unroll
    for (int n = 0; n < 2; n++)
#pragma unroll
        for (int u = 0; u < 4; u++) acc[n][u] = 0.f;

#pragma unroll
    for (int k = 0; k < 16; k++) {
        int kk = k * 8;
        uint32_t a[4];
        int ar = m0 + lr, ac = kk + lc;
        a[0] = zt[ar * 132 + ac];
        a[1] = zt[(ar + 8) * 132 + ac];
        a[2] = zt[ar * 132 + ac + 4];
        a[3] = zt[(ar + 8) * 132 + ac + 4];
#pragma unroll
        for (int n = 0; n < 2; n++) {
            uint32_t b[2];
            int bn = n * 8 + lr;
            b[0] = wgt[bn * 132 + kk + lc];
            b[1] = wgt[bn * 132 + kk + lc + 4];
            mma_tf32(acc[n], a, b);
        }
    }
    __syncthreads();   // mus/rvs visible; all zt mma reads done

    float* outs = (float*)zt;             // [h][j], stride 68
#pragma unroll
    for (int n = 0; n < 2; n++) {
        int h0 = n * 8 + 2 * lc;
#pragma unroll
        for (int half = 0; half < 2; half++) {
            int r = m0 + lr + half * 8;
            float mu = mus[r], rv = rvs[r];
            outs[h0 * 68 + r]       = rv * (acc[n][half * 2 + 0] - mu * Ssh[h0])     + Bcsh[h0];
            outs[(h0 + 1) * 68 + r] = rv * (acc[n][half * 2 + 1] - mu * Ssh[h0 + 1]) + Bcsh[h0 + 1];
        }
    }
    __syncthreads();
#pragma unroll
    for (int it = 0; it < 2; it++) {
        int idx = tid + 128 * it;
        int h = idx >> 4, j4 = (idx & 15) * 4;
        float4 o4;
        o4.x = outs[h * 68 + j4 + 0];
        o4.y = outs[h * 68 + j4 + 1];
        o4.z = outs[h * 68 + j4 + 2];
        o4.w = outs[h * 68 + j4 + 3];
        *(float4*)&g_bias[((size_t)h * NTOK + i) * NTOK + j0 + j4] = o4;
    }
}

// ===========================================================================
// Kernel 4: flash attention via tf32 mma, split-KV x4, partials out. (R7)
// ===========================================================================
__global__ __launch_bounds__(128) void attn_kernel(const float* __restrict__ mask)
{
    int h     = blockIdx.y;
    int qb    = blockIdx.x * 64;
    int split = blockIdx.z;
    int tid  = threadIdx.x;
    int lane = tid & 31;
    int warp = tid >> 5;
    int lr = lane >> 2, lc = lane & 3;
    int m0 = warp * 16;

    __shared__ uint32_t qs[64 * 52];
    __shared__ uint32_t kv[64 * 56];      // union: K^T[48][72] / V[64][56]
    __shared__ uint32_t ps[64 * 68];

    for (int t = tid; t < 768; t += 128) {
        int r = t / 12, c4 = (t % 12) * 4;
        float4 v = *(const float4*)&g_q[(qb + r) * HD + h * DH + c4];
        uint32_t* d = &qs[r * 52 + c4];
        d[0] = f2tf32(v.x); d[1] = f2tf32(v.y);
        d[2] = f2tf32(v.z); d[3] = f2tf32(v.w);
    }

    float mrow0 = -1e30f, mrow1 = -1e30f, lrow0 = 0.f, lrow1 = 0.f;
    float oacc[6][4];
#pragma unroll
    for (int vt = 0; vt < 6; vt++)
#pragma unroll
        for (int u = 0; u < 4; u++) oacc[vt][u] = 0.f;

    float mq0 = mask[qb + m0 + lr];
    float mq1 = mask[qb + m0 + lr + 8];

    for (int jt = split * 4; jt < split * 4 + 4; jt++) {
        int j0 = jt * 64;
        __syncthreads();
        for (int t = tid; t < 768; t += 128) {
            int j = t & 63, dq = t >> 6;
            float4 v = *(const float4*)&g_k[(j0 + j) * HD + h * DH + dq * 4];
            kv[(dq * 4 + 0) * 72 + j] = f2tf32(v.x);
            kv[(dq * 4 + 1) * 72 + j] = f2tf32(v.y);
            kv[(dq * 4 + 2) * 72 + j] = f2tf32(v.z);
            kv[(dq * 4 + 3) * 72 + j] = f2tf32(v.w);
        }
        __syncthreads();

        float sacc[8][4];
#pragma unroll
        for (int nt = 0; nt < 8; nt++)
#pragma unroll
            for (int u = 0; u < 4; u++) sacc[nt][u] = 0.f;
#pragma unroll
        for (int k = 0; k < 6; k++) {
            int kk = k * 8;
            uint32_t a[4];
            int ar = m0 + lr, ac = kk + lc;
            a[0] = qs[ar * 52 + ac];
            a[1] = qs[(ar + 8) * 52 + ac];
            a[2] = qs[ar * 52 + ac + 4];
            a[3] = qs[(ar + 8) * 52 + ac + 4];
#pragma unroll
            for (int nt = 0; nt < 8; nt++) {
                uint32_t b[2];
                b[0] = kv[(kk + lc) * 72 + nt * 8 + lr];
                b[1] = kv[(kk + lc + 4) * 72 + nt * 8 + lr];
                mma_tf32(sacc[nt], a, b);
            }
        }

        float rmax0 = -1e30f, rmax1 = -1e30f;
#pragma unroll
        for (int nt = 0; nt < 8; nt++) {
            int jc = j0 + nt * 8 + 2 * lc;
            float2 b0 = *(const float2*)&g_bias[((size_t)h * NTOK + qb + m0 + lr) * NTOK + jc];
            float2 b1 = *(const float2*)&g_bias[((size_t)h * NTOK + qb + m0 + lr + 8) * NTOK + jc];
            float mk0 = mask[jc], mk1 = mask[jc + 1];
            sacc[nt][0] += b0.x + INFV * (mq0 * mk0 - 1.f);
            sacc[nt][1] += b0.y + INFV * (mq0 * mk1 - 1.f);
            sacc[nt][2] += b1.x + INFV * (mq1 * mk0 - 1.f);
            sacc[nt][3] += b1.y + INFV * (mq1 * mk1 - 1.f);
            rmax0 = fmaxf(rmax0, fmaxf(sacc[nt][0], sacc[nt][1]));
            rmax1 = fmaxf(rmax1, fmaxf(sacc[nt][2], sacc[nt][3]));
        }
#pragma unroll
        for (int off = 1; off < 4; off <<= 1) {
            rmax0 = fmaxf(rmax0, __shfl_xor_sync(0xffffffffu, rmax0, off));
            rmax1 = fmaxf(rmax1, __shfl_xor_sync(0xffffffffu, rmax1, off));
        }
        float mnew0 = fmaxf(mrow0, rmax0);
        float mnew1 = fmaxf(mrow1, rmax1);
        float scale0 = __expf(mrow0 - mnew0);
        float scale1 = __expf(mrow1 - mnew1);

        float sum0 = 0.f, sum1 = 0.f;
#pragma unroll
        for (int nt = 0; nt < 8; nt++) {
            sacc[nt][0] = __expf(sacc[nt][0] - mnew0);
            sacc[nt][1] = __expf(sacc[nt][1] - mnew0);
            sacc[nt][2] = __expf(sacc[nt][2] - mnew1);
            sacc[nt][3] = __expf(sacc[nt][3] - mnew1);
            sum0 += sacc[nt][0] + sacc[nt][1];
            sum1 += sacc[nt][2] + sacc[nt][3];
            uint2 p0, p1;
            p0.x = f2tf32(sacc[nt][0]); p0.y = f2tf32(sacc[nt][1]);
            p1.x = f2tf32(sacc[nt][2]); p1.y = f2tf32(sacc[nt][3]);
            *(uint2*)&ps[(m0 + lr) * 68 + nt * 8 + 2 * lc]     = p0;
            *(uint2*)&ps[(m0 + lr + 8) * 68 + nt * 8 + 2 * lc] = p1;
        }
#pragma unroll
        for (int off = 1; off < 4; off <<= 1) {
            sum0 += __shfl_xor_sync(0xffffffffu, sum0, off);
            sum1 += __shfl_xor_sync(0xffffffffu, sum1, off);
        }
        lrow0 = lrow0 * scale0 + sum0;  mrow0 = mnew0;
        lrow1 = lrow1 * scale1 + sum1;  mrow1 = mnew1;
#pragma unroll
        for (int vt = 0; vt < 6; vt++) {
            oacc[vt][0] *= scale0; oacc[vt][1] *= scale0;
            oacc[vt][2] *= scale1; oacc[vt][3] *= scale1;
        }

        __syncthreads();
        for (int t = tid; t < 768; t += 128) {
            int r = t / 12, c4 = (t % 12) * 4;
            float4 v = *(const float4*)&g_v[(j0 + r) * HD + h * DH + c4];
            uint32_t* d = &kv[r * 56 + c4];
            d[0] = f2tf32(v.x); d[1] = f2tf32(v.y);
            d[2] = f2tf32(v.z); d[3] = f2tf32(v.w);
        }
        __syncthreads();

#pragma unroll
        for (int k = 0; k < 8; k++) {
            int kk = k * 8;
            uint32_t a[4];
            int ar = m0 + lr, ac = kk + lc;
            a[0] = ps[ar * 68 + ac];
            a[1] = ps[(ar + 8) * 68 + ac];
            a[2] = ps[ar * 68 + ac + 4];
            a[3] = ps[(ar + 8) * 68 + ac + 4];
#pragma unroll
            for (int vt = 0; vt < 6; vt++) {
                uint32_t b[2];
                b[0] = kv[(kk + lc) * 56 + vt * 8 + lr];
                b[1] = kv[(kk + lc + 4) * 56 + vt * 8 + lr];
                mma_tf32(oacc[vt], a, b);
            }
        }
    }

    int q0 = qb + m0 + lr, q1 = q0 + 8;
    int pb0 = ((split * NH + h) * NTOK + q0) * DH;
    int pb1 = ((split * NH + h) * NTOK + q1) * DH;
#pragma unroll
    for (int vt = 0; vt < 6; vt++) {
        int d = vt * 8 + 2 * lc;
        *(float2*)&g_po[pb0 + d] = make_float2(oacc[vt][0], oacc[vt][1]);
        *(float2*)&g_po[pb1 + d] = make_float2(oacc[vt][2], oacc[vt][3]);
    }
    if (lc == 0) {
        g_pm[(split * NH + h) * NTOK + q0] = mrow0;
        g_pl[(split * NH + h) * NTOK + q0] = lrow0;
        g_pm[(split * NH + h) * NTOK + q1] = mrow1;
        g_pl[(split * NH + h) * NTOK + q1] = lrow1;
    }
}

// ===========================================================================
// Kernel 4b: merge 4 splits, normalize, apply gate -> g_og.  (R7)
// ===========================================================================
__global__ __launch_bounds__(256) void merge_kernel()
{
    int q = blockIdx.x;
    int t = threadIdx.x;
    int h = t >> 4;
    int d0 = (t & 15) * 3;

    float m[NSPLIT], l[NSPLIT];
    float M = -1e30f;
#pragma unroll
    for (int s = 0; s < NSPLIT; s++) {
        m[s] = g_pm[(s * NH + h) * NTOK + q];
        l[s] = g_pl[(s * NH + h) * NTOK + q];
        M = fmaxf(M, m[s]);
    }
    float w[NSPLIT], ltot = 0.f;
#pragma unroll
    for (int s = 0; s < NSPLIT; s++) {
        w[s] = __expf(m[s] - M);
        ltot += l[s] * w[s];
    }
    float inv = 1.f / ltot;
    int go = q * HD + h * DH + d0;
#pragma unroll
    for (int u = 0; u < 3; u++) {
        float val = 0.f;
#pragma unroll
        for (int s = 0; s < NSPLIT; s++)
            val += g_po[((s * NH + h) * NTOK + q) * DH + d0 + u] * w[s];
        g_og[go + u] = val * inv * g_g[go + u];
    }
}

// ===========================================================================
// Kernel 5: output projection via tf32 mma. BM=64, BN=64, BK=32. (R7)
// ===========================================================================
__global__ __launch_bounds__(128) void outproj_kernel(const float* __restrict__ W,
                                                      const float* __restrict__ bo,
                                                      float* __restrict__ out)
{
    int n0 = blockIdx.x * 64;
    int m0 = blockIdx.y * 64;

    __shared__ uint32_t As[64 * 36];
    __shared__ uint32_t Bs[32 * 72];

    int tid  = threadIdx.x;
    int lane = tid & 31;
    int warp = tid >> 5;
    int wm = warp >> 1, wn = warp & 1;
    int mw0 = wm * 32, nw0 = wn * 32;
    int lr = lane >> 2, lc = lane & 3;

    float acc[2][4][4];
#pragma unroll
    for (int mt = 0; mt < 2; mt++)
#pragma unroll
        for (int nt = 0; nt < 4; nt++)
#pragma unroll
            for (int u = 0; u < 4; u++) acc[mt][nt][u] = 0.f;

    for (int k0 = 0; k0 < HD; k0 += 32) {
#pragma unroll
        for (int it = 0; it < 4; it++) {
            int t = tid + it * 128;
            int r = t >> 3, c4 = t & 7;
            float4 v = *(const float4*)&g_og[(m0 + r) * HD + k0 + c4 * 4];
            uint32_t* d = &As[r * 36 + c4 * 4];
            d[0] = f2tf32(v.x); d[1] = f2tf32(v.y);
            d[2] = f2tf32(v.z); d[3] = f2tf32(v.w);
        }
#pragma unroll
        for (int it = 0; it < 4; it++) {
            int t = tid + it * 128;
            int r = t >> 4, c4 = t & 15;
            float4 v = *(const float4*)&W[(k0 + r) * CQ + n0 + c4 * 4];
            uint32_t* d = &Bs[r * 72 + c4 * 4];
            d[0] = f2tf32(v.x); d[1] = f2tf32(v.y);
            d[2] = f2tf32(v.z); d[3] = f2tf32(v.w);
        }
        __syncthreads();
#pragma unroll
        for (int ks = 0; ks < 4; ks++) {
            int kk = ks * 8;
            uint32_t a[2][4];
#pragma unroll
            for (int mt = 0; mt < 2; mt++) {
                int ar = mw0 + mt * 16 + lr;
                int ac = kk + lc;
                a[mt][0] = As[ar * 36 + ac];
                a[mt][1] = As[(ar + 8) * 36 + ac];
                a[mt][2] = As[ar * 36 + ac + 4];
                a[mt][3] = As[(ar + 8) * 36 + ac + 4];
            }
#pragma unroll
            for (int nt = 0; nt < 4; nt++) {
                uint32_t b[2];
                int bk = kk + lc;
                int bn = nw0 + nt * 8 + lr;
                b[0] = Bs[bk * 72 + bn];
                b[1] = Bs[(bk + 4) * 72 + bn];
                mma_tf32(acc[0][nt], a[0], b);
                mma_tf32(acc[1][nt], a[1], b);
            }
        }
        __syncthreads();
    }

#pragma unroll
    for (int mt = 0; mt < 2; mt++) {
#pragma unroll
        for (int nt = 0; nt < 4; nt++) {
            int cc = n0 + nw0 + nt * 8 + 2 * lc;
            float b0 = bo[cc], b1 = bo[cc + 1];
#pragma unroll
            for (int half = 0; half < 2; half++) {
                int r = m0 + mw0 + mt * 16 + lr + half * 8;
                float2 o2;
                o2.x = acc[mt][nt][half * 2 + 0] + b0;
                o2.y = acc[mt][nt][half * 2 + 1] + b1;
                *(float2*)&out[r * CQ + cc] = o2;
            }
        }
    }
}

// ===========================================================================
extern "C" void kernel_launch(void* const* d_in, const int* in_sizes, int n_in,
                              void* d_out, int out_size)
{
    const float* a    = (const float*)d_in[0];
    const float* z    = (const float*)d_in[1];
    const float* mask = (const float*)d_in[2];
    const float* g_a  = (const float*)d_in[3];
    const float* b_a  = (const float*)d_in[4];
    const float* g_z  = (const float*)d_in[5];
    const float* b_z  = (const float*)d_in[6];
    const float* w_z  = (const float*)d_in[7];
    const float* w_q  = (const float*)d_in[8];
    const float* w_k  = (const float*)d_in[9];
    const float* w_v  = (const float*)d_in[10];
    const float* w_g  = (const float*)d_in[11];
    const float* b_g  = (const float*)d_in[12];
    const float* w_o  = (const float*)d_in[13];
    const float* b_o  = (const float*)d_in[14];
    float* out = (float*)d_out;

    pb_setup_kernel<<<1, 128>>>(g_z, b_z, w_z);
    ln_a_kernel<<<NTOK, 256>>>(a, g_a, b_a);
    proj_kernel<<<dim3(24, 16), 128>>>(w_q, w_k, w_v, w_g, b_g);
    pairbias_kernel<<<dim3(16, NTOK), 128>>>(z);
    attn_kernel<<<dim3(16, NH, NSPLIT), 128>>>(mask);
    merge_kernel<<<NTOK, 256>>>();
    outproj_kernel<<<dim3(12, 16), 128>>>(w_o, b_o, out);
}

// round 11
// speedup vs baseline: 2.7434x; 1.1442x over previous
#include <cuda_runtime.h>
#include <math.h>
#include <stdint.h>

#define NTOK 1024
#define CQ   768
#define CZ   128
#define NH   16
#define DH   48
#define HD   768
#define EPSV 1e-5f
#define INFV 1.0e9f
#define NSPLIT 4

// ------------- static device scratch (no allocations allowed) -------------
__device__ float g_an[NTOK * CQ];
__device__ float g_q [NTOK * HD];
__device__ float g_k [NTOK * HD];
__device__ float g_v [NTOK * HD];
__device__ float g_g [NTOK * HD];
__device__ float g_og[NTOK * HD];
__device__ float g_bias[(size_t)NH * NTOK * NTOK];   // [h][i][j] 64 MB
__device__ float g_po[NSPLIT * NH * NTOK * DH];      // unnormalized o partials
__device__ float g_pm[NSPLIT * NH * NTOK];
__device__ float g_pl[NSPLIT * NH * NTOK];
// wgt fragment-quad layout: head h, lc, group g (k-steps 2g,2g+1):
//   [h*144 + lc*36 + g*4 + w], w: {c=16g+lc, 16g+lc+4, 16g+8+lc, 16g+8+lc+4}
__device__ __align__(16) uint32_t g_wgt[NH * 144];
__device__ float g_Svec[NH], g_Bcvec[NH];

// ------------------------- tf32 mma helpers -------------------------------
__device__ __forceinline__ uint32_t f2tf32(float f) {
    uint32_t r;
    asm("cvt.rna.tf32.f32 %0, %1;" : "=r"(r) : "f"(f));
    return r;
}
__device__ __forceinline__ void mma_tf32(float* d, const uint32_t* a, const uint32_t* b) {
    asm("mma.sync.aligned.m16n8k8.row.col.f32.tf32.tf32.f32 "
        "{%0,%1,%2,%3}, {%4,%5,%6,%7}, {%8,%9}, {%0,%1,%2,%3};"
        : "+f"(d[0]), "+f"(d[1]), "+f"(d[2]), "+f"(d[3])
        : "r"(a[0]), "r"(a[1]), "r"(a[2]), "r"(a[3]), "r"(b[0]), "r"(b[1]));
}
__device__ __forceinline__ uint32_t smem_u32(const void* p) {
    uint32_t r;
    asm("{.reg .u64 t; cvta.to.shared.u64 t, %1; cvt.u32.u64 %0, t;}" : "=r"(r) : "l"(p));
    return r;
}
__device__ __forceinline__ void cp_async16(uint32_t dst, const void* src) {
    asm volatile("cp.async.cg.shared.global [%0], [%1], 16;" :: "r"(dst), "l"(src));
}
__device__ __forceinline__ void cp_async_wait_all() {
    asm volatile("cp.async.commit_group;\n cp.async.wait_group 0;" ::: "memory");
}

// ===========================================================================
// Kernel 1: LayerNorm(a) -> g_an (blocks 0..1023); block 1024 = pb setup.
// ===========================================================================
__global__ __launch_bounds__(256) void ln_a_kernel(const float* __restrict__ a,
                                                   const float* __restrict__ ga,
                                                   const float* __restrict__ ba,
                                                   const float* __restrict__ gz,
                                                   const float* __restrict__ bz,
                                                   const float* __restrict__ wz)
{
    int row = blockIdx.x;
    int tid = threadIdx.x;
    if (row == NTOK) {
        // pair-bias setup: fragment-quad tf32 wgt + S/Bc vectors
        for (int i = tid; i < NH * 144; i += 256) g_wgt[i] = 0u;
        __syncthreads();
        for (int i = tid; i < NH * CZ; i += 256) {
            int h = i >> 7, c = i & 127;
            int g = c >> 4, rem = c & 15;
            int lc = rem & 3, w = rem >> 2;
            g_wgt[h * 144 + lc * 36 + g * 4 + w] = f2tf32(gz[c] * wz[c * NH + h]);
        }
        if (tid < NH) {
            float S = 0.f, Bc = 0.f;
            for (int c = 0; c < CZ; c++) {
                S  += gz[c] * wz[c * NH + tid];
                Bc += bz[c] * wz[c * NH + tid];
            }
            g_Svec[tid] = S; g_Bcvec[tid] = Bc;
        }
        return;
    }
    const float* x = a + row * CQ;
    float v0 = x[tid], v1 = x[tid + 256], v2 = x[tid + 512];
    float s = v0 + v1 + v2;
    float q = v0 * v0 + v1 * v1 + v2 * v2;
#pragma unroll
    for (int o = 16; o > 0; o >>= 1) {
        s += __shfl_xor_sync(0xffffffffu, s, o);
        q += __shfl_xor_sync(0xffffffffu, q, o);
    }
    __shared__ float sw[8], qw[8];
    __shared__ float smu, srv;
    if ((tid & 31) == 0) { sw[tid >> 5] = s; qw[tid >> 5] = q; }
    __syncthreads();
    if (tid == 0) {
        float S = 0.f, Q = 0.f;
#pragma unroll
        for (int w = 0; w < 8; w++) { S += sw[w]; Q += qw[w]; }
        float mu = S * (1.f / (float)CQ);
        float var = Q * (1.f / (float)CQ) - mu * mu;
        smu = mu;
        srv = rsqrtf(fmaxf(var, 0.f) + EPSV);
    }
    __syncthreads();
    float mu = smu, r = srv;
    float* o = g_an + row * CQ;
    o[tid]       = (v0 - mu) * r * ga[tid]       + ba[tid];
    o[tid + 256] = (v1 - mu) * r * ga[tid + 256] + ba[tid + 256];
    o[tid + 512] = (v2 - mu) * r * ga[tid + 512] + ba[tid + 512];
}

// ===========================================================================
// Kernel 2: fused QKVG projections via tf32 mma. BM=64, BN=128, BK=32. (R7)
// ===========================================================================
__global__ __launch_bounds__(128) void proj_kernel(const float* __restrict__ Wq,
                                                   const float* __restrict__ Wk,
                                                   const float* __restrict__ Wv,
                                                   const float* __restrict__ Wg,
                                                   const float* __restrict__ bg)
{
    int n0 = blockIdx.x * 128;
    int sel  = n0 / HD;
    int ncol = n0 - sel * HD;
    const float* W = (sel == 0) ? Wq : (sel == 1) ? Wk : (sel == 2) ? Wv : Wg;
    float*       O = (sel == 0) ? g_q : (sel == 1) ? g_k : (sel == 2) ? g_v : g_g;
    int m0 = blockIdx.y * 64;

    __shared__ __align__(16) uint32_t As[64 * 36];
    __shared__ __align__(16) uint32_t Bs[32 * 136];

    int tid  = threadIdx.x;
    int lane = tid & 31;
    int warp = tid >> 5;
    int wm = warp >> 1, wn = warp & 1;
    int mw0 = wm * 32, nw0 = wn * 64;
    int lr = lane >> 2, lc = lane & 3;

    float acc[2][8][4];
#pragma unroll
    for (int mt = 0; mt < 2; mt++)
#pragma unroll
        for (int nt = 0; nt < 8; nt++)
#pragma unroll
            for (int u = 0; u < 4; u++) acc[mt][nt][u] = 0.f;

    for (int k0 = 0; k0 < CQ; k0 += 32) {
#pragma unroll
        for (int it = 0; it < 4; it++) {
            int t = tid + it * 128;
            int r = t >> 3, c4 = t & 7;
            float4 v = *(const float4*)&g_an[(m0 + r) * CQ + k0 + c4 * 4];
            uint32_t* d = &As[r * 36 + c4 * 4];
            d[0] = f2tf32(v.x); d[1] = f2tf32(v.y);
            d[2] = f2tf32(v.z); d[3] = f2tf32(v.w);
        }
#pragma unroll
        for (int it = 0; it < 8; it++) {
            int t = tid + it * 128;
            int r = t >> 5, c4 = t & 31;
            float4 v = *(const float4*)&W[(k0 + r) * HD + ncol + c4 * 4];
            uint32_t* d = &Bs[r * 136 + c4 * 4];
            d[0] = f2tf32(v.x); d[1] = f2tf32(v.y);
            d[2] = f2tf32(v.z); d[3] = f2tf32(v.w);
        }
        __syncthreads();
#pragma unroll
        for (int ks = 0; ks < 4; ks++) {
            int kk = ks * 8;
            uint32_t a[2][4];
#pragma unroll
            for (int mt = 0; mt < 2; mt++) {
                int ar = mw0 + mt * 16 + lr;
                int ac = kk + lc;
                a[mt][0] = As[ar * 36 + ac];
                a[mt][1] = As[(ar + 8) * 36 + ac];
                a[mt][2] = As[ar * 36 + ac + 4];
                a[mt][3] = As[(ar + 8) * 36 + ac + 4];
            }
#pragma unroll
            for (int nt = 0; nt < 8; nt++) {
                uint32_t b[2];
                int bk = kk + lc;
                int bn = nw0 + nt * 8 + lr;
                b[0] = Bs[bk * 136 + bn];
                b[1] = Bs[(bk + 4) * 136 + bn];
                mma_tf32(acc[0][nt], a[0], b);
                mma_tf32(acc[1][nt], a[1], b);
            }
        }
        __syncthreads();
    }

    const float scaleq = 0.14433756729740643f;
#pragma unroll
    for (int mt = 0; mt < 2; mt++) {
#pragma unroll
        for (int nt = 0; nt < 8; nt++) {
            int cc = ncol + nw0 + nt * 8 + 2 * lc;
#pragma unroll
            for (int half = 0; half < 2; half++) {
                int r = m0 + mw0 + mt * 16 + lr + half * 8;
                float v0 = acc[mt][nt][half * 2 + 0];
                float v1 = acc[mt][nt][half * 2 + 1];
                if (sel == 0) { v0 *= scaleq; v1 *= scaleq; }
                else if (sel == 3) {
                    v0 = 1.f / (1.f + __expf(-(v0 + bg[cc])));
                    v1 = 1.f / (1.f + __expf(-(v1 + bg[cc + 1])));
                }
                float2 o2; o2.x = v0; o2.y = v1;
                *(float2*)&O[r * HD + cc] = o2;
            }
        }
    }
}

// ===========================================================================
// Kernel 3: pair bias via tf32 mma + fused LN.
//  - z staged fp32 via cp.async.cg (L1 bypassed), cvt at A-fragment load
//  - wgt fragment-quad layout: B-frags via aligned LDS.128, conflict-free
// Grid (16 j-tiles, 1024 i), 128 threads.
// ===========================================================================
__global__ __launch_bounds__(128) void pairbias_kernel(const float* __restrict__ z)
{
    __shared__ __align__(16) float    ztf[64 * 132];   // fp32 z; reused as out stage
    __shared__ __align__(16) uint32_t wgt[NH * 144];   // tf32, fragment-quad
    __shared__ float Ssh[NH], Bcsh[NH], mus[64], rvs[64];

    int tid  = threadIdx.x;
    int lane = tid & 31;
    int warp = tid >> 5;
    int i  = blockIdx.y;
    int j0 = blockIdx.x * 64;

    // async-stage wgt (2304 words = 576 uint4) and z (2048 float4)
    {
        const uint4* src = (const uint4*)g_wgt;
        for (int t2 = tid; t2 < 576; t2 += 128)
            cp_async16(smem_u32((uint4*)wgt + t2), src + t2);
    }
    const float4* zb = (const float4*)(z + ((size_t)i * NTOK + j0) * CZ);
#pragma unroll
    for (int u = 0; u < 16; u++) {
        int idx = tid + 128 * u;
        int r = idx >> 5;
        cp_async16(smem_u32(&ztf[r * 132 + lane * 4]), zb + idx);
    }
    if (tid < NH) { Ssh[tid] = g_Svec[tid]; Bcsh[tid] = g_Bcvec[tid]; }
    cp_async_wait_all();
    __syncthreads();

    // LN stats from fp32 smem: warps 0-1, one row per thread
    if (tid < 64) {
        float s = 0.f, sq = 0.f;
        const float* zr = &ztf[tid * 132];
#pragma unroll
        for (int cq = 0; cq < 32; cq++) {
            float4 w = *(const float4*)&zr[cq * 4];
            s += w.x + w.y + w.z + w.w;
            sq = fmaf(w.x, w.x, sq); sq = fmaf(w.y, w.y, sq);
            sq = fmaf(w.z, w.z, sq); sq = fmaf(w.w, w.w, sq);
        }
        float mu  = s * (1.f / (float)CZ);
        float var = sq * (1.f / (float)CZ) - mu * mu;
        mus[tid] = mu;
        rvs[tid] = rsqrtf(fmaxf(var, 0.f) + EPSV);
    }

    // mma: warp owns rows [warp*16, warp*16+16), N=16, K=128
    int m0 = warp * 16;
    int lr = lane >> 2, lc = lane & 3;
    float acc[2][4];
#pragma unroll
    for (int n = 0; n < 2; n++)
#pragma unroll
        for (int u = 0; u < 4; u++) acc[n][u] = 0.f;

    const uint32_t* wgt0 = &wgt[lr * 144 + lc * 36];        // head row lr   (n=0)
    const uint32_t* wgt1 = &wgt[(8 + lr) * 144 + lc * 36];  // head row 8+lr (n=1)
#pragma unroll
    for (int g = 0; g < 8; g++) {
        uint4 bq0 = *(const uint4*)(wgt0 + g * 4);   // b-pairs for k=2g, 2g+1
        uint4 bq1 = *(const uint4*)(wgt1 + g * 4);
#pragma unroll
        for (int kh = 0; kh < 2; kh++) {
            int kk = (g * 2 + kh) * 8;
            int ar = m0 + lr, ac = kk + lc;
            uint32_t a[4];
            a[0] = f2tf32(ztf[ar * 132 + ac]);
            a[1] = f2tf32(ztf[(ar + 8) * 132 + ac]);
            a[2] = f2tf32(ztf[ar * 132 + ac + 4]);
            a[3] = f2tf32(ztf[(ar + 8) * 132 + ac + 4]);
            uint32_t b0[2], b1[2];
            b0[0] = kh ? bq0.z : bq0.x;  b0[1] = kh ? bq0.w : bq0.y;
            b1[0] = kh ? bq1.z : bq1.x;  b1[1] = kh ? bq1.w : bq1.y;
            mma_tf32(acc[0], a, b0);
            mma_tf32(acc[1], a, b1);
        }
    }
    __syncthreads();   // mus/rvs visible; all ztf mma reads done

    float* outs = ztf;                    // [h][j], stride 68
#pragma unroll
    for (int n = 0; n < 2; n++) {
        int h0 = n * 8 + 2 * lc;
#pragma unroll
        for (int half = 0; half < 2; half++) {
            int r = m0 + lr + half * 8;
            float mu = mus[r], rv = rvs[r];
            outs[h0 * 68 + r]       = rv * (acc[n][half * 2 + 0] - mu * Ssh[h0])     + Bcsh[h0];
            outs[(h0 + 1) * 68 + r] = rv * (acc[n][half * 2 + 1] - mu * Ssh[h0 + 1]) + Bcsh[h0 + 1];
        }
    }
    __syncthreads();
#pragma unroll
    for (int it = 0; it < 2; it++) {
        int idx = tid + 128 * it;
        int h = idx >> 4, j4 = (idx & 15) * 4;
        float4 o4;
        o4.x = outs[h * 68 + j4 + 0];
        o4.y = outs[h * 68 + j4 + 1];
        o4.z = outs[h * 68 + j4 + 2];
        o4.w = outs[h * 68 + j4 + 3];
        *(float4*)&g_bias[((size_t)h * NTOK + i) * NTOK + j0 + j4] = o4;
    }
}

// ===========================================================================
// Kernel 4: flash attention via tf32 mma, split-KV x4, partials out. (R7)
// ===========================================================================
__global__ __launch_bounds__(128) void attn_kernel(const float* __restrict__ mask)
{
    int h     = blockIdx.y;
    int qb    = blockIdx.x * 64;
    int split = blockIdx.z;
    int tid  = threadIdx.x;
    int lane = tid & 31;
    int warp = tid >> 5;
    int lr = lane >> 2, lc = lane & 3;
    int m0 = warp * 16;

    __shared__ __align__(16) uint32_t qs[64 * 52];
    __shared__ __align__(16) uint32_t kv[64 * 56];   // union: K^T[48][72] / V[64][56]
    __shared__ __align__(16) uint32_t ps[64 * 68];

    for (int t = tid; t < 768; t += 128) {
        int r = t / 12, c4 = (t % 12) * 4;
        float4 v = *(const float4*)&g_q[(qb + r) * HD + h * DH + c4];
        uint32_t* d = &qs[r * 52 + c4];
        d[0] = f2tf32(v.x); d[1] = f2tf32(v.y);
        d[2] = f2tf32(v.z); d[3] = f2tf32(v.w);
    }

    float mrow0 = -1e30f, mrow1 = -1e30f, lrow0 = 0.f, lrow1 = 0.f;
    float oacc[6][4];
#pragma unroll
    for (int vt = 0; vt < 6; vt++)
#pragma unroll
        for (int u = 0; u < 4; u++) oacc[vt][u] = 0.f;

    float mq0 = mask[qb + m0 + lr];
    float mq1 = mask[qb + m0 + lr + 8];

    for (int jt = split * 4; jt < split * 4 + 4; jt++) {
        int j0 = jt * 64;
        __syncthreads();
        for (int t = tid; t < 768; t += 128) {
            int j = t & 63, dq = t >> 6;
            float4 v = *(const float4*)&g_k[(j0 + j) * HD + h * DH + dq * 4];
            kv[(dq * 4 + 0) * 72 + j] = f2tf32(v.x);
            kv[(dq * 4 + 1) * 72 + j] = f2tf32(v.y);
            kv[(dq * 4 + 2) * 72 + j] = f2tf32(v.z);
            kv[(dq * 4 + 3) * 72 + j] = f2tf32(v.w);
        }
        __syncthreads();

        float sacc[8][4];
#pragma unroll
        for (int nt = 0; nt < 8; nt++)
#pragma unroll
            for (int u = 0; u < 4; u++) sacc[nt][u] = 0.f;
#pragma unroll
        for (int k = 0; k < 6; k++) {
            int kk = k * 8;
            uint32_t a[4];
            int ar = m0 + lr, ac = kk + lc;
            a[0] = qs[ar * 52 + ac];
            a[1] = qs[(ar + 8) * 52 + ac];
            a[2] = qs[ar * 52 + ac + 4];
            a[3] = qs[(ar + 8) * 52 + ac + 4];
#pragma unroll
            for (int nt = 0; nt < 8; nt++) {
                uint32_t b[2];
                b[0] = kv[(kk + lc) * 72 + nt * 8 + lr];
                b[1] = kv[(kk + lc + 4) * 72 + nt * 8 + lr];
                mma_tf32(sacc[nt], a, b);
            }
        }

        float rmax0 = -1e30f, rmax1 = -1e30f;
#pragma unroll
        for (int nt = 0; nt < 8; nt++) {
            int jc = j0 + nt * 8 + 2 * lc;
            float2 b0 = *(const float2*)&g_bias[((size_t)h * NTOK + qb + m0 + lr) * NTOK + jc];
            float2 b1 = *(const float2*)&g_bias[((size_t)h * NTOK + qb + m0 + lr + 8) * NTOK + jc];
            float mk0 = mask[jc], mk1 = mask[jc + 1];
            sacc[nt][0] += b0.x + INFV * (mq0 * mk0 - 1.f);
            sacc[nt][1] += b0.y + INFV * (mq0 * mk1 - 1.f);
            sacc[nt][2] += b1.x + INFV * (mq1 * mk0 - 1.f);
            sacc[nt][3] += b1.y + INFV * (mq1 * mk1 - 1.f);
            rmax0 = fmaxf(rmax0, fmaxf(sacc[nt][0], sacc[nt][1]));
            rmax1 = fmaxf(rmax1, fmaxf(sacc[nt][2], sacc[nt][3]));
        }
#pragma unroll
        for (int off = 1; off < 4; off <<= 1) {
            rmax0 = fmaxf(rmax0, __shfl_xor_sync(0xffffffffu, rmax0, off));
            rmax1 = fmaxf(rmax1, __shfl_xor_sync(0xffffffffu, rmax1, off));
        }
        float mnew0 = fmaxf(mrow0, rmax0);
        float mnew1 = fmaxf(mrow1, rmax1);
        float scale0 = __expf(mrow0 - mnew0);
        float scale1 = __expf(mrow1 - mnew1);

        float sum0 = 0.f, sum1 = 0.f;
#pragma unroll
        for (int nt = 0; nt < 8; nt++) {
            sacc[nt][0] = __expf(sacc[nt][0] - mnew0);
            sacc[nt][1] = __expf(sacc[nt][1] - mnew0);
            sacc[nt][2] = __expf(sacc[nt][2] - mnew1);
            sacc[nt][3] = __expf(sacc[nt][3] - mnew1);
            sum0 += sacc[nt][0] + sacc[nt][1];
            sum1 += sacc[nt][2] + sacc[nt][3];
            uint2 p0, p1;
            p0.x = f2tf32(sacc[nt][0]); p0.y = f2tf32(sacc[nt][1]);
            p1.x = f2tf32(sacc[nt][2]); p1.y = f2tf32(sacc[nt][3]);
            *(uint2*)&ps[(m0 + lr) * 68 + nt * 8 + 2 * lc]     = p0;
            *(uint2*)&ps[(m0 + lr + 8) * 68 + nt * 8 + 2 * lc] = p1;
        }
#pragma unroll
        for (int off = 1; off < 4; off <<= 1) {
            sum0 += __shfl_xor_sync(0xffffffffu, sum0, off);
            sum1 += __shfl_xor_sync(0xffffffffu, sum1, off);
        }
        lrow0 = lrow0 * scale0 + sum0;  mrow0 = mnew0;
        lrow1 = lrow1 * scale1 + sum1;  mrow1 = mnew1;
#pragma unroll
        for (int vt = 0; vt < 6; vt++) {
            oacc[vt][0] *= scale0; oacc[vt][1] *= scale0;
            oacc[vt][2] *= scale1; oacc[vt][3] *= scale1;
        }

        __syncthreads();
        for (int t = tid; t < 768; t += 128) {
            int r = t / 12, c4 = (t % 12) * 4;
            float4 v = *(const float4*)&g_v[(j0 + r) * HD + h * DH + c4];
            uint32_t* d = &kv[r * 56 + c4];
            d[0] = f2tf32(v.x); d[1] = f2tf32(v.y);
            d[2] = f2tf32(v.z); d[3] = f2tf32(v.w);
        }
        __syncthreads();

#pragma unroll
        for (int k = 0; k < 8; k++) {
            int kk = k * 8;
            uint32_t a[4];
            int ar = m0 + lr, ac = kk + lc;
            a[0] = ps[ar * 68 + ac];
            a[1] = ps[(ar + 8) * 68 + ac];
            a[2] = ps[ar * 68 + ac + 4];
            a[3] = ps[(ar + 8) * 68 + ac + 4];
#pragma unroll
            for (int vt = 0; vt < 6; vt++) {
                uint32_t b[2];
                b[0] = kv[(kk + lc) * 56 + vt * 8 + lr];
                b[1] = kv[(kk + lc + 4) * 56 + vt * 8 + lr];
                mma_tf32(oacc[vt], a, b);
            }
        }
    }

    int q0 = qb + m0 + lr, q1 = q0 + 8;
    int pb0 = ((split * NH + h) * NTOK + q0) * DH;
    int pb1 = ((split * NH + h) * NTOK + q1) * DH;
#pragma unroll
    for (int vt = 0; vt < 6; vt++) {
        int d = vt * 8 + 2 * lc;
        *(float2*)&g_po[pb0 + d] = make_float2(oacc[vt][0], oacc[vt][1]);
        *(float2*)&g_po[pb1 + d] = make_float2(oacc[vt][2], oacc[vt][3]);
    }
    if (lc == 0) {
        g_pm[(split * NH + h) * NTOK + q0] = mrow0;
        g_pl[(split * NH + h) * NTOK + q0] = lrow0;
        g_pm[(split * NH + h) * NTOK + q1] = mrow1;
        g_pl[(split * NH + h) * NTOK + q1] = lrow1;
    }
}

// ===========================================================================
// Kernel 4b: merge 4 splits, normalize, apply gate -> g_og.  (R7)
// ===========================================================================
__global__ __launch_bounds__(256) void merge_kernel()
{
    int q = blockIdx.x;
    int t = threadIdx.x;
    int h = t >> 4;
    int d0 = (t & 15) * 3;

    float m[NSPLIT], l[NSPLIT];
    float M = -1e30f;
#pragma unroll
    for (int s = 0; s < NSPLIT; s++) {
        m[s] = g_pm[(s * NH + h) * NTOK + q];
        l[s] = g_pl[(s * NH + h) * NTOK + q];
        M = fmaxf(M, m[s]);
    }
    float w[NSPLIT], ltot = 0.f;
#pragma unroll
    for (int s = 0; s < NSPLIT; s++) {
        w[s] = __expf(m[s] - M);
        ltot += l[s] * w[s];
    }
    float inv = 1.f / ltot;
    int go = q * HD + h * DH + d0;
#pragma unroll
    for (int u = 0; u < 3; u++) {
        float val = 0.f;
#pragma unroll
        for (int s = 0; s < NSPLIT; s++)
            val += g_po[((s * NH + h) * NTOK + q) * DH + d0 + u] * w[s];
        g_og[go + u] = val * inv * g_g[go + u];
    }
}

// ===========================================================================
// Kernel 5: output projection via tf32 mma. BM=64, BN=64, BK=32. (R7)
// ===========================================================================
__global__ __launch_bounds__(128) void outproj_kernel(const float* __restrict__ W,
                                                      const float* __restrict__ bo,
                                                      float* __restrict__ out)
{
    int n0 = blockIdx.x * 64;
    int m0 = blockIdx.y * 64;

    __shared__ __align__(16) uint32_t As[64 * 36];
    __shared__ __align__(16) uint32_t Bs[32 * 72];

    int tid  = threadIdx.x;
    int lane = tid & 31;
    int warp = tid >> 5;
    int wm = warp >> 1, wn = warp & 1;
    int mw0 = wm * 32, nw0 = wn * 32;
    int lr = lane >> 2, lc = lane & 3;

    float acc[2][4][4];
#pragma unroll
    for (int mt = 0; mt < 2; mt++)
#pragma unroll
        for (int nt = 0; nt < 4; nt++)
#pragma unroll
            for (int u = 0; u < 4; u++) acc[mt][nt][u] = 0.f;

    for (int k0 = 0; k0 < HD; k0 += 32) {
#pragma unroll
        for (int it = 0; it < 4; it++) {
            int t = tid + it * 128;
            int r = t >> 3, c4 = t & 7;
            float4 v = *(const float4*)&g_og[(m0 + r) * HD + k0 + c4 * 4];
            uint32_t* d = &As[r * 36 + c4 * 4];
            d[0] = f2tf32(v.x); d[1] = f2tf32(v.y);
            d[2] = f2tf32(v.z); d[3] = f2tf32(v.w);
        }
#pragma unroll
        for (int it = 0; it < 4; it++) {
            int t = tid + it * 128;
            int r = t >> 4, c4 = t & 15;
            float4 v = *(const float4*)&W[(k0 + r) * CQ + n0 + c4 * 4];
            uint32_t* d = &Bs[r * 72 + c4 * 4];
            d[0] = f2tf32(v.x); d[1] = f2tf32(v.y);
            d[2] = f2tf32(v.z); d[3] = f2tf32(v.w);
        }
        __syncthreads();
#pragma unroll
        for (int ks = 0; ks < 4; ks++) {
            int kk = ks * 8;
            uint32_t a[2][4];
#pragma unroll
            for (int mt = 0; mt < 2; mt++) {
                int ar = mw0 + mt * 16 + lr;
                int ac = kk + lc;
                a[mt][0] = As[ar * 36 + ac];
                a[mt][1] = As[(ar + 8) * 36 + ac];
                a[mt][2] = As[ar * 36 + ac + 4];
                a[mt][3] = As[(ar + 8) * 36 + ac + 4];
            }
#pragma unroll
            for (int nt = 0; nt < 4; nt++) {
                uint32_t b[2];
                int bk = kk + lc;
                int bn = nw0 + nt * 8 + lr;
                b[0] = Bs[bk * 72 + bn];
                b[1] = Bs[(bk + 4) * 72 + bn];
                mma_tf32(acc[0][nt], a[0], b);
                mma_tf32(acc[1][nt], a[1], b);
            }
        }
        __syncthreads();
    }

#pragma unroll
    for (int mt = 0; mt < 2; mt++) {
#pragma unroll
        for (int nt = 0; nt < 4; nt++) {
            int cc = n0 + nw0 + nt * 8 + 2 * lc;
            float b0 = bo[cc], b1 = bo[cc + 1];
#pragma unroll
            for (int half = 0; half < 2; half++) {
                int r = m0 + mw0 + mt * 16 + lr + half * 8;
                float2 o2;
                o2.x = acc[mt][nt][half * 2 + 0] + b0;
                o2.y = acc[mt][nt][half * 2 + 1] + b1;
                *(float2*)&out[r * CQ + cc] = o2;
            }
        }
    }
}

// ===========================================================================
extern "C" void kernel_launch(void* const* d_in, const int* in_sizes, int n_in,
                              void* d_out, int out_size)
{
    const float* a    = (const float*)d_in[0];
    const float* z    = (const float*)d_in[1];
    const float* mask = (const float*)d_in[2];
    const float* g_a  = (const float*)d_in[3];
    const float* b_a  = (const float*)d_in[4];
    const float* g_z  = (const float*)d_in[5];
    const float* b_z  = (const float*)d_in[6];
    const float* w_z  = (const float*)d_in[7];
    const float* w_q  = (const float*)d_in[8];
    const float* w_k  = (const float*)d_in[9];
    const float* w_v  = (const float*)d_in[10];
    const float* w_g  = (const float*)d_in[11];
    const float* b_g  = (const float*)d_in[12];
    const float* w_o  = (const float*)d_in[13];
    const float* b_o  = (const float*)d_in[14];
    float* out = (float*)d_out;

    ln_a_kernel<<<NTOK + 1, 256>>>(a, g_a, b_a, g_z, b_z, w_z);
    proj_kernel<<<dim3(24, 16), 128>>>(w_q, w_k, w_v, w_g, b_g);
    pairbias_kernel<<<dim3(16, NTOK), 128>>>(z);
    attn_kernel<<<dim3(16, NH, NSPLIT), 128>>>(mask);
    merge_kernel<<<NTOK, 256>>>();
    outproj_kernel<<<dim3(12, 16), 128>>>(w_o, b_o, out);
}

// round 12
// speedup vs baseline: 3.0167x; 1.0996x over previous
#include <cuda_runtime.h>
#include <cuda_fp16.h>
#include <math.h>
#include <stdint.h>

#define NTOK 1024
#define CQ   768
#define CZ   128
#define NH   16
#define DH   48
#define HD   768
#define EPSV 1e-5f
#define INFV 1.0e9f
#define NSPLIT 4

// ------------- static device scratch (no allocations allowed) -------------
__device__ float g_an[NTOK * CQ];
__device__ float g_q [NTOK * HD];
__device__ float g_k [NTOK * HD];
__device__ float g_v [NTOK * HD];
__device__ float g_g [NTOK * HD];
__device__ float g_og[NTOK * HD];
__device__ float g_bias[(size_t)NH * NTOK * NTOK];   // [h][i][j] 64 MB
__device__ float g_po[NSPLIT * NH * NTOK * DH];      // unnormalized o partials
__device__ float g_pm[NSPLIT * NH * NTOK];
__device__ float g_pl[NSPLIT * NH * NTOK];
// wgt fragment-quad layout: head h, lc, group g (k-steps 2g,2g+1):
//   [h*144 + lc*36 + g*4 + w], w: {c=16g+lc, 16g+lc+4, 16g+8+lc, 16g+8+lc+4}
__device__ __align__(16) uint32_t g_wgt[NH * 144];
__device__ float g_Svec[NH], g_Bcvec[NH];

// ------------------------- mma helpers -------------------------------
__device__ __forceinline__ uint32_t f2tf32(float f) {
    uint32_t r;
    asm("cvt.rna.tf32.f32 %0, %1;" : "=r"(r) : "f"(f));
    return r;
}
__device__ __forceinline__ void mma_tf32(float* d, const uint32_t* a, const uint32_t* b) {
    asm("mma.sync.aligned.m16n8k8.row.col.f32.tf32.tf32.f32 "
        "{%0,%1,%2,%3}, {%4,%5,%6,%7}, {%8,%9}, {%0,%1,%2,%3};"
        : "+f"(d[0]), "+f"(d[1]), "+f"(d[2]), "+f"(d[3])
        : "r"(a[0]), "r"(a[1]), "r"(a[2]), "r"(a[3]), "r"(b[0]), "r"(b[1]));
}
__device__ __forceinline__ void mma_f16(float* d, const uint32_t* a, const uint32_t* b) {
    asm("mma.sync.aligned.m16n8k16.row.col.f32.f16.f16.f32 "
        "{%0,%1,%2,%3}, {%4,%5,%6,%7}, {%8,%9}, {%0,%1,%2,%3};"
        : "+f"(d[0]), "+f"(d[1]), "+f"(d[2]), "+f"(d[3])
        : "r"(a[0]), "r"(a[1]), "r"(a[2]), "r"(a[3]), "r"(b[0]), "r"(b[1]));
}
__device__ __forceinline__ uint32_t packh2(float lo, float hi) {
    __half2 h = __floats2half2_rn(lo, hi);
    return *(uint32_t*)&h;
}
__device__ __forceinline__ uint32_t smem_u32(const void* p) {
    uint32_t r;
    asm("{.reg .u64 t; cvta.to.shared.u64 t, %1; cvt.u32.u64 %0, t;}" : "=r"(r) : "l"(p));
    return r;
}
__device__ __forceinline__ void cp_async16(uint32_t dst, const void* src) {
    asm volatile("cp.async.cg.shared.global [%0], [%1], 16;" :: "r"(dst), "l"(src));
}
__device__ __forceinline__ void cp_async_wait_all() {
    asm volatile("cp.async.commit_group;\n cp.async.wait_group 0;" ::: "memory");
}

// ===========================================================================
// Kernel 1: LayerNorm(a) -> g_an (blocks 0..1023); block 1024 = pb setup.
// ===========================================================================
__global__ __launch_bounds__(256) void ln_a_kernel(const float* __restrict__ a,
                                                   const float* __restrict__ ga,
                                                   const float* __restrict__ ba,
                                                   const float* __restrict__ gz,
                                                   const float* __restrict__ bz,
                                                   const float* __restrict__ wz)
{
    int row = blockIdx.x;
    int tid = threadIdx.x;
    if (row == NTOK) {
        for (int i = tid; i < NH * 144; i += 256) g_wgt[i] = 0u;
        __syncthreads();
        for (int i = tid; i < NH * CZ; i += 256) {
            int h = i >> 7, c = i & 127;
            int g = c >> 4, rem = c & 15;
            int lc = rem & 3, w = rem >> 2;
            g_wgt[h * 144 + lc * 36 + g * 4 + w] = f2tf32(gz[c] * wz[c * NH + h]);
        }
        if (tid < NH) {
            float S = 0.f, Bc = 0.f;
            for (int c = 0; c < CZ; c++) {
                S  += gz[c] * wz[c * NH + tid];
                Bc += bz[c] * wz[c * NH + tid];
            }
            g_Svec[tid] = S; g_Bcvec[tid] = Bc;
        }
        return;
    }
    const float* x = a + row * CQ;
    float v0 = x[tid], v1 = x[tid + 256], v2 = x[tid + 512];
    float s = v0 + v1 + v2;
    float q = v0 * v0 + v1 * v1 + v2 * v2;
#pragma unroll
    for (int o = 16; o > 0; o >>= 1) {
        s += __shfl_xor_sync(0xffffffffu, s, o);
        q += __shfl_xor_sync(0xffffffffu, q, o);
    }
    __shared__ float sw[8], qw[8];
    __shared__ float smu, srv;
    if ((tid & 31) == 0) { sw[tid >> 5] = s; qw[tid >> 5] = q; }
    __syncthreads();
    if (tid == 0) {
        float S = 0.f, Q = 0.f;
#pragma unroll
        for (int w = 0; w < 8; w++) { S += sw[w]; Q += qw[w]; }
        float mu = S * (1.f / (float)CQ);
        float var = Q * (1.f / (float)CQ) - mu * mu;
        smu = mu;
        srv = rsqrtf(fmaxf(var, 0.f) + EPSV);
    }
    __syncthreads();
    float mu = smu, r = srv;
    float* o = g_an + row * CQ;
    o[tid]       = (v0 - mu) * r * ga[tid]       + ba[tid];
    o[tid + 256] = (v1 - mu) * r * ga[tid + 256] + ba[tid + 256];
    o[tid + 512] = (v2 - mu) * r * ga[tid + 512] + ba[tid + 512];
}

// ===========================================================================
// Kernel 2: fused QKVG projections via tf32 mma. BM=64, BN=128, BK=32. (R7)
// ===========================================================================
__global__ __launch_bounds__(128) void proj_kernel(const float* __restrict__ Wq,
                                                   const float* __restrict__ Wk,
                                                   const float* __restrict__ Wv,
                                                   const float* __restrict__ Wg,
                                                   const float* __restrict__ bg)
{
    int n0 = blockIdx.x * 128;
    int sel  = n0 / HD;
    int ncol = n0 - sel * HD;
    const float* W = (sel == 0) ? Wq : (sel == 1) ? Wk : (sel == 2) ? Wv : Wg;
    float*       O = (sel == 0) ? g_q : (sel == 1) ? g_k : (sel == 2) ? g_v : g_g;
    int m0 = blockIdx.y * 64;

    __shared__ __align__(16) uint32_t As[64 * 36];
    __shared__ __align__(16) uint32_t Bs[32 * 136];

    int tid  = threadIdx.x;
    int lane = tid & 31;
    int warp = tid >> 5;
    int wm = warp >> 1, wn = warp & 1;
    int mw0 = wm * 32, nw0 = wn * 64;
    int lr = lane >> 2, lc = lane & 3;

    float acc[2][8][4];
#pragma unroll
    for (int mt = 0; mt < 2; mt++)
#pragma unroll
        for (int nt = 0; nt < 8; nt++)
#pragma unroll
            for (int u = 0; u < 4; u++) acc[mt][nt][u] = 0.f;

    for (int k0 = 0; k0 < CQ; k0 += 32) {
#pragma unroll
        for (int it = 0; it < 4; it++) {
            int t = tid + it * 128;
            int r = t >> 3, c4 = t & 7;
            float4 v = *(const float4*)&g_an[(m0 + r) * CQ + k0 + c4 * 4];
            uint32_t* d = &As[r * 36 + c4 * 4];
            d[0] = f2tf32(v.x); d[1] = f2tf32(v.y);
            d[2] = f2tf32(v.z); d[3] = f2tf32(v.w);
        }
#pragma unroll
        for (int it = 0; it < 8; it++) {
            int t = tid + it * 128;
            int r = t >> 5, c4 = t & 31;
            float4 v = *(const float4*)&W[(k0 + r) * HD + ncol + c4 * 4];
            uint32_t* d = &Bs[r * 136 + c4 * 4];
            d[0] = f2tf32(v.x); d[1] = f2tf32(v.y);
            d[2] = f2tf32(v.z); d[3] = f2tf32(v.w);
        }
        __syncthreads();
#pragma unroll
        for (int ks = 0; ks < 4; ks++) {
            int kk = ks * 8;
            uint32_t a[2][4];
#pragma unroll
            for (int mt = 0; mt < 2; mt++) {
                int ar = mw0 + mt * 16 + lr;
                int ac = kk + lc;
                a[mt][0] = As[ar * 36 + ac];
                a[mt][1] = As[(ar + 8) * 36 + ac];
                a[mt][2] = As[ar * 36 + ac + 4];
                a[mt][3] = As[(ar + 8) * 36 + ac + 4];
            }
#pragma unroll
            for (int nt = 0; nt < 8; nt++) {
                uint32_t b[2];
                int bk = kk + lc;
                int bn = nw0 + nt * 8 + lr;
                b[0] = Bs[bk * 136 + bn];
                b[1] = Bs[(bk + 4) * 136 + bn];
                mma_tf32(acc[0][nt], a[0], b);
                mma_tf32(acc[1][nt], a[1], b);
            }
        }
        __syncthreads();
    }

    const float scaleq = 0.14433756729740643f;
#pragma unroll
    for (int mt = 0; mt < 2; mt++) {
#pragma unroll
        for (int nt = 0; nt < 8; nt++) {
            int cc = ncol + nw0 + nt * 8 + 2 * lc;
#pragma unroll
            for (int half = 0; half < 2; half++) {
                int r = m0 + mw0 + mt * 16 + lr + half * 8;
                float v0 = acc[mt][nt][half * 2 + 0];
                float v1 = acc[mt][nt][half * 2 + 1];
                if (sel == 0) { v0 *= scaleq; v1 *= scaleq; }
                else if (sel == 3) {
                    v0 = 1.f / (1.f + __expf(-(v0 + bg[cc])));
                    v1 = 1.f / (1.f + __expf(-(v1 + bg[cc + 1])));
                }
                float2 o2; o2.x = v0; o2.y = v1;
                *(float2*)&O[r * HD + cc] = o2;
            }
        }
    }
}

// ===========================================================================
// Kernel 3: pair bias via tf32 mma + fused LN.  (R10, unchanged)
// ===========================================================================
__global__ __launch_bounds__(128) void pairbias_kernel(const float* __restrict__ z)
{
    __shared__ __align__(16) float    ztf[64 * 132];
    __shared__ __align__(16) uint32_t wgt[NH * 144];
    __shared__ float Ssh[NH], Bcsh[NH], mus[64], rvs[64];

    int tid  = threadIdx.x;
    int lane = tid & 31;
    int warp = tid >> 5;
    int i  = blockIdx.y;
    int j0 = blockIdx.x * 64;

    {
        const uint4* src = (const uint4*)g_wgt;
        for (int t2 = tid; t2 < 576; t2 += 128)
            cp_async16(smem_u32((uint4*)wgt + t2), src + t2);
    }
    const float4* zb = (const float4*)(z + ((size_t)i * NTOK + j0) * CZ);
#pragma unroll
    for (int u = 0; u < 16; u++) {
        int idx = tid + 128 * u;
        int r = idx >> 5;
        cp_async16(smem_u32(&ztf[r * 132 + lane * 4]), zb + idx);
    }
    if (tid < NH) { Ssh[tid] = g_Svec[tid]; Bcsh[tid] = g_Bcvec[tid]; }
    cp_async_wait_all();
    __syncthreads();

    if (tid < 64) {
        float s = 0.f, sq = 0.f;
        const float* zr = &ztf[tid * 132];
#pragma unroll
        for (int cq = 0; cq < 32; cq++) {
            float4 w = *(const float4*)&zr[cq * 4];
            s += w.x + w.y + w.z + w.w;
            sq = fmaf(w.x, w.x, sq); sq = fmaf(w.y, w.y, sq);
            sq = fmaf(w.z, w.z, sq); sq = fmaf(w.w, w.w, sq);
        }
        float mu  = s * (1.f / (float)CZ);
        float var = sq * (1.f / (float)CZ) - mu * mu;
        mus[tid] = mu;
        rvs[tid] = rsqrtf(fmaxf(var, 0.f) + EPSV);
    }

    int m0 = warp * 16;
    int lr = lane >> 2, lc = lane & 3;
    float acc[2][4];
#pragma unroll
    for (int n = 0; n < 2; n++)
#pragma unroll
        for (int u = 0; u < 4; u++) acc[n][u] = 0.f;

    const uint32_t* wgt0 = &wgt[lr * 144 + lc * 36];
    const uint32_t* wgt1 = &wgt[(8 + lr) * 144 + lc * 36];
#pragma unroll
    for (int g = 0; g < 8; g++) {
        uint4 bq0 = *(const uint4*)(wgt0 + g * 4);
        uint4 bq1 = *(const uint4*)(wgt1 + g * 4);
#pragma unroll
        for (int kh = 0; kh < 2; kh++) {
            int kk = (g * 2 + kh) * 8;
            int ar = m0 + lr, ac = kk + lc;
            uint32_t a[4];
            a[0] = f2tf32(ztf[ar * 132 + ac]);
            a[1] = f2tf32(ztf[(ar + 8) * 132 + ac]);
            a[2] = f2tf32(ztf[ar * 132 + ac + 4]);
            a[3] = f2tf32(ztf[(ar + 8) * 132 + ac + 4]);
            uint32_t b0[2], b1[2];
            b0[0] = kh ? bq0.z : bq0.x;  b0[1] = kh ? bq0.w : bq0.y;
            b1[0] = kh ? bq1.z : bq1.x;  b1[1] = kh ? bq1.w : bq1.y;
            mma_tf32(acc[0], a, b0);
            mma_tf32(acc[1], a, b1);
        }
    }
    __syncthreads();

    float* outs = ztf;
#pragma unroll
    for (int n = 0; n < 2; n++) {
        int h0 = n * 8 + 2 * lc;
#pragma unroll
        for (int half = 0; half < 2; half++) {
            int r = m0 + lr + half * 8;
            float mu = mus[r], rv = rvs[r];
            outs[h0 * 68 + r]       = rv * (acc[n][half * 2 + 0] - mu * Ssh[h0])     + Bcsh[h0];
            outs[(h0 + 1) * 68 + r] = rv * (acc[n][half * 2 + 1] - mu * Ssh[h0 + 1]) + Bcsh[h0 + 1];
        }
    }
    __syncthreads();
#pragma unroll
    for (int it = 0; it < 2; it++) {
        int idx = tid + 128 * it;
        int h = idx >> 4, j4 = (idx & 15) * 4;
        float4 o4;
        o4.x = outs[h * 68 + j4 + 0];
        o4.y = outs[h * 68 + j4 + 1];
        o4.z = outs[h * 68 + j4 + 2];
        o4.w = outs[h * 68 + j4 + 3];
        *(float4*)&g_bias[((size_t)h * NTOK + i) * NTOK + j0 + j4] = o4;
    }
}

// ===========================================================================
// Kernel 4: flash attention. QK^T tf32 mma; PV fp16 m16n8k16 with P converted
// IN REGISTERS (accumulator layout == fp16 A-fragment layout). No P smem,
// 2 barriers per KV tile, smem 45->34 KB. Split-KV x4, partials out.
// ===========================================================================
__global__ __launch_bounds__(128) void attn_kernel(const float* __restrict__ mask)
{
    int h     = blockIdx.y;
    int qb    = blockIdx.x * 64;
    int split = blockIdx.z;
    int tid  = threadIdx.x;
    int lane = tid & 31;
    int warp = tid >> 5;
    int lr = lane >> 2, lc = lane & 3;
    int m0 = warp * 16;

    __shared__ __align__(16) uint32_t qs[64 * 52];   // tf32 Q [q][d]
    __shared__ __align__(16) uint32_t ks[48 * 72];   // tf32 K^T [d][j]
    __shared__ __align__(16) uint32_t vsh[48 * 36];  // half2 V^T [d][j/2]

    for (int t = tid; t < 768; t += 128) {
        int r = t / 12, c4 = (t % 12) * 4;
        float4 v = *(const float4*)&g_q[(qb + r) * HD + h * DH + c4];
        uint32_t* d = &qs[r * 52 + c4];
        d[0] = f2tf32(v.x); d[1] = f2tf32(v.y);
        d[2] = f2tf32(v.z); d[3] = f2tf32(v.w);
    }

    float mrow0 = -1e30f, mrow1 = -1e30f, lrow0 = 0.f, lrow1 = 0.f;
    float oacc[6][4];
#pragma unroll
    for (int vt = 0; vt < 6; vt++)
#pragma unroll
        for (int u = 0; u < 4; u++) oacc[vt][u] = 0.f;

    float mq0 = mask[qb + m0 + lr];
    float mq1 = mask[qb + m0 + lr + 8];

    for (int jt = split * 4; jt < split * 4 + 4; jt++) {
        int j0 = jt * 64;
        __syncthreads();                     // prev-tile ks/vsh reads done
        // stage K^T (tf32) [d][j], stride 72
        for (int t = tid; t < 768; t += 128) {
            int j = t & 63, dq = t >> 6;
            float4 v = *(const float4*)&g_k[(j0 + j) * HD + h * DH + dq * 4];
            ks[(dq * 4 + 0) * 72 + j] = f2tf32(v.x);
            ks[(dq * 4 + 1) * 72 + j] = f2tf32(v.y);
            ks[(dq * 4 + 2) * 72 + j] = f2tf32(v.z);
            ks[(dq * 4 + 3) * 72 + j] = f2tf32(v.w);
        }
        // stage V^T (half2 j-pairs) [d][jp], stride 36 words
        for (int u = tid; u < 384; u += 128) {
            int jp = u & 31, db = u >> 5;
            const float* vA = &g_v[(j0 + 2 * jp)     * HD + h * DH + db * 4];
            const float* vB = &g_v[(j0 + 2 * jp + 1) * HD + h * DH + db * 4];
            float4 a4 = *(const float4*)vA;
            float4 b4 = *(const float4*)vB;
            vsh[(db * 4 + 0) * 36 + jp] = packh2(a4.x, b4.x);
            vsh[(db * 4 + 1) * 36 + jp] = packh2(a4.y, b4.y);
            vsh[(db * 4 + 2) * 36 + jp] = packh2(a4.z, b4.z);
            vsh[(db * 4 + 3) * 36 + jp] = packh2(a4.w, b4.w);
        }
        __syncthreads();

        // scores S[16 x 64] per warp (tf32)
        float sacc[8][4];
#pragma unroll
        for (int nt = 0; nt < 8; nt++)
#pragma unroll
            for (int u = 0; u < 4; u++) sacc[nt][u] = 0.f;
#pragma unroll
        for (int k = 0; k < 6; k++) {
            int kk = k * 8;
            uint32_t a[4];
            int ar = m0 + lr, ac = kk + lc;
            a[0] = qs[ar * 52 + ac];
            a[1] = qs[(ar + 8) * 52 + ac];
            a[2] = qs[ar * 52 + ac + 4];
            a[3] = qs[(ar + 8) * 52 + ac + 4];
#pragma unroll
            for (int nt = 0; nt < 8; nt++) {
                uint32_t b[2];
                b[0] = ks[(kk + lc) * 72 + nt * 8 + lr];
                b[1] = ks[(kk + lc + 4) * 72 + nt * 8 + lr];
                mma_tf32(sacc[nt], a, b);
            }
        }

        // bias + mask, running row max
        float rmax0 = -1e30f, rmax1 = -1e30f;
#pragma unroll
        for (int nt = 0; nt < 8; nt++) {
            int jc = j0 + nt * 8 + 2 * lc;
            float2 b0 = *(const float2*)&g_bias[((size_t)h * NTOK + qb + m0 + lr) * NTOK + jc];
            float2 b1 = *(const float2*)&g_bias[((size_t)h * NTOK + qb + m0 + lr + 8) * NTOK + jc];
            float mk0 = mask[jc], mk1 = mask[jc + 1];
            sacc[nt][0] += b0.x + INFV * (mq0 * mk0 - 1.f);
            sacc[nt][1] += b0.y + INFV * (mq0 * mk1 - 1.f);
            sacc[nt][2] += b1.x + INFV * (mq1 * mk0 - 1.f);
            sacc[nt][3] += b1.y + INFV * (mq1 * mk1 - 1.f);
            rmax0 = fmaxf(rmax0, fmaxf(sacc[nt][0], sacc[nt][1]));
            rmax1 = fmaxf(rmax1, fmaxf(sacc[nt][2], sacc[nt][3]));
        }
#pragma unroll
        for (int off = 1; off < 4; off <<= 1) {
            rmax0 = fmaxf(rmax0, __shfl_xor_sync(0xffffffffu, rmax0, off));
            rmax1 = fmaxf(rmax1, __shfl_xor_sync(0xffffffffu, rmax1, off));
        }
        float mnew0 = fmaxf(mrow0, rmax0);
        float mnew1 = fmaxf(mrow1, rmax1);
        float scale0 = __expf(mrow0 - mnew0);
        float scale1 = __expf(mrow1 - mnew1);

        // exp, row sums, and pack P to fp16 A-fragments in registers
        float sum0 = 0.f, sum1 = 0.f;
        uint32_t ph[8][2];
#pragma unroll
        for (int nt = 0; nt < 8; nt++) {
            sacc[nt][0] = __expf(sacc[nt][0] - mnew0);
            sacc[nt][1] = __expf(sacc[nt][1] - mnew0);
            sacc[nt][2] = __expf(sacc[nt][2] - mnew1);
            sacc[nt][3] = __expf(sacc[nt][3] - mnew1);
            sum0 += sacc[nt][0] + sacc[nt][1];
            sum1 += sacc[nt][2] + sacc[nt][3];
            ph[nt][0] = packh2(sacc[nt][0], sacc[nt][1]);   // rows lr
            ph[nt][1] = packh2(sacc[nt][2], sacc[nt][3]);   // rows lr+8
        }
#pragma unroll
        for (int off = 1; off < 4; off <<= 1) {
            sum0 += __shfl_xor_sync(0xffffffffu, sum0, off);
            sum1 += __shfl_xor_sync(0xffffffffu, sum1, off);
        }
        lrow0 = lrow0 * scale0 + sum0;  mrow0 = mnew0;
        lrow1 = lrow1 * scale1 + sum1;  mrow1 = mnew1;
#pragma unroll
        for (int vt = 0; vt < 6; vt++) {
            oacc[vt][0] *= scale0; oacc[vt][1] *= scale0;
            oacc[vt][2] *= scale1; oacc[vt][3] *= scale1;
        }

        // O += P @ V : fp16 m16n8k16, A from registers, B from vsh
#pragma unroll
        for (int ks4 = 0; ks4 < 4; ks4++) {
            uint32_t a[4];
            a[0] = ph[ks4 * 2][0];
            a[1] = ph[ks4 * 2][1];
            a[2] = ph[ks4 * 2 + 1][0];
            a[3] = ph[ks4 * 2 + 1][1];
#pragma unroll
            for (int vt = 0; vt < 6; vt++) {
                int d = vt * 8 + lr;
                uint32_t b[2];
                b[0] = vsh[d * 36 + ks4 * 8 + lc];
                b[1] = vsh[d * 36 + ks4 * 8 + 4 + lc];
                mma_f16(oacc[vt], a, b);
            }
        }
    }

    int q0 = qb + m0 + lr, q1 = q0 + 8;
    int pb0 = ((split * NH + h) * NTOK + q0) * DH;
    int pb1 = ((split * NH + h) * NTOK + q1) * DH;
#pragma unroll
    for (int vt = 0; vt < 6; vt++) {
        int d = vt * 8 + 2 * lc;
        *(float2*)&g_po[pb0 + d] = make_float2(oacc[vt][0], oacc[vt][1]);
        *(float2*)&g_po[pb1 + d] = make_float2(oacc[vt][2], oacc[vt][3]);
    }
    if (lc == 0) {
        g_pm[(split * NH + h) * NTOK + q0] = mrow0;
        g_pl[(split * NH + h) * NTOK + q0] = lrow0;
        g_pm[(split * NH + h) * NTOK + q1] = mrow1;
        g_pl[(split * NH + h) * NTOK + q1] = lrow1;
    }
}

// ===========================================================================
// Kernel 4b: merge 4 splits, normalize, apply gate -> g_og.  (R7)
// ===========================================================================
__global__ __launch_bounds__(256) void merge_kernel()
{
    int q = blockIdx.x;
    int t = threadIdx.x;
    int h = t >> 4;
    int d0 = (t & 15) * 3;

    float m[NSPLIT], l[NSPLIT];
    float M = -1e30f;
#pragma unroll
    for (int s = 0; s < NSPLIT; s++) {
        m[s] = g_pm[(s * NH + h) * NTOK + q];
        l[s] = g_pl[(s * NH + h) * NTOK + q];
        M = fmaxf(M, m[s]);
    }
    float w[NSPLIT], ltot = 0.f;
#pragma unroll
    for (int s = 0; s < NSPLIT; s++) {
        w[s] = __expf(m[s] - M);
        ltot += l[s] * w[s];
    }
    float inv = 1.f / ltot;
    int go = q * HD + h * DH + d0;
#pragma unroll
    for (int u = 0; u < 3; u++) {
        float val = 0.f;
#pragma unroll
        for (int s = 0; s < NSPLIT; s++)
            val += g_po[((s * NH + h) * NTOK + q) * DH + d0 + u] * w[s];
        g_og[go + u] = val * inv * g_g[go + u];
    }
}

// ===========================================================================
// Kernel 5: output projection via tf32 mma. BM=64, BN=64, BK=32. (R7)
// ===========================================================================
__global__ __launch_bounds__(128) void outproj_kernel(const float* __restrict__ W,
                                                      const float* __restrict__ bo,
                                                      float* __restrict__ out)
{
    int n0 = blockIdx.x * 64;
    int m0 = blockIdx.y * 64;

    __shared__ __align__(16) uint32_t As[64 * 36];
    __shared__ __align__(16) uint32_t Bs[32 * 72];

    int tid  = threadIdx.x;
    int lane = tid & 31;
    int warp = tid >> 5;
    int wm = warp >> 1, wn = warp & 1;
    int mw0 = wm * 32, nw0 = wn * 32;
    int lr = lane >> 2, lc = lane & 3;

    float acc[2][4][4];
#pragma unroll
    for (int mt = 0; mt < 2; mt++)
#pragma unroll
        for (int nt = 0; nt < 4; nt++)
#pragma unroll
            for (int u = 0; u < 4; u++) acc[mt][nt][u] = 0.f;

    for (int k0 = 0; k0 < HD; k0 += 32) {
#pragma unroll
        for (int it = 0; it < 4; it++) {
            int t = tid + it * 128;
            int r = t >> 3, c4 = t & 7;
            float4 v = *(const float4*)&g_og[(m0 + r) * HD + k0 + c4 * 4];
            uint32_t* d = &As[r * 36 + c4 * 4];
            d[0] = f2tf32(v.x); d[1] = f2tf32(v.y);
            d[2] = f2tf32(v.z); d[3] = f2tf32(v.w);
        }
#pragma unroll
        for (int it = 0; it < 4; it++) {
            int t = tid + it * 128;
            int r = t >> 4, c4 = t & 15;
            float4 v = *(const float4*)&W[(k0 + r) * CQ + n0 + c4 * 4];
            uint32_t* d = &Bs[r * 72 + c4 * 4];
            d[0] = f2tf32(v.x); d[1] = f2tf32(v.y);
            d[2] = f2tf32(v.z); d[3] = f2tf32(v.w);
        }
        __syncthreads();
#pragma unroll
        for (int ks = 0; ks < 4; ks++) {
            int kk = ks * 8;
            uint32_t a[2][4];
#pragma unroll
            for (int mt = 0; mt < 2; mt++) {
                int ar = mw0 + mt * 16 + lr;
                int ac = kk + lc;
                a[mt][0] = As[ar * 36 + ac];
                a[mt][1] = As[(ar + 8) * 36 + ac];
                a[mt][2] = As[ar * 36 + ac + 4];
                a[mt][3] = As[(ar + 8) * 36 + ac + 4];
            }
#pragma unroll
            for (int nt = 0; nt < 4; nt++) {
                uint32_t b[2];
                int bk = kk + lc;
                int bn = nw0 + nt * 8 + lr;
                b[0] = Bs[bk * 72 + bn];
                b[1] = Bs[(bk + 4) * 72 + bn];
                mma_tf32(acc[0][nt], a[0], b);
                mma_tf32(acc[1][nt], a[1], b);
            }
        }
        __syncthreads();
    }

#pragma unroll
    for (int mt = 0; mt < 2; mt++) {
#pragma unroll
        for (int nt = 0; nt < 4; nt++) {
            int cc = n0 + nw0 + nt * 8 + 2 * lc;
            float b0 = bo[cc], b1 = bo[cc + 1];
#pragma unroll
            for (int half = 0; half < 2; half++) {
                int r = m0 + mw0 + mt * 16 + lr + half * 8;
                float2 o2;
                o2.x = acc[mt][nt][half * 2 + 0] + b0;
                o2.y = acc[mt][nt][half * 2 + 1] + b1;
                *(float2*)&out[r * CQ + cc] = o2;
            }
        }
    }
}

// ===========================================================================
extern "C" void kernel_launch(void* const* d_in, const int* in_sizes, int n_in,
                              void* d_out, int out_size)
{
    const float* a    = (const float*)d_in[0];
    const float* z    = (const float*)d_in[1];
    const float* mask = (const float*)d_in[2];
    const float* g_a  = (const float*)d_in[3];
    const float* b_a  = (const float*)d_in[4];
    const float* g_z  = (const float*)d_in[5];
    const float* b_z  = (const float*)d_in[6];
    const float* w_z  = (const float*)d_in[7];
    const float* w_q  = (const float*)d_in[8];
    const float* w_k  = (const float*)d_in[9];
    const float* w_v  = (const float*)d_in[10];
    const float* w_g  = (const float*)d_in[11];
    const float* b_g  = (const float*)d_in[12];
    const float* w_o  = (const float*)d_in[13];
    const float* b_o  = (const float*)d_in[14];
    float* out = (float*)d_out;

    ln_a_kernel<<<NTOK + 1, 256>>>(a, g_a, b_a, g_z, b_z, w_z);
    proj_kernel<<<dim3(24, 16), 128>>>(w_q, w_k, w_v, w_g, b_g);
    pairbias_kernel<<<dim3(16, NTOK), 128>>>(z);
    attn_kernel<<<dim3(16, NH, NSPLIT), 128>>>(mask);
    merge_kernel<<<NTOK, 256>>>();
    outproj_kernel<<<dim3(12, 16), 128>>>(w_o, b_o, out);
}

// round 13
// speedup vs baseline: 3.4214x; 1.1342x over previous
#include <cuda_runtime.h>
#include <cuda_fp16.h>
#include <math.h>
#include <stdint.h>

#define NTOK 1024
#define CQ   768
#define CZ   128
#define NH   16
#define DH   48
#define HD   768
#define EPSV 1e-5f
#define INFV 1.0e9f
#define NSPLIT 4

// ------------- static device scratch (no allocations allowed) -------------
__device__ float g_an[NTOK * CQ];
__device__ float g_q [NTOK * HD];
__device__ __align__(16) uint32_t g_kT[HD * NTOK];  // tf32 K^T [h*DH+d][tok]
__device__ __align__(16) __half   g_vh[HD * NTOK];  // fp16 V^T [h*DH+d][tok]
__device__ float g_g [NTOK * HD];
__device__ float g_og[NTOK * HD];
__device__ __align__(16) __half g_biash[(size_t)NH * NTOK * NTOK];  // 32 MB
__device__ float g_po[NSPLIT * NH * NTOK * DH];
__device__ float g_pm[NSPLIT * NH * NTOK];
__device__ float g_pl[NSPLIT * NH * NTOK];
__device__ __align__(16) uint32_t g_wgt[NH * 144];  // tf32 wg, fragment-quad
__device__ float g_Svec[NH], g_Bcvec[NH];

// ------------------------- mma helpers -------------------------------
__device__ __forceinline__ uint32_t f2tf32(float f) {
    uint32_t r;
    asm("cvt.rna.tf32.f32 %0, %1;" : "=r"(r) : "f"(f));
    return r;
}
__device__ __forceinline__ void mma_tf32(float* d, const uint32_t* a, const uint32_t* b) {
    asm("mma.sync.aligned.m16n8k8.row.col.f32.tf32.tf32.f32 "
        "{%0,%1,%2,%3}, {%4,%5,%6,%7}, {%8,%9}, {%0,%1,%2,%3};"
        : "+f"(d[0]), "+f"(d[1]), "+f"(d[2]), "+f"(d[3])
        : "r"(a[0]), "r"(a[1]), "r"(a[2]), "r"(a[3]), "r"(b[0]), "r"(b[1]));
}
__device__ __forceinline__ void mma_f16(float* d, const uint32_t* a, const uint32_t* b) {
    asm("mma.sync.aligned.m16n8k16.row.col.f32.f16.f16.f32 "
        "{%0,%1,%2,%3}, {%4,%5,%6,%7}, {%8,%9}, {%0,%1,%2,%3};"
        : "+f"(d[0]), "+f"(d[1]), "+f"(d[2]), "+f"(d[3])
        : "r"(a[0]), "r"(a[1]), "r"(a[2]), "r"(a[3]), "r"(b[0]), "r"(b[1]));
}
__device__ __forceinline__ uint32_t packh2(float lo, float hi) {
    __half2 h = __floats2half2_rn(lo, hi);
    return *(uint32_t*)&h;
}
__device__ __forceinline__ uint32_t smem_u32(const void* p) {
    uint32_t r;
    asm("{.reg .u64 t; cvta.to.shared.u64 t, %1; cvt.u32.u64 %0, t;}" : "=r"(r) : "l"(p));
    return r;
}
__device__ __forceinline__ void cp_async16(uint32_t dst, const void* src) {
    asm volatile("cp.async.cg.shared.global [%0], [%1], 16;" :: "r"(dst), "l"(src));
}
__device__ __forceinline__ void cp_async_wait_all() {
    asm volatile("cp.async.commit_group;\n cp.async.wait_group 0;" ::: "memory");
}

// ===========================================================================
// Kernel 1: LayerNorm(a) -> g_an (blocks 0..1023); block 1024 = pb setup.
// ===========================================================================
__global__ __launch_bounds__(256) void ln_a_kernel(const float* __restrict__ a,
                                                   const float* __restrict__ ga,
                                                   const float* __restrict__ ba,
                                                   const float* __restrict__ gz,
                                                   const float* __restrict__ bz,
                                                   const float* __restrict__ wz)
{
    int row = blockIdx.x;
    int tid = threadIdx.x;
    if (row == NTOK) {
        for (int i = tid; i < NH * 144; i += 256) g_wgt[i] = 0u;
        __syncthreads();
        for (int i = tid; i < NH * CZ; i += 256) {
            int h = i >> 7, c = i & 127;
            int g = c >> 4, rem = c & 15;
            int lc = rem & 3, w = rem >> 2;
            g_wgt[h * 144 + lc * 36 + g * 4 + w] = f2tf32(gz[c] * wz[c * NH + h]);
        }
        if (tid < NH) {
            float S = 0.f, Bc = 0.f;
            for (int c = 0; c < CZ; c++) {
                S  += gz[c] * wz[c * NH + tid];
                Bc += bz[c] * wz[c * NH + tid];
            }
            g_Svec[tid] = S; g_Bcvec[tid] = Bc;
        }
        return;
    }
    const float* x = a + row * CQ;
    float v0 = x[tid], v1 = x[tid + 256], v2 = x[tid + 512];
    float s = v0 + v1 + v2;
    float q = v0 * v0 + v1 * v1 + v2 * v2;
#pragma unroll
    for (int o = 16; o > 0; o >>= 1) {
        s += __shfl_xor_sync(0xffffffffu, s, o);
        q += __shfl_xor_sync(0xffffffffu, q, o);
    }
    __shared__ float sw[8], qw[8];
    __shared__ float smu, srv;
    if ((tid & 31) == 0) { sw[tid >> 5] = s; qw[tid >> 5] = q; }
    __syncthreads();
    if (tid == 0) {
        float S = 0.f, Q = 0.f;
#pragma unroll
        for (int w = 0; w < 8; w++) { S += sw[w]; Q += qw[w]; }
        float mu = S * (1.f / (float)CQ);
        float var = Q * (1.f / (float)CQ) - mu * mu;
        smu = mu;
        srv = rsqrtf(fmaxf(var, 0.f) + EPSV);
    }
    __syncthreads();
    float mu = smu, r = srv;
    float* o = g_an + row * CQ;
    o[tid]       = (v0 - mu) * r * ga[tid]       + ba[tid];
    o[tid + 256] = (v1 - mu) * r * ga[tid + 256] + ba[tid + 256];
    o[tid + 512] = (v2 - mu) * r * ga[tid + 512] + ba[tid + 512];
}

// ===========================================================================
// Kernel 2: fused QKVG projections via tf32 mma. BM=64, BN=128, BK=32.
// K written pre-transposed as tf32 (g_kT), V pre-transposed as fp16 (g_vh).
// ===========================================================================
__global__ __launch_bounds__(128) void proj_kernel(const float* __restrict__ Wq,
                                                   const float* __restrict__ Wk,
                                                   const float* __restrict__ Wv,
                                                   const float* __restrict__ Wg,
                                                   const float* __restrict__ bg)
{
    int n0 = blockIdx.x * 128;
    int sel  = n0 / HD;
    int ncol = n0 - sel * HD;
    const float* W = (sel == 0) ? Wq : (sel == 1) ? Wk : (sel == 2) ? Wv : Wg;
    int m0 = blockIdx.y * 64;

    __shared__ __align__(16) uint32_t As[64 * 36];
    __shared__ __align__(16) uint32_t Bs[32 * 136];

    int tid  = threadIdx.x;
    int lane = tid & 31;
    int warp = tid >> 5;
    int wm = warp >> 1, wn = warp & 1;
    int mw0 = wm * 32, nw0 = wn * 64;
    int lr = lane >> 2, lc = lane & 3;

    float acc[2][8][4];
#pragma unroll
    for (int mt = 0; mt < 2; mt++)
#pragma unroll
        for (int nt = 0; nt < 8; nt++)
#pragma unroll
            for (int u = 0; u < 4; u++) acc[mt][nt][u] = 0.f;

    for (int k0 = 0; k0 < CQ; k0 += 32) {
#pragma unroll
        for (int it = 0; it < 4; it++) {
            int t = tid + it * 128;
            int r = t >> 3, c4 = t & 7;
            float4 v = *(const float4*)&g_an[(m0 + r) * CQ + k0 + c4 * 4];
            uint32_t* d = &As[r * 36 + c4 * 4];
            d[0] = f2tf32(v.x); d[1] = f2tf32(v.y);
            d[2] = f2tf32(v.z); d[3] = f2tf32(v.w);
        }
#pragma unroll
        for (int it = 0; it < 8; it++) {
            int t = tid + it * 128;
            int r = t >> 5, c4 = t & 31;
            float4 v = *(const float4*)&W[(k0 + r) * HD + ncol + c4 * 4];
            uint32_t* d = &Bs[r * 136 + c4 * 4];
            d[0] = f2tf32(v.x); d[1] = f2tf32(v.y);
            d[2] = f2tf32(v.z); d[3] = f2tf32(v.w);
        }
        __syncthreads();
#pragma unroll
        for (int ks = 0; ks < 4; ks++) {
            int kk = ks * 8;
            uint32_t a[2][4];
#pragma unroll
            for (int mt = 0; mt < 2; mt++) {
                int ar = mw0 + mt * 16 + lr;
                int ac = kk + lc;
                a[mt][0] = As[ar * 36 + ac];
                a[mt][1] = As[(ar + 8) * 36 + ac];
                a[mt][2] = As[ar * 36 + ac + 4];
                a[mt][3] = As[(ar + 8) * 36 + ac + 4];
            }
#pragma unroll
            for (int nt = 0; nt < 8; nt++) {
                uint32_t b[2];
                int bk = kk + lc;
                int bn = nw0 + nt * 8 + lr;
                b[0] = Bs[bk * 136 + bn];
                b[1] = Bs[(bk + 4) * 136 + bn];
                mma_tf32(acc[0][nt], a[0], b);
                mma_tf32(acc[1][nt], a[1], b);
            }
        }
        __syncthreads();
    }

    const float scaleq = 0.14433756729740643f;
#pragma unroll
    for (int mt = 0; mt < 2; mt++) {
#pragma unroll
        for (int nt = 0; nt < 8; nt++) {
            int cc = ncol + nw0 + nt * 8 + 2 * lc;
#pragma unroll
            for (int half = 0; half < 2; half++) {
                int r = m0 + mw0 + mt * 16 + lr + half * 8;
                float v0 = acc[mt][nt][half * 2 + 0];
                float v1 = acc[mt][nt][half * 2 + 1];
                if (sel == 0) {
                    float2 o2; o2.x = v0 * scaleq; o2.y = v1 * scaleq;
                    *(float2*)&g_q[r * HD + cc] = o2;
                } else if (sel == 1) {          // K^T tf32
                    g_kT[cc * NTOK + r]       = f2tf32(v0);
                    g_kT[(cc + 1) * NTOK + r] = f2tf32(v1);
                } else if (sel == 2) {          // V^T fp16
                    g_vh[cc * NTOK + r]       = __float2half_rn(v0);
                    g_vh[(cc + 1) * NTOK + r] = __float2half_rn(v1);
                } else {
                    float2 o2;
                    o2.x = 1.f / (1.f + __expf(-(v0 + bg[cc])));
                    o2.y = 1.f / (1.f + __expf(-(v1 + bg[cc + 1])));
                    *(float2*)&g_g[r * HD + cc] = o2;
                }
            }
        }
    }
}

// ===========================================================================
// Kernel 3: pair bias via tf32 mma + fused LN; bias written as fp16.
// ===========================================================================
__global__ __launch_bounds__(128) void pairbias_kernel(const float* __restrict__ z)
{
    __shared__ __align__(16) float    ztf[64 * 132];
    __shared__ __align__(16) uint32_t wgt[NH * 144];
    __shared__ float Ssh[NH], Bcsh[NH], mus[64], rvs[64];

    int tid  = threadIdx.x;
    int lane = tid & 31;
    int warp = tid >> 5;
    int i  = blockIdx.y;
    int j0 = blockIdx.x * 64;

    {
        const uint4* src = (const uint4*)g_wgt;
        for (int t2 = tid; t2 < 576; t2 += 128)
            cp_async16(smem_u32((uint4*)wgt + t2), src + t2);
    }
    const float4* zb = (const float4*)(z + ((size_t)i * NTOK + j0) * CZ);
#pragma unroll
    for (int u = 0; u < 16; u++) {
        int idx = tid + 128 * u;
        int r = idx >> 5;
        cp_async16(smem_u32(&ztf[r * 132 + lane * 4]), zb + idx);
    }
    if (tid < NH) { Ssh[tid] = g_Svec[tid]; Bcsh[tid] = g_Bcvec[tid]; }
    cp_async_wait_all();
    __syncthreads();

    if (tid < 64) {
        float s = 0.f, sq = 0.f;
        const float* zr = &ztf[tid * 132];
#pragma unroll
        for (int cq = 0; cq < 32; cq++) {
            float4 w = *(const float4*)&zr[cq * 4];
            s += w.x + w.y + w.z + w.w;
            sq = fmaf(w.x, w.x, sq); sq = fmaf(w.y, w.y, sq);
            sq = fmaf(w.z, w.z, sq); sq = fmaf(w.w, w.w, sq);
        }
        float mu  = s * (1.f / (float)CZ);
        float var = sq * (1.f / (float)CZ) - mu * mu;
        mus[tid] = mu;
        rvs[tid] = rsqrtf(fmaxf(var, 0.f) + EPSV);
    }

    int m0 = warp * 16;
    int lr = lane >> 2, lc = lane & 3;
    float acc[2][4];
#pragma unroll
    for (int n = 0; n < 2; n++)
#pragma unroll
        for (int u = 0; u < 4; u++) acc[n][u] = 0.f;

    const uint32_t* wgt0 = &wgt[lr * 144 + lc * 36];
    const uint32_t* wgt1 = &wgt[(8 + lr) * 144 + lc * 36];
#pragma unroll
    for (int g = 0; g < 8; g++) {
        uint4 bq0 = *(const uint4*)(wgt0 + g * 4);
        uint4 bq1 = *(const uint4*)(wgt1 + g * 4);
#pragma unroll
        for (int kh = 0; kh < 2; kh++) {
            int kk = (g * 2 + kh) * 8;
            int ar = m0 + lr, ac = kk + lc;
            uint32_t a[4];
            a[0] = f2tf32(ztf[ar * 132 + ac]);
            a[1] = f2tf32(ztf[(ar + 8) * 132 + ac]);
            a[2] = f2tf32(ztf[ar * 132 + ac + 4]);
            a[3] = f2tf32(ztf[(ar + 8) * 132 + ac + 4]);
            uint32_t b0[2], b1[2];
            b0[0] = kh ? bq0.z : bq0.x;  b0[1] = kh ? bq0.w : bq0.y;
            b1[0] = kh ? bq1.z : bq1.x;  b1[1] = kh ? bq1.w : bq1.y;
            mma_tf32(acc[0], a, b0);
            mma_tf32(acc[1], a, b1);
        }
    }
    __syncthreads();

    float* outs = ztf;                    // [h][j], stride 68
#pragma unroll
    for (int n = 0; n < 2; n++) {
        int h0 = n * 8 + 2 * lc;
#pragma unroll
        for (int half = 0; half < 2; half++) {
            int r = m0 + lr + half * 8;
            float mu = mus[r], rv = rvs[r];
            outs[h0 * 68 + r]       = rv * (acc[n][half * 2 + 0] - mu * Ssh[h0])     + Bcsh[h0];
            outs[(h0 + 1) * 68 + r] = rv * (acc[n][half * 2 + 1] - mu * Ssh[h0 + 1]) + Bcsh[h0 + 1];
        }
    }
    __syncthreads();
    // pack fp16 and write coalesced 16B chunks (one per thread)
    {
        int h = tid >> 3, j8 = (tid & 7) * 8;
        const float* src = &outs[h * 68 + j8];
        uint4 pk;
        pk.x = packh2(src[0], src[1]);
        pk.y = packh2(src[2], src[3]);
        pk.z = packh2(src[4], src[5]);
        pk.w = packh2(src[6], src[7]);
        *(uint4*)&g_biash[((size_t)h * NTOK + i) * NTOK + j0 + j8] = pk;
    }
}

// ===========================================================================
// Kernel 4: flash attention. K^T/V^T staged via raw cp.async (pre-transposed
// by proj). QK^T tf32 mma; PV fp16 with register P. Bias read as fp16.
// Split-KV x4, partials out.
// ===========================================================================
__global__ __launch_bounds__(128) void attn_kernel(const float* __restrict__ mask)
{
    int h     = blockIdx.y;
    int qb    = blockIdx.x * 64;
    int split = blockIdx.z;
    int tid  = threadIdx.x;
    int lane = tid & 31;
    int warp = tid >> 5;
    int lr = lane >> 2, lc = lane & 3;
    int m0 = warp * 16;

    __shared__ __align__(16) uint32_t qs[64 * 52];   // tf32 Q [q][d]
    __shared__ __align__(16) uint32_t ks[48 * 72];   // tf32 K^T [d][j]
    __shared__ __align__(16) uint32_t vsh[48 * 36];  // half2 V^T [d][j/2]

    for (int t = tid; t < 768; t += 128) {
        int r = t / 12, c4 = (t % 12) * 4;
        float4 v = *(const float4*)&g_q[(qb + r) * HD + h * DH + c4];
        uint32_t* d = &qs[r * 52 + c4];
        d[0] = f2tf32(v.x); d[1] = f2tf32(v.y);
        d[2] = f2tf32(v.z); d[3] = f2tf32(v.w);
    }

    float mrow0 = -1e30f, mrow1 = -1e30f, lrow0 = 0.f, lrow1 = 0.f;
    float oacc[6][4];
#pragma unroll
    for (int vt = 0; vt < 6; vt++)
#pragma unroll
        for (int u = 0; u < 4; u++) oacc[vt][u] = 0.f;

    float mq0 = mask[qb + m0 + lr];
    float mq1 = mask[qb + m0 + lr + 8];

    for (int jt = split * 4; jt < split * 4 + 4; jt++) {
        int j0 = jt * 64;
        __syncthreads();                     // prev-tile ks/vsh reads done
        // K^T: 48 rows x 64 tf32 = 768 x 16B chunks; 6 per thread
#pragma unroll
        for (int it = 0; it < 6; it++) {
            int u = tid + it * 128;
            int row = u >> 4, cx = u & 15;
            cp_async16(smem_u32(&ks[row * 72 + cx * 4]),
                       &g_kT[(size_t)(h * DH + row) * NTOK + j0 + cx * 4]);
        }
        // V^T: 48 rows x 64 fp16 = 384 x 16B chunks; 3 per thread
#pragma unroll
        for (int it = 0; it < 3; it++) {
            int u = tid + it * 128;
            int row = u >> 3, cx = u & 7;
            cp_async16(smem_u32(&vsh[row * 36 + cx * 4]),
                       &g_vh[(size_t)(h * DH + row) * NTOK + j0 + cx * 8]);
        }
        cp_async_wait_all();
        __syncthreads();

        // scores S[16 x 64] per warp (tf32)
        float sacc[8][4];
#pragma unroll
        for (int nt = 0; nt < 8; nt++)
#pragma unroll
            for (int u = 0; u < 4; u++) sacc[nt][u] = 0.f;
#pragma unroll
        for (int k = 0; k < 6; k++) {
            int kk = k * 8;
            uint32_t a[4];
            int ar = m0 + lr, ac = kk + lc;
            a[0] = qs[ar * 52 + ac];
            a[1] = qs[(ar + 8) * 52 + ac];
            a[2] = qs[ar * 52 + ac + 4];
            a[3] = qs[(ar + 8) * 52 + ac + 4];
#pragma unroll
            for (int nt = 0; nt < 8; nt++) {
                uint32_t b[2];
                b[0] = ks[(kk + lc) * 72 + nt * 8 + lr];
                b[1] = ks[(kk + lc + 4) * 72 + nt * 8 + lr];
                mma_tf32(sacc[nt], a, b);
            }
        }

        // fp16 bias + mask, running row max
        float rmax0 = -1e30f, rmax1 = -1e30f;
        const __half* bias0 = &g_biash[((size_t)h * NTOK + qb + m0 + lr) * NTOK];
        const __half* bias1 = &g_biash[((size_t)h * NTOK + qb + m0 + lr + 8) * NTOK];
#pragma unroll
        for (int nt = 0; nt < 8; nt++) {
            int jc = j0 + nt * 8 + 2 * lc;
            float2 b0 = __half22float2(*(const __half2*)&bias0[jc]);
            float2 b1 = __half22float2(*(const __half2*)&bias1[jc]);
            float mk0 = mask[jc], mk1 = mask[jc + 1];
            sacc[nt][0] += b0.x + INFV * (mq0 * mk0 - 1.f);
            sacc[nt][1] += b0.y + INFV * (mq0 * mk1 - 1.f);
            sacc[nt][2] += b1.x + INFV * (mq1 * mk0 - 1.f);
            sacc[nt][3] += b1.y + INFV * (mq1 * mk1 - 1.f);
            rmax0 = fmaxf(rmax0, fmaxf(sacc[nt][0], sacc[nt][1]));
            rmax1 = fmaxf(rmax1, fmaxf(sacc[nt][2], sacc[nt][3]));
        }
#pragma unroll
        for (int off = 1; off < 4; off <<= 1) {
            rmax0 = fmaxf(rmax0, __shfl_xor_sync(0xffffffffu, rmax0, off));
            rmax1 = fmaxf(rmax1, __shfl_xor_sync(0xffffffffu, rmax1, off));
        }
        float mnew0 = fmaxf(mrow0, rmax0);
        float mnew1 = fmaxf(mrow1, rmax1);
        float scale0 = __expf(mrow0 - mnew0);
        float scale1 = __expf(mrow1 - mnew1);

        float sum0 = 0.f, sum1 = 0.f;
        uint32_t ph[8][2];
#pragma unroll
        for (int nt = 0; nt < 8; nt++) {
            sacc[nt][0] = __expf(sacc[nt][0] - mnew0);
            sacc[nt][1] = __expf(sacc[nt][1] - mnew0);
            sacc[nt][2] = __expf(sacc[nt][2] - mnew1);
            sacc[nt][3] = __expf(sacc[nt][3] - mnew1);
            sum0 += sacc[nt][0] + sacc[nt][1];
            sum1 += sacc[nt][2] + sacc[nt][3];
            ph[nt][0] = packh2(sacc[nt][0], sacc[nt][1]);
            ph[nt][1] = packh2(sacc[nt][2], sacc[nt][3]);
        }
#pragma unroll
        for (int off = 1; off < 4; off <<= 1) {
            sum0 += __shfl_xor_sync(0xffffffffu, sum0, off);
            sum1 += __shfl_xor_sync(0xffffffffu, sum1, off);
        }
        lrow0 = lrow0 * scale0 + sum0;  mrow0 = mnew0;
        lrow1 = lrow1 * scale1 + sum1;  mrow1 = mnew1;
#pragma unroll
        for (int vt = 0; vt < 6; vt++) {
            oacc[vt][0] *= scale0; oacc[vt][1] *= scale0;
            oacc[vt][2] *= scale1; oacc[vt][3] *= scale1;
        }

        // O += P @ V : fp16 m16n8k16, A in registers, B from vsh
#pragma unroll
        for (int ks4 = 0; ks4 < 4; ks4++) {
            uint32_t a[4];
            a[0] = ph[ks4 * 2][0];
            a[1] = ph[ks4 * 2][1];
            a[2] = ph[ks4 * 2 + 1][0];
            a[3] = ph[ks4 * 2 + 1][1];
#pragma unroll
            for (int vt = 0; vt < 6; vt++) {
                int d = vt * 8 + lr;
                uint32_t b[2];
                b[0] = vsh[d * 36 + ks4 * 8 + lc];
                b[1] = vsh[d * 36 + ks4 * 8 + 4 + lc];
                mma_f16(oacc[vt], a, b);
            }
        }
    }

    int q0 = qb + m0 + lr, q1 = q0 + 8;
    int pb0 = ((split * NH + h) * NTOK + q0) * DH;
    int pb1 = ((split * NH + h) * NTOK + q1) * DH;
#pragma unroll
    for (int vt = 0; vt < 6; vt++) {
        int d = vt * 8 + 2 * lc;
        *(float2*)&g_po[pb0 + d] = make_float2(oacc[vt][0], oacc[vt][1]);
        *(float2*)&g_po[pb1 + d] = make_float2(oacc[vt][2], oacc[vt][3]);
    }
    if (lc == 0) {
        g_pm[(split * NH + h) * NTOK + q0] = mrow0;
        g_pl[(split * NH + h) * NTOK + q0] = lrow0;
        g_pm[(split * NH + h) * NTOK + q1] = mrow1;
        g_pl[(split * NH + h) * NTOK + q1] = lrow1;
    }
}

// ===========================================================================
// Kernel 4b: merge 4 splits, normalize, apply gate -> g_og.
// ===========================================================================
__global__ __launch_bounds__(256) void merge_kernel()
{
    int q = blockIdx.x;
    int t = threadIdx.x;
    int h = t >> 4;
    int d0 = (t & 15) * 3;

    float m[NSPLIT], l[NSPLIT];
    float M = -1e30f;
#pragma unroll
    for (int s = 0; s < NSPLIT; s++) {
        m[s] = g_pm[(s * NH + h) * NTOK + q];
        l[s] = g_pl[(s * NH + h) * NTOK + q];
        M = fmaxf(M, m[s]);
    }
    float w[NSPLIT], ltot = 0.f;
#pragma unroll
    for (int s = 0; s < NSPLIT; s++) {
        w[s] = __expf(m[s] - M);
        ltot += l[s] * w[s];
    }
    float inv = 1.f / ltot;
    int go = q * HD + h * DH + d0;
#pragma unroll
    for (int u = 0; u < 3; u++) {
        float val = 0.f;
#pragma unroll
        for (int s = 0; s < NSPLIT; s++)
            val += g_po[((s * NH + h) * NTOK + q) * DH + d0 + u] * w[s];
        g_og[go + u] = val * inv * g_g[go + u];
    }
}

// ===========================================================================
// Kernel 5: output projection via tf32 mma. BM=64, BN=64, BK=32.
// ===========================================================================
__global__ __launch_bounds__(128) void outproj_kernel(const float* __restrict__ W,
                                                      const float* __restrict__ bo,
                                                      float* __restrict__ out)
{
    int n0 = blockIdx.x * 64;
    int m0 = blockIdx.y * 64;

    __shared__ __align__(16) uint32_t As[64 * 36];
    __shared__ __align__(16) uint32_t Bs[32 * 72];

    int tid  = threadIdx.x;
    int lane = tid & 31;
    int warp = tid >> 5;
    int wm = warp >> 1, wn = warp & 1;
    int mw0 = wm * 32, nw0 = wn * 32;
    int lr = lane >> 2, lc = lane & 3;

    float acc[2][4][4];
#pragma unroll
    for (int mt = 0; mt < 2; mt++)
#pragma unroll
        for (int nt = 0; nt < 4; nt++)
#pragma unroll
            for (int u = 0; u < 4; u++) acc[mt][nt][u] = 0.f;

    for (int k0 = 0; k0 < HD; k0 += 32) {
#pragma unroll
        for (int it = 0; it < 4; it++) {
            int t = tid + it * 128;
            int r = t >> 3, c4 = t & 7;
            float4 v = *(const float4*)&g_og[(m0 + r) * HD + k0 + c4 * 4];
            uint32_t* d = &As[r * 36 + c4 * 4];
            d[0] = f2tf32(v.x); d[1] = f2tf32(v.y);
            d[2] = f2tf32(v.z); d[3] = f2tf32(v.w);
        }
#pragma unroll
        for (int it = 0; it < 4; it++) {
            int t = tid + it * 128;
            int r = t >> 4, c4 = t & 15;
            float4 v = *(const float4*)&W[(k0 + r) * CQ + n0 + c4 * 4];
            uint32_t* d = &Bs[r * 72 + c4 * 4];
            d[0] = f2tf32(v.x); d[1] = f2tf32(v.y);
            d[2] = f2tf32(v.z); d[3] = f2tf32(v.w);
        }
        __syncthreads();
#pragma unroll
        for (int ks = 0; ks < 4; ks++) {
            int kk = ks * 8;
            uint32_t a[2][4];
#pragma unroll
            for (int mt = 0; mt < 2; mt++) {
                int ar = mw0 + mt * 16 + lr;
                int ac = kk + lc;
                a[mt][0] = As[ar * 36 + ac];
                a[mt][1] = As[(ar + 8) * 36 + ac];
                a[mt][2] = As[ar * 36 + ac + 4];
                a[mt][3] = As[(ar + 8) * 36 + ac + 4];
            }
#pragma unroll
            for (int nt = 0; nt < 4; nt++) {
                uint32_t b[2];
                int bk = kk + lc;
                int bn = nw0 + nt * 8 + lr;
                b[0] = Bs[bk * 72 + bn];
                b[1] = Bs[(bk + 4) * 72 + bn];
                mma_tf32(acc[0][nt], a[0], b);
                mma_tf32(acc[1][nt], a[1], b);
            }
        }
        __syncthreads();
    }

#pragma unroll
    for (int mt = 0; mt < 2; mt++) {
#pragma unroll
        for (int nt = 0; nt < 4; nt++) {
            int cc = n0 + nw0 + nt * 8 + 2 * lc;
            float b0 = bo[cc], b1 = bo[cc + 1];
#pragma unroll
            for (int half = 0; half < 2; half++) {
                int r = m0 + mw0 + mt * 16 + lr + half * 8;
                float2 o2;
                o2.x = acc[mt][nt][half * 2 + 0] + b0;
                o2.y = acc[mt][nt][half * 2 + 1] + b1;
                *(float2*)&out[r * CQ + cc] = o2;
            }
        }
    }
}

// ===========================================================================
extern "C" void kernel_launch(void* const* d_in, const int* in_sizes, int n_in,
                              void* d_out, int out_size)
{
    const float* a    = (const float*)d_in[0];
    const float* z    = (const float*)d_in[1];
    const float* mask = (const float*)d_in[2];
    const float* g_a  = (const float*)d_in[3];
    const float* b_a  = (const float*)d_in[4];
    const float* g_z  = (const float*)d_in[5];
    const float* b_z  = (const float*)d_in[6];
    const float* w_z  = (const float*)d_in[7];
    const float* w_q  = (const float*)d_in[8];
    const float* w_k  = (const float*)d_in[9];
    const float* w_v  = (const float*)d_in[10];
    const float* w_g  = (const float*)d_in[11];
    const float* b_g  = (const float*)d_in[12];
    const float* w_o  = (const float*)d_in[13];
    const float* b_o  = (const float*)d_in[14];
    float* out = (float*)d_out;

    ln_a_kernel<<<NTOK + 1, 256>>>(a, g_a, b_a, g_z, b_z, w_z);
    proj_kernel<<<dim3(24, 16), 128>>>(w_q, w_k, w_v, w_g, b_g);
    pairbias_kernel<<<dim3(16, NTOK), 128>>>(z);
    attn_kernel<<<dim3(16, NH, NSPLIT), 128>>>(mask);
    merge_kernel<<<NTOK, 256>>>();
    outproj_kernel<<<dim3(12, 16), 128>>>(w_o, b_o, out);
}

// round 14
// speedup vs baseline: 3.5453x; 1.0362x over previous
#include <cuda_runtime.h>
#include <cuda_fp16.h>
#include <math.h>
#include <stdint.h>

#define NTOK 1024
#define CQ   768
#define CZ   128
#define NH   16
#define DH   48
#define HD   768
#define EPSV 1e-5f
#define INFV 1.0e9f
#define NSPLIT 4

// ------------- static device scratch (no allocations allowed) -------------
__device__ float g_an[NTOK * CQ];
__device__ __align__(16) __half   g_qh[NTOK * HD];       // fp16 Q [tok][HD] (scaled)
__device__ __align__(16) uint32_t g_kp[(HD / 2) * NTOK]; // half2 K (d,d+1) [d2][tok]
__device__ __align__(16) __half   g_vh[HD * NTOK];       // fp16 V^T [h*DH+d][tok]
__device__ float g_g [NTOK * HD];
__device__ float g_og[NTOK * HD];
__device__ __align__(16) __half g_biash[(size_t)NH * NTOK * NTOK];  // 32 MB
__device__ float g_po[NSPLIT * NH * NTOK * DH];
__device__ float g_pm[NSPLIT * NH * NTOK];
__device__ float g_pl[NSPLIT * NH * NTOK];
__device__ __align__(16) uint32_t g_wgt[NH * 144];  // tf32 wg, fragment-quad
__device__ float g_Svec[NH], g_Bcvec[NH];

// ------------------------- mma helpers -------------------------------
__device__ __forceinline__ uint32_t f2tf32(float f) {
    uint32_t r;
    asm("cvt.rna.tf32.f32 %0, %1;" : "=r"(r) : "f"(f));
    return r;
}
__device__ __forceinline__ void mma_tf32(float* d, const uint32_t* a, const uint32_t* b) {
    asm("mma.sync.aligned.m16n8k8.row.col.f32.tf32.tf32.f32 "
        "{%0,%1,%2,%3}, {%4,%5,%6,%7}, {%8,%9}, {%0,%1,%2,%3};"
        : "+f"(d[0]), "+f"(d[1]), "+f"(d[2]), "+f"(d[3])
        : "r"(a[0]), "r"(a[1]), "r"(a[2]), "r"(a[3]), "r"(b[0]), "r"(b[1]));
}
__device__ __forceinline__ void mma_f16(float* d, const uint32_t* a, const uint32_t* b) {
    asm("mma.sync.aligned.m16n8k16.row.col.f32.f16.f16.f32 "
        "{%0,%1,%2,%3}, {%4,%5,%6,%7}, {%8,%9}, {%0,%1,%2,%3};"
        : "+f"(d[0]), "+f"(d[1]), "+f"(d[2]), "+f"(d[3])
        : "r"(a[0]), "r"(a[1]), "r"(a[2]), "r"(a[3]), "r"(b[0]), "r"(b[1]));
}
__device__ __forceinline__ uint32_t packh2(float lo, float hi) {
    __half2 h = __floats2half2_rn(lo, hi);
    return *(uint32_t*)&h;
}
__device__ __forceinline__ uint32_t smem_u32(const void* p) {
    uint32_t r;
    asm("{.reg .u64 t; cvta.to.shared.u64 t, %1; cvt.u32.u64 %0, t;}" : "=r"(r) : "l"(p));
    return r;
}
__device__ __forceinline__ void cp_async16(uint32_t dst, const void* src) {
    asm volatile("cp.async.cg.shared.global [%0], [%1], 16;" :: "r"(dst), "l"(src));
}
__device__ __forceinline__ void cp_async_wait_all() {
    asm volatile("cp.async.commit_group;\n cp.async.wait_group 0;" ::: "memory");
}

// ===========================================================================
// Kernel 1: LayerNorm(a) -> g_an (blocks 0..1023); block 1024 = pb setup.
// ===========================================================================
__global__ __launch_bounds__(256) void ln_a_kernel(const float* __restrict__ a,
                                                   const float* __restrict__ ga,
                                                   const float* __restrict__ ba,
                                                   const float* __restrict__ gz,
                                                   const float* __restrict__ bz,
                                                   const float* __restrict__ wz)
{
    int row = blockIdx.x;
    int tid = threadIdx.x;
    if (row == NTOK) {
        for (int i = tid; i < NH * 144; i += 256) g_wgt[i] = 0u;
        __syncthreads();
        for (int i = tid; i < NH * CZ; i += 256) {
            int h = i >> 7, c = i & 127;
            int g = c >> 4, rem = c & 15;
            int lc = rem & 3, w = rem >> 2;
            g_wgt[h * 144 + lc * 36 + g * 4 + w] = f2tf32(gz[c] * wz[c * NH + h]);
        }
        if (tid < NH) {
            float S = 0.f, Bc = 0.f;
            for (int c = 0; c < CZ; c++) {
                S  += gz[c] * wz[c * NH + tid];
                Bc += bz[c] * wz[c * NH + tid];
            }
            g_Svec[tid] = S; g_Bcvec[tid] = Bc;
        }
        return;
    }
    const float* x = a + row * CQ;
    float v0 = x[tid], v1 = x[tid + 256], v2 = x[tid + 512];
    float s = v0 + v1 + v2;
    float q = v0 * v0 + v1 * v1 + v2 * v2;
#pragma unroll
    for (int o = 16; o > 0; o >>= 1) {
        s += __shfl_xor_sync(0xffffffffu, s, o);
        q += __shfl_xor_sync(0xffffffffu, q, o);
    }
    __shared__ float sw[8], qw[8];
    __shared__ float smu, srv;
    if ((tid & 31) == 0) { sw[tid >> 5] = s; qw[tid >> 5] = q; }
    __syncthreads();
    if (tid == 0) {
        float S = 0.f, Q = 0.f;
#pragma unroll
        for (int w = 0; w < 8; w++) { S += sw[w]; Q += qw[w]; }
        float mu = S * (1.f / (float)CQ);
        float var = Q * (1.f / (float)CQ) - mu * mu;
        smu = mu;
        srv = rsqrtf(fmaxf(var, 0.f) + EPSV);
    }
    __syncthreads();
    float mu = smu, r = srv;
    float* o = g_an + row * CQ;
    o[tid]       = (v0 - mu) * r * ga[tid]       + ba[tid];
    o[tid + 256] = (v1 - mu) * r * ga[tid + 256] + ba[tid + 256];
    o[tid + 512] = (v2 - mu) * r * ga[tid + 512] + ba[tid + 512];
}

// ===========================================================================
// Kernel 2: fused QKVG projections via tf32 mma. BM=64, BN=128, BK=32.
// Q written fp16 (scaled), K as d-paired half2 [d2][tok], V fp16 [d][tok].
// ===========================================================================
__global__ __launch_bounds__(128) void proj_kernel(const float* __restrict__ Wq,
                                                   const float* __restrict__ Wk,
                                                   const float* __restrict__ Wv,
                                                   const float* __restrict__ Wg,
                                                   const float* __restrict__ bg)
{
    int n0 = blockIdx.x * 128;
    int sel  = n0 / HD;
    int ncol = n0 - sel * HD;
    const float* W = (sel == 0) ? Wq : (sel == 1) ? Wk : (sel == 2) ? Wv : Wg;
    int m0 = blockIdx.y * 64;

    __shared__ __align__(16) uint32_t As[64 * 36];
    __shared__ __align__(16) uint32_t Bs[32 * 136];

    int tid  = threadIdx.x;
    int lane = tid & 31;
    int warp = tid >> 5;
    int wm = warp >> 1, wn = warp & 1;
    int mw0 = wm * 32, nw0 = wn * 64;
    int lr = lane >> 2, lc = lane & 3;

    float acc[2][8][4];
#pragma unroll
    for (int mt = 0; mt < 2; mt++)
#pragma unroll
        for (int nt = 0; nt < 8; nt++)
#pragma unroll
            for (int u = 0; u < 4; u++) acc[mt][nt][u] = 0.f;

    for (int k0 = 0; k0 < CQ; k0 += 32) {
#pragma unroll
        for (int it = 0; it < 4; it++) {
            int t = tid + it * 128;
            int r = t >> 3, c4 = t & 7;
            float4 v = *(const float4*)&g_an[(m0 + r) * CQ + k0 + c4 * 4];
            uint32_t* d = &As[r * 36 + c4 * 4];
            d[0] = f2tf32(v.x); d[1] = f2tf32(v.y);
            d[2] = f2tf32(v.z); d[3] = f2tf32(v.w);
        }
#pragma unroll
        for (int it = 0; it < 8; it++) {
            int t = tid + it * 128;
            int r = t >> 5, c4 = t & 31;
            float4 v = *(const float4*)&W[(k0 + r) * HD + ncol + c4 * 4];
            uint32_t* d = &Bs[r * 136 + c4 * 4];
            d[0] = f2tf32(v.x); d[1] = f2tf32(v.y);
            d[2] = f2tf32(v.z); d[3] = f2tf32(v.w);
        }
        __syncthreads();
#pragma unroll
        for (int ks = 0; ks < 4; ks++) {
            int kk = ks * 8;
            uint32_t a[2][4];
#pragma unroll
            for (int mt = 0; mt < 2; mt++) {
                int ar = mw0 + mt * 16 + lr;
                int ac = kk + lc;
                a[mt][0] = As[ar * 36 + ac];
                a[mt][1] = As[(ar + 8) * 36 + ac];
                a[mt][2] = As[ar * 36 + ac + 4];
                a[mt][3] = As[(ar + 8) * 36 + ac + 4];
            }
#pragma unroll
            for (int nt = 0; nt < 8; nt++) {
                uint32_t b[2];
                int bk = kk + lc;
                int bn = nw0 + nt * 8 + lr;
                b[0] = Bs[bk * 136 + bn];
                b[1] = Bs[(bk + 4) * 136 + bn];
                mma_tf32(acc[0][nt], a[0], b);
                mma_tf32(acc[1][nt], a[1], b);
            }
        }
        __syncthreads();
    }

    const float scaleq = 0.14433756729740643f;
#pragma unroll
    for (int mt = 0; mt < 2; mt++) {
#pragma unroll
        for (int nt = 0; nt < 8; nt++) {
            int cc = ncol + nw0 + nt * 8 + 2 * lc;   // always even
#pragma unroll
            for (int half = 0; half < 2; half++) {
                int r = m0 + mw0 + mt * 16 + lr + half * 8;
                float v0 = acc[mt][nt][half * 2 + 0];
                float v1 = acc[mt][nt][half * 2 + 1];
                if (sel == 0) {                 // Q fp16, scaled
                    *(uint32_t*)&g_qh[r * HD + cc] = packh2(v0 * scaleq, v1 * scaleq);
                } else if (sel == 1) {          // K d-paired half2 [d2][tok]
                    g_kp[(cc >> 1) * NTOK + r] = packh2(v0, v1);
                } else if (sel == 2) {          // V^T fp16 [d][tok]
                    g_vh[cc * NTOK + r]       = __float2half_rn(v0);
                    g_vh[(cc + 1) * NTOK + r] = __float2half_rn(v1);
                } else {
                    float2 o2;
                    o2.x = 1.f / (1.f + __expf(-(v0 + bg[cc])));
                    o2.y = 1.f / (1.f + __expf(-(v1 + bg[cc + 1])));
                    *(float2*)&g_g[r * HD + cc] = o2;
                }
            }
        }
    }
}

// ===========================================================================
// Kernel 3: pair bias via tf32 mma + fused LN; bias written as fp16. (R12)
// ===========================================================================
__global__ __launch_bounds__(128) void pairbias_kernel(const float* __restrict__ z)
{
    __shared__ __align__(16) float    ztf[64 * 132];
    __shared__ __align__(16) uint32_t wgt[NH * 144];
    __shared__ float Ssh[NH], Bcsh[NH], mus[64], rvs[64];

    int tid  = threadIdx.x;
    int lane = tid & 31;
    int warp = tid >> 5;
    int i  = blockIdx.y;
    int j0 = blockIdx.x * 64;

    {
        const uint4* src = (const uint4*)g_wgt;
        for (int t2 = tid; t2 < 576; t2 += 128)
            cp_async16(smem_u32((uint4*)wgt + t2), src + t2);
    }
    const float4* zb = (const float4*)(z + ((size_t)i * NTOK + j0) * CZ);
#pragma unroll
    for (int u = 0; u < 16; u++) {
        int idx = tid + 128 * u;
        int r = idx >> 5;
        cp_async16(smem_u32(&ztf[r * 132 + lane * 4]), zb + idx);
    }
    if (tid < NH) { Ssh[tid] = g_Svec[tid]; Bcsh[tid] = g_Bcvec[tid]; }
    cp_async_wait_all();
    __syncthreads();

    if (tid < 64) {
        float s = 0.f, sq = 0.f;
        const float* zr = &ztf[tid * 132];
#pragma unroll
        for (int cq = 0; cq < 32; cq++) {
            float4 w = *(const float4*)&zr[cq * 4];
            s += w.x + w.y + w.z + w.w;
            sq = fmaf(w.x, w.x, sq); sq = fmaf(w.y, w.y, sq);
            sq = fmaf(w.z, w.z, sq); sq = fmaf(w.w, w.w, sq);
        }
        float mu  = s * (1.f / (float)CZ);
        float var = sq * (1.f / (float)CZ) - mu * mu;
        mus[tid] = mu;
        rvs[tid] = rsqrtf(fmaxf(var, 0.f) + EPSV);
    }

    int m0 = warp * 16;
    int lr = lane >> 2, lc = lane & 3;
    float acc[2][4];
#pragma unroll
    for (int n = 0; n < 2; n++)
#pragma unroll
        for (int u = 0; u < 4; u++) acc[n][u] = 0.f;

    const uint32_t* wgt0 = &wgt[lr * 144 + lc * 36];
    const uint32_t* wgt1 = &wgt[(8 + lr) * 144 + lc * 36];
#pragma unroll
    for (int g = 0; g < 8; g++) {
        uint4 bq0 = *(const uint4*)(wgt0 + g * 4);
        uint4 bq1 = *(const uint4*)(wgt1 + g * 4);
#pragma unroll
        for (int kh = 0; kh < 2; kh++) {
            int kk = (g * 2 + kh) * 8;
            int ar = m0 + lr, ac = kk + lc;
            uint32_t a[4];
            a[0] = f2tf32(ztf[ar * 132 + ac]);
            a[1] = f2tf32(ztf[(ar + 8) * 132 + ac]);
            a[2] = f2tf32(ztf[ar * 132 + ac + 4]);
            a[3] = f2tf32(ztf[(ar + 8) * 132 + ac + 4]);
            uint32_t b0[2], b1[2];
            b0[0] = kh ? bq0.z : bq0.x;  b0[1] = kh ? bq0.w : bq0.y;
            b1[0] = kh ? bq1.z : bq1.x;  b1[1] = kh ? bq1.w : bq1.y;
            mma_tf32(acc[0], a, b0);
            mma_tf32(acc[1], a, b1);
        }
    }
    __syncthreads();

    float* outs = ztf;                    // [h][j], stride 68
#pragma unroll
    for (int n = 0; n < 2; n++) {
        int h0 = n * 8 + 2 * lc;
#pragma unroll
        for (int half = 0; half < 2; half++) {
            int r = m0 + lr + half * 8;
            float mu = mus[r], rv = rvs[r];
            outs[h0 * 68 + r]       = rv * (acc[n][half * 2 + 0] - mu * Ssh[h0])     + Bcsh[h0];
            outs[(h0 + 1) * 68 + r] = rv * (acc[n][half * 2 + 1] - mu * Ssh[h0 + 1]) + Bcsh[h0 + 1];
        }
    }
    __syncthreads();
    {
        int h = tid >> 3, j8 = (tid & 7) * 8;
        const float* src = &outs[h * 68 + j8];
        uint4 pk;
        pk.x = packh2(src[0], src[1]);
        pk.y = packh2(src[2], src[3]);
        pk.z = packh2(src[4], src[5]);
        pk.w = packh2(src[6], src[7]);
        *(uint4*)&g_biash[((size_t)h * NTOK + i) * NTOK + j0 + j8] = pk;
    }
}

// ===========================================================================
// Kernel 4: flash attention, all-fp16 tensor path.
// QK^T: fp16 m16n8k16, 3 k-steps (Q smem stride 56 halves, K [d2][j] stride 72
// words; both fragment patterns conflict-free). PV: fp16 with register P.
// Staging via raw cp.async (Q/K/V pre-packed by proj). Split-KV x4.
// ===========================================================================
__global__ __launch_bounds__(128) void attn_kernel(const float* __restrict__ mask)
{
    int h     = blockIdx.y;
    int qb    = blockIdx.x * 64;
    int split = blockIdx.z;
    int tid  = threadIdx.x;
    int lane = tid & 31;
    int warp = tid >> 5;
    int lr = lane >> 2, lc = lane & 3;
    int m0 = warp * 16;

    __shared__ __align__(16) __half   qs[64 * 56];   // fp16 Q [q][d], stride 56
    __shared__ __align__(16) uint32_t ks2[24 * 72];  // half2 K (d,d+1) [d2][j]
    __shared__ __align__(16) uint32_t vsh[48 * 36];  // half2 V^T [d][j/2]

    // stage Q via cp.async: 64 rows x 6 chunks = 384; 3 per thread
#pragma unroll
    for (int it = 0; it < 3; it++) {
        int u = tid + it * 128;
        int row = u / 6, cx = u % 6;
        cp_async16(smem_u32(&qs[row * 56 + cx * 8]),
                   &g_qh[(size_t)(qb + row) * HD + h * DH + cx * 8]);
    }

    float mrow0 = -1e30f, mrow1 = -1e30f, lrow0 = 0.f, lrow1 = 0.f;
    float oacc[6][4];
#pragma unroll
    for (int vt = 0; vt < 6; vt++)
#pragma unroll
        for (int u = 0; u < 4; u++) oacc[vt][u] = 0.f;

    float mq0 = mask[qb + m0 + lr];
    float mq1 = mask[qb + m0 + lr + 8];

    for (int jt = split * 4; jt < split * 4 + 4; jt++) {
        int j0 = jt * 64;
        __syncthreads();                     // prev-tile ks2/vsh reads done
        // K: 24 d2-rows x 64 words = 384 chunks; 3 per thread
#pragma unroll
        for (int it = 0; it < 3; it++) {
            int u = tid + it * 128;
            int row = u >> 4, cx = u & 15;
            cp_async16(smem_u32(&ks2[row * 72 + cx * 4]),
                       &g_kp[(size_t)(h * (DH / 2) + row) * NTOK + j0 + cx * 4]);
        }
        // V: 48 d-rows x 32 words = 384 chunks; 3 per thread
#pragma unroll
        for (int it = 0; it < 3; it++) {
            int u = tid + it * 128;
            int row = u >> 3, cx = u & 7;
            cp_async16(smem_u32(&vsh[row * 36 + cx * 4]),
                       &g_vh[(size_t)(h * DH + row) * NTOK + j0 + cx * 8]);
        }
        cp_async_wait_all();
        __syncthreads();

        // scores S[16 x 64] per warp: fp16 mma, 3 k16 steps
        float sacc[8][4];
#pragma unroll
        for (int nt = 0; nt < 8; nt++)
#pragma unroll
            for (int u = 0; u < 4; u++) sacc[nt][u] = 0.f;
#pragma unroll
        for (int s = 0; s < 3; s++) {
            int ar = m0 + lr;
            uint32_t a[4];
            a[0] = *(const uint32_t*)&qs[ar * 56 + (s * 8 + lc) * 2];
            a[1] = *(const uint32_t*)&qs[(ar + 8) * 56 + (s * 8 + lc) * 2];
            a[2] = *(const uint32_t*)&qs[ar * 56 + (s * 8 + 4 + lc) * 2];
            a[3] = *(const uint32_t*)&qs[(ar + 8) * 56 + (s * 8 + 4 + lc) * 2];
#pragma unroll
            for (int nt = 0; nt < 8; nt++) {
                uint32_t b[2];
                b[0] = ks2[(s * 8 + lc) * 72 + nt * 8 + lr];
                b[1] = ks2[(s * 8 + 4 + lc) * 72 + nt * 8 + lr];
                mma_f16(sacc[nt], a, b);
            }
        }

        // fp16 bias + mask, running row max
        float rmax0 = -1e30f, rmax1 = -1e30f;
        const __half* bias0 = &g_biash[((size_t)h * NTOK + qb + m0 + lr) * NTOK];
        const __half* bias1 = &g_biash[((size_t)h * NTOK + qb + m0 + lr + 8) * NTOK];
#pragma unroll
        for (int nt = 0; nt < 8; nt++) {
            int jc = j0 + nt * 8 + 2 * lc;
            float2 b0 = __half22float2(*(const __half2*)&bias0[jc]);
            float2 b1 = __half22float2(*(const __half2*)&bias1[jc]);
            float mk0 = mask[jc], mk1 = mask[jc + 1];
            sacc[nt][0] += b0.x + INFV * (mq0 * mk0 - 1.f);
            sacc[nt][1] += b0.y + INFV * (mq0 * mk1 - 1.f);
            sacc[nt][2] += b1.x + INFV * (mq1 * mk0 - 1.f);
            sacc[nt][3] += b1.y + INFV * (mq1 * mk1 - 1.f);
            rmax0 = fmaxf(rmax0, fmaxf(sacc[nt][0], sacc[nt][1]));
            rmax1 = fmaxf(rmax1, fmaxf(sacc[nt][2], sacc[nt][3]));
        }
#pragma unroll
        for (int off = 1; off < 4; off <<= 1) {
            rmax0 = fmaxf(rmax0, __shfl_xor_sync(0xffffffffu, rmax0, off));
            rmax1 = fmaxf(rmax1, __shfl_xor_sync(0xffffffffu, rmax1, off));
        }
        float mnew0 = fmaxf(mrow0, rmax0);
        float mnew1 = fmaxf(mrow1, rmax1);
        float scale0 = __expf(mrow0 - mnew0);
        float scale1 = __expf(mrow1 - mnew1);

        float sum0 = 0.f, sum1 = 0.f;
        uint32_t ph[8][2];
#pragma unroll
        for (int nt = 0; nt < 8; nt++) {
            sacc[nt][0] = __expf(sacc[nt][0] - mnew0);
            sacc[nt][1] = __expf(sacc[nt][1] - mnew0);
            sacc[nt][2] = __expf(sacc[nt][2] - mnew1);
            sacc[nt][3] = __expf(sacc[nt][3] - mnew1);
            sum0 += sacc[nt][0] + sacc[nt][1];
            sum1 += sacc[nt][2] + sacc[nt][3];
            ph[nt][0] = packh2(sacc[nt][0], sacc[nt][1]);
            ph[nt][1] = packh2(sacc[nt][2], sacc[nt][3]);
        }
#pragma unroll
        for (int off = 1; off < 4; off <<= 1) {
            sum0 += __shfl_xor_sync(0xffffffffu, sum0, off);
            sum1 += __shfl_xor_sync(0xffffffffu, sum1, off);
        }
        lrow0 = lrow0 * scale0 + sum0;  mrow0 = mnew0;
        lrow1 = lrow1 * scale1 + sum1;  mrow1 = mnew1;
#pragma unroll
        for (int vt = 0; vt < 6; vt++) {
            oacc[vt][0] *= scale0; oacc[vt][1] *= scale0;
            oacc[vt][2] *= scale1; oacc[vt][3] *= scale1;
        }

        // O += P @ V : fp16 m16n8k16, A in registers, B from vsh
#pragma unroll
        for (int ks4 = 0; ks4 < 4; ks4++) {
            uint32_t a[4];
            a[0] = ph[ks4 * 2][0];
            a[1] = ph[ks4 * 2][1];
            a[2] = ph[ks4 * 2 + 1][0];
            a[3] = ph[ks4 * 2 + 1][1];
#pragma unroll
            for (int vt = 0; vt < 6; vt++) {
                int d = vt * 8 + lr;
                uint32_t b[2];
                b[0] = vsh[d * 36 + ks4 * 8 + lc];
                b[1] = vsh[d * 36 + ks4 * 8 + 4 + lc];
                mma_f16(oacc[vt], a, b);
            }
        }
    }

    int q0 = qb + m0 + lr, q1 = q0 + 8;
    int pb0 = ((split * NH + h) * NTOK + q0) * DH;
    int pb1 = ((split * NH + h) * NTOK + q1) * DH;
#pragma unroll
    for (int vt = 0; vt < 6; vt++) {
        int d = vt * 8 + 2 * lc;
        *(float2*)&g_po[pb0 + d] = make_float2(oacc[vt][0], oacc[vt][1]);
        *(float2*)&g_po[pb1 + d] = make_float2(oacc[vt][2], oacc[vt][3]);
    }
    if (lc == 0) {
        g_pm[(split * NH + h) * NTOK + q0] = mrow0;
        g_pl[(split * NH + h) * NTOK + q0] = lrow0;
        g_pm[(split * NH + h) * NTOK + q1] = mrow1;
        g_pl[(split * NH + h) * NTOK + q1] = lrow1;
    }
}

// ===========================================================================
// Kernel 4b: merge 4 splits, normalize, apply gate -> g_og.
// ===========================================================================
__global__ __launch_bounds__(256) void merge_kernel()
{
    int q = blockIdx.x;
    int t = threadIdx.x;
    int h = t >> 4;
    int d0 = (t & 15) * 3;

    float m[NSPLIT], l[NSPLIT];
    float M = -1e30f;
#pragma unroll
    for (int s = 0; s < NSPLIT; s++) {
        m[s] = g_pm[(s * NH + h) * NTOK + q];
        l[s] = g_pl[(s * NH + h) * NTOK + q];
        M = fmaxf(M, m[s]);
    }
    float w[NSPLIT], ltot = 0.f;
#pragma unroll
    for (int s = 0; s < NSPLIT; s++) {
        w[s] = __expf(m[s] - M);
        ltot += l[s] * w[s];
    }
    float inv = 1.f / ltot;
    int go = q * HD + h * DH + d0;
#pragma unroll
    for (int u = 0; u < 3; u++) {
        float val = 0.f;
#pragma unroll
        for (int s = 0; s < NSPLIT; s++)
            val += g_po[((s * NH + h) * NTOK + q) * DH + d0 + u] * w[s];
        g_og[go + u] = val * inv * g_g[go + u];
    }
}

// ===========================================================================
// Kernel 5: output projection via tf32 mma. BM=64, BN=64, BK=32.
// ===========================================================================
__global__ __launch_bounds__(128) void outproj_kernel(const float* __restrict__ W,
                                                      const float* __restrict__ bo,
                                                      float* __restrict__ out)
{
    int n0 = blockIdx.x * 64;
    int m0 = blockIdx.y * 64;

    __shared__ __align__(16) uint32_t As[64 * 36];
    __shared__ __align__(16) uint32_t Bs[32 * 72];

    int tid  = threadIdx.x;
    int lane = tid & 31;
    int warp = tid >> 5;
    int wm = warp >> 1, wn = warp & 1;
    int mw0 = wm * 32, nw0 = wn * 32;
    int lr = lane >> 2, lc = lane & 3;

    float acc[2][4][4];
#pragma unroll
    for (int mt = 0; mt < 2; mt++)
#pragma unroll
        for (int nt = 0; nt < 4; nt++)
#pragma unroll
            for (int u = 0; u < 4; u++) acc[mt][nt][u] = 0.f;

    for (int k0 = 0; k0 < HD; k0 += 32) {
#pragma unroll
        for (int it = 0; it < 4; it++) {
            int t = tid + it * 128;
            int r = t >> 3, c4 = t & 7;
            float4 v = *(const float4*)&g_og[(m0 + r) * HD + k0 + c4 * 4];
            uint32_t* d = &As[r * 36 + c4 * 4];
            d[0] = f2tf32(v.x); d[1] = f2tf32(v.y);
            d[2] = f2tf32(v.z); d[3] = f2tf32(v.w);
        }
#pragma unroll
        for (int it = 0; it < 4; it++) {
            int t = tid + it * 128;
            int r = t >> 4, c4 = t & 15;
            float4 v = *(const float4*)&W[(k0 + r) * CQ + n0 + c4 * 4];
            uint32_t* d = &Bs[r * 72 + c4 * 4];
            d[0] = f2tf32(v.x); d[1] = f2tf32(v.y);
            d[2] = f2tf32(v.z); d[3] = f2tf32(v.w);
        }
        __syncthreads();
#pragma unroll
        for (int ks = 0; ks < 4; ks++) {
            int kk = ks * 8;
            uint32_t a[2][4];
#pragma unroll
            for (int mt = 0; mt < 2; mt++) {
                int ar = mw0 + mt * 16 + lr;
                int ac = kk + lc;
                a[mt][0] = As[ar * 36 + ac];
                a[mt][1] = As[(ar + 8) * 36 + ac];
                a[mt][2] = As[ar * 36 + ac + 4];
                a[mt][3] = As[(ar + 8) * 36 + ac + 4];
            }
#pragma unroll
            for (int nt = 0; nt < 4; nt++) {
                uint32_t b[2];
                int bk = kk + lc;
                int bn = nw0 + nt * 8 + lr;
                b[0] = Bs[bk * 72 + bn];
                b[1] = Bs[(bk + 4) * 72 + bn];
                mma_tf32(acc[0][nt], a[0], b);
                mma_tf32(acc[1][nt], a[1], b);
            }
        }
        __syncthreads();
    }

#pragma unroll
    for (int mt = 0; mt < 2; mt++) {
#pragma unroll
        for (int nt = 0; nt < 4; nt++) {
            int cc = n0 + nw0 + nt * 8 + 2 * lc;
            float b0 = bo[cc], b1 = bo[cc + 1];
#pragma unroll
            for (int half = 0; half < 2; half++) {
                int r = m0 + mw0 + mt * 16 + lr + half * 8;
                float2 o2;
                o2.x = acc[mt][nt][half * 2 + 0] + b0;
                o2.y = acc[mt][nt][half * 2 + 1] + b1;
                *(float2*)&out[r * CQ + cc] = o2;
            }
        }
    }
}

// ===========================================================================
extern "C" void kernel_launch(void* const* d_in, const int* in_sizes, int n_in,
                              void* d_out, int out_size)
{
    const float* a    = (const float*)d_in[0];
    const float* z    = (const float*)d_in[1];
    const float* mask = (const float*)d_in[2];
    const float* g_a  = (const float*)d_in[3];
    const float* b_a  = (const float*)d_in[4];
    const float* g_z  = (const float*)d_in[5];
    const float* b_z  = (const float*)d_in[6];
    const float* w_z  = (const float*)d_in[7];
    const float* w_q  = (const float*)d_in[8];
    const float* w_k  = (const float*)d_in[9];
    const float* w_v  = (const float*)d_in[10];
    const float* w_g  = (const float*)d_in[11];
    const float* b_g  = (const float*)d_in[12];
    const float* w_o  = (const float*)d_in[13];
    const float* b_o  = (const float*)d_in[14];
    float* out = (float*)d_out;

    ln_a_kernel<<<NTOK + 1, 256>>>(a, g_a, b_a, g_z, b_z, w_z);
    proj_kernel<<<dim3(24, 16), 128>>>(w_q, w_k, w_v, w_g, b_g);
    pairbias_kernel<<<dim3(16, NTOK), 128>>>(z);
    attn_kernel<<<dim3(16, NH, NSPLIT), 128>>>(mask);
    merge_kernel<<<NTOK, 256>>>();
    outproj_kernel<<<dim3(12, 16), 128>>>(w_o, b_o, out);
}

// round 15
// speedup vs baseline: 4.0804x; 1.1509x over previous
#include <cuda_runtime.h>
#include <cuda_fp16.h>
#include <math.h>
#include <stdint.h>

#define NTOK 1024
#define CQ   768
#define CZ   128
#define NH   16
#define DH   48
#define HD   768
#define EPSV 1e-5f
#define INFV 1.0e9f
#define NSPLIT 4

// ------------- static device scratch (no allocations allowed) -------------
__device__ __align__(16) __half   g_anh[NTOK * CQ];      // fp16 LN(a)
__device__ __align__(16) __half   g_qh[NTOK * HD];       // fp16 Q (scaled)
__device__ __align__(16) uint32_t g_kp[(HD / 2) * NTOK]; // half2 K (d,d+1) [d2][tok]
__device__ __align__(16) __half   g_vh[HD * NTOK];       // fp16 V^T [h*DH+d][tok]
__device__ float g_g [NTOK * HD];
__device__ __align__(16) __half   g_ogh[NTOK * HD];      // fp16 gated attn out
__device__ __align__(16) __half g_biash[(size_t)NH * NTOK * NTOK];  // 32 MB
__device__ float g_po[NSPLIT * NH * NTOK * DH];
__device__ float g_pm[NSPLIT * NH * NTOK];
__device__ float g_pl[NSPLIT * NH * NTOK];
__device__ __align__(16) uint32_t g_wgt[NH * 144];  // tf32 wg, fragment-quad
__device__ float g_Svec[NH], g_Bcvec[NH];

// ------------------------- mma helpers -------------------------------
__device__ __forceinline__ uint32_t f2tf32(float f) {
    uint32_t r;
    asm("cvt.rna.tf32.f32 %0, %1;" : "=r"(r) : "f"(f));
    return r;
}
__device__ __forceinline__ void mma_tf32(float* d, const uint32_t* a, const uint32_t* b) {
    asm("mma.sync.aligned.m16n8k8.row.col.f32.tf32.tf32.f32 "
        "{%0,%1,%2,%3}, {%4,%5,%6,%7}, {%8,%9}, {%0,%1,%2,%3};"
        : "+f"(d[0]), "+f"(d[1]), "+f"(d[2]), "+f"(d[3])
        : "r"(a[0]), "r"(a[1]), "r"(a[2]), "r"(a[3]), "r"(b[0]), "r"(b[1]));
}
__device__ __forceinline__ void mma_f16(float* d, const uint32_t* a, const uint32_t* b) {
    asm("mma.sync.aligned.m16n8k16.row.col.f32.f16.f16.f32 "
        "{%0,%1,%2,%3}, {%4,%5,%6,%7}, {%8,%9}, {%0,%1,%2,%3};"
        : "+f"(d[0]), "+f"(d[1]), "+f"(d[2]), "+f"(d[3])
        : "r"(a[0]), "r"(a[1]), "r"(a[2]), "r"(a[3]), "r"(b[0]), "r"(b[1]));
}
__device__ __forceinline__ uint32_t packh2(float lo, float hi) {
    __half2 h = __floats2half2_rn(lo, hi);
    return *(uint32_t*)&h;
}
__device__ __forceinline__ uint32_t smem_u32(const void* p) {
    uint32_t r;
    asm("{.reg .u64 t; cvta.to.shared.u64 t, %1; cvt.u32.u64 %0, t;}" : "=r"(r) : "l"(p));
    return r;
}
__device__ __forceinline__ void cp_async16(uint32_t dst, const void* src) {
    asm volatile("cp.async.cg.shared.global [%0], [%1], 16;" :: "r"(dst), "l"(src));
}
__device__ __forceinline__ void cp_async_wait_all() {
    asm volatile("cp.async.commit_group;\n cp.async.wait_group 0;" ::: "memory");
}

// ===========================================================================
// Kernel 1: LayerNorm(a) -> g_anh fp16 (blocks 0..1023); block 1024 = setup.
// ===========================================================================
__global__ __launch_bounds__(256) void ln_a_kernel(const float* __restrict__ a,
                                                   const float* __restrict__ ga,
                                                   const float* __restrict__ ba,
                                                   const float* __restrict__ gz,
                                                   const float* __restrict__ bz,
                                                   const float* __restrict__ wz)
{
    int row = blockIdx.x;
    int tid = threadIdx.x;
    if (row == NTOK) {
        for (int i = tid; i < NH * 144; i += 256) g_wgt[i] = 0u;
        __syncthreads();
        for (int i = tid; i < NH * CZ; i += 256) {
            int h = i >> 7, c = i & 127;
            int g = c >> 4, rem = c & 15;
            int lc = rem & 3, w = rem >> 2;
            g_wgt[h * 144 + lc * 36 + g * 4 + w] = f2tf32(gz[c] * wz[c * NH + h]);
        }
        if (tid < NH) {
            float S = 0.f, Bc = 0.f;
            for (int c = 0; c < CZ; c++) {
                S  += gz[c] * wz[c * NH + tid];
                Bc += bz[c] * wz[c * NH + tid];
            }
            g_Svec[tid] = S; g_Bcvec[tid] = Bc;
        }
        return;
    }
    const float* x = a + row * CQ;
    float v0 = x[tid], v1 = x[tid + 256], v2 = x[tid + 512];
    float s = v0 + v1 + v2;
    float q = v0 * v0 + v1 * v1 + v2 * v2;
#pragma unroll
    for (int o = 16; o > 0; o >>= 1) {
        s += __shfl_xor_sync(0xffffffffu, s, o);
        q += __shfl_xor_sync(0xffffffffu, q, o);
    }
    __shared__ float sw[8], qw[8];
    __shared__ float smu, srv;
    if ((tid & 31) == 0) { sw[tid >> 5] = s; qw[tid >> 5] = q; }
    __syncthreads();
    if (tid == 0) {
        float S = 0.f, Q = 0.f;
#pragma unroll
        for (int w = 0; w < 8; w++) { S += sw[w]; Q += qw[w]; }
        float mu = S * (1.f / (float)CQ);
        float var = Q * (1.f / (float)CQ) - mu * mu;
        smu = mu;
        srv = rsqrtf(fmaxf(var, 0.f) + EPSV);
    }
    __syncthreads();
    float mu = smu, r = srv;
    __half* o = g_anh + row * CQ;
    o[tid]       = __float2half_rn((v0 - mu) * r * ga[tid]       + ba[tid]);
    o[tid + 256] = __float2half_rn((v1 - mu) * r * ga[tid + 256] + ba[tid + 256]);
    o[tid + 512] = __float2half_rn((v2 - mu) * r * ga[tid + 512] + ba[tid + 512]);
}

// ===========================================================================
// Kernel 2: fused QKVG projections via fp16 m16n8k16. BM=64, BN=128, BK=32.
// A staged raw (fp16 an via cp.async); B packed to k-paired half2 at staging.
// Q->fp16 scaled, K->half2 [d2][tok], V->fp16 [d][tok], gate->fp32.
// ===========================================================================
__global__ __launch_bounds__(128) void proj_kernel(const float* __restrict__ Wq,
                                                   const float* __restrict__ Wk,
                                                   const float* __restrict__ Wv,
                                                   const float* __restrict__ Wg,
                                                   const float* __restrict__ bg)
{
    int n0 = blockIdx.x * 128;
    int sel  = n0 / HD;
    int ncol = n0 - sel * HD;
    const float* W = (sel == 0) ? Wq : (sel == 1) ? Wk : (sel == 2) ? Wv : Wg;
    int m0 = blockIdx.y * 64;

    __shared__ __align__(16) __half   As[64 * 40];    // fp16 [m][k], stride 40
    __shared__ __align__(16) uint32_t Bs[16 * 136];   // half2 k-pairs [k2][n]

    int tid  = threadIdx.x;
    int lane = tid & 31;
    int warp = tid >> 5;
    int wm = warp >> 1, wn = warp & 1;
    int mw0 = wm * 32, nw0 = wn * 64;
    int lr = lane >> 2, lc = lane & 3;

    float acc[2][8][4];
#pragma unroll
    for (int mt = 0; mt < 2; mt++)
#pragma unroll
        for (int nt = 0; nt < 8; nt++)
#pragma unroll
            for (int u = 0; u < 4; u++) acc[mt][nt][u] = 0.f;

    for (int k0 = 0; k0 < CQ; k0 += 32) {
        // A: 64 rows x 4 chunks of 8 halves; 2 per thread (cp.async)
#pragma unroll
        for (int it = 0; it < 2; it++) {
            int u = tid + it * 128;
            int r = u >> 2, cx = u & 3;
            cp_async16(smem_u32(&As[r * 40 + cx * 8]),
                       &g_anh[(size_t)(m0 + r) * CQ + k0 + cx * 8]);
        }
        // B: pack W rows (2k2, 2k2+1) into half2; 16 k2 x 32 n4 chunks, 4/thread
#pragma unroll
        for (int it = 0; it < 4; it++) {
            int cidx = tid + it * 128;
            int k2 = cidx >> 5, n4 = cidx & 31;
            const float* w0 = &W[(size_t)(k0 + 2 * k2) * HD + ncol + n4 * 4];
            float4 r0 = *(const float4*)w0;
            float4 r1 = *(const float4*)(w0 + HD);
            uint4 pk;
            pk.x = packh2(r0.x, r1.x); pk.y = packh2(r0.y, r1.y);
            pk.z = packh2(r0.z, r1.z); pk.w = packh2(r0.w, r1.w);
            *(uint4*)&Bs[k2 * 136 + n4 * 4] = pk;
        }
        cp_async_wait_all();
        __syncthreads();
#pragma unroll
        for (int s = 0; s < 2; s++) {
            uint32_t a[2][4];
#pragma unroll
            for (int mt = 0; mt < 2; mt++) {
                int ar = mw0 + mt * 16 + lr;
                a[mt][0] = *(const uint32_t*)&As[ar * 40 + s * 16 + 2 * lc];
                a[mt][1] = *(const uint32_t*)&As[(ar + 8) * 40 + s * 16 + 2 * lc];
                a[mt][2] = *(const uint32_t*)&As[ar * 40 + s * 16 + 8 + 2 * lc];
                a[mt][3] = *(const uint32_t*)&As[(ar + 8) * 40 + s * 16 + 8 + 2 * lc];
            }
#pragma unroll
            for (int nt = 0; nt < 8; nt++) {
                int bn = nw0 + nt * 8 + lr;
                uint32_t b[2];
                b[0] = Bs[(s * 8 + lc) * 136 + bn];
                b[1] = Bs[(s * 8 + 4 + lc) * 136 + bn];
                mma_f16(acc[0][nt], a[0], b);
                mma_f16(acc[1][nt], a[1], b);
            }
        }
        __syncthreads();
    }

    const float scaleq = 0.14433756729740643f;
#pragma unroll
    for (int mt = 0; mt < 2; mt++) {
#pragma unroll
        for (int nt = 0; nt < 8; nt++) {
            int cc = ncol + nw0 + nt * 8 + 2 * lc;   // always even
#pragma unroll
            for (int half = 0; half < 2; half++) {
                int r = m0 + mw0 + mt * 16 + lr + half * 8;
                float v0 = acc[mt][nt][half * 2 + 0];
                float v1 = acc[mt][nt][half * 2 + 1];
                if (sel == 0) {
                    *(uint32_t*)&g_qh[r * HD + cc] = packh2(v0 * scaleq, v1 * scaleq);
                } else if (sel == 1) {
                    g_kp[(cc >> 1) * NTOK + r] = packh2(v0, v1);
                } else if (sel == 2) {
                    g_vh[cc * NTOK + r]       = __float2half_rn(v0);
                    g_vh[(cc + 1) * NTOK + r] = __float2half_rn(v1);
                } else {
                    float2 o2;
                    o2.x = 1.f / (1.f + __expf(-(v0 + bg[cc])));
                    o2.y = 1.f / (1.f + __expf(-(v1 + bg[cc + 1])));
                    *(float2*)&g_g[r * HD + cc] = o2;
                }
            }
        }
    }
}

// ===========================================================================
// Kernel 3: pair bias via tf32 mma + fused LN; bias written fp16. (R12)
// ===========================================================================
__global__ __launch_bounds__(128) void pairbias_kernel(const float* __restrict__ z)
{
    __shared__ __align__(16) float    ztf[64 * 132];
    __shared__ __align__(16) uint32_t wgt[NH * 144];
    __shared__ float Ssh[NH], Bcsh[NH], mus[64], rvs[64];

    int tid  = threadIdx.x;
    int lane = tid & 31;
    int warp = tid >> 5;
    int i  = blockIdx.y;
    int j0 = blockIdx.x * 64;

    {
        const uint4* src = (const uint4*)g_wgt;
        for (int t2 = tid; t2 < 576; t2 += 128)
            cp_async16(smem_u32((uint4*)wgt + t2), src + t2);
    }
    const float4* zb = (const float4*)(z + ((size_t)i * NTOK + j0) * CZ);
#pragma unroll
    for (int u = 0; u < 16; u++) {
        int idx = tid + 128 * u;
        int r = idx >> 5;
        cp_async16(smem_u32(&ztf[r * 132 + lane * 4]), zb + idx);
    }
    if (tid < NH) { Ssh[tid] = g_Svec[tid]; Bcsh[tid] = g_Bcvec[tid]; }
    cp_async_wait_all();
    __syncthreads();

    if (tid < 64) {
        float s = 0.f, sq = 0.f;
        const float* zr = &ztf[tid * 132];
#pragma unroll
        for (int cq = 0; cq < 32; cq++) {
            float4 w = *(const float4*)&zr[cq * 4];
            s += w.x + w.y + w.z + w.w;
            sq = fmaf(w.x, w.x, sq); sq = fmaf(w.y, w.y, sq);
            sq = fmaf(w.z, w.z, sq); sq = fmaf(w.w, w.w, sq);
        }
        float mu  = s * (1.f / (float)CZ);
        float var = sq * (1.f / (float)CZ) - mu * mu;
        mus[tid] = mu;
        rvs[tid] = rsqrtf(fmaxf(var, 0.f) + EPSV);
    }

    int m0 = warp * 16;
    int lr = lane >> 2, lc = lane & 3;
    float acc[2][4];
#pragma unroll
    for (int n = 0; n < 2; n++)
#pragma unroll
        for (int u = 0; u < 4; u++) acc[n][u] = 0.f;

    const uint32_t* wgt0 = &wgt[lr * 144 + lc * 36];
    const uint32_t* wgt1 = &wgt[(8 + lr) * 144 + lc * 36];
#pragma unroll
    for (int g = 0; g < 8; g++) {
        uint4 bq0 = *(const uint4*)(wgt0 + g * 4);
        uint4 bq1 = *(const uint4*)(wgt1 + g * 4);
#pragma unroll
        for (int kh = 0; kh < 2; kh++) {
            int kk = (g * 2 + kh) * 8;
            int ar = m0 + lr, ac = kk + lc;
            uint32_t a[4];
            a[0] = f2tf32(ztf[ar * 132 + ac]);
            a[1] = f2tf32(ztf[(ar + 8) * 132 + ac]);
            a[2] = f2tf32(ztf[ar * 132 + ac + 4]);
            a[3] = f2tf32(ztf[(ar + 8) * 132 + ac + 4]);
            uint32_t b0[2], b1[2];
            b0[0] = kh ? bq0.z : bq0.x;  b0[1] = kh ? bq0.w : bq0.y;
            b1[0] = kh ? bq1.z : bq1.x;  b1[1] = kh ? bq1.w : bq1.y;
            mma_tf32(acc[0], a, b0);
            mma_tf32(acc[1], a, b1);
        }
    }
    __syncthreads();

    float* outs = ztf;                    // [h][j], stride 68
#pragma unroll
    for (int n = 0; n < 2; n++) {
        int h0 = n * 8 + 2 * lc;
#pragma unroll
        for (int half = 0; half < 2; half++) {
            int r = m0 + lr + half * 8;
            float mu = mus[r], rv = rvs[r];
            outs[h0 * 68 + r]       = rv * (acc[n][half * 2 + 0] - mu * Ssh[h0])     + Bcsh[h0];
            outs[(h0 + 1) * 68 + r] = rv * (acc[n][half * 2 + 1] - mu * Ssh[h0 + 1]) + Bcsh[h0 + 1];
        }
    }
    __syncthreads();
    {
        int h = tid >> 3, j8 = (tid & 7) * 8;
        const float* src = &outs[h * 68 + j8];
        uint4 pk;
        pk.x = packh2(src[0], src[1]);
        pk.y = packh2(src[2], src[3]);
        pk.z = packh2(src[4], src[5]);
        pk.w = packh2(src[6], src[7]);
        *(uint4*)&g_biash[((size_t)h * NTOK + i) * NTOK + j0 + j8] = pk;
    }
}

// ===========================================================================
// Kernel 4: flash attention, all-fp16 tensor path. (R13, unchanged)
// ===========================================================================
__global__ __launch_bounds__(128) void attn_kernel(const float* __restrict__ mask)
{
    int h     = blockIdx.y;
    int qb    = blockIdx.x * 64;
    int split = blockIdx.z;
    int tid  = threadIdx.x;
    int lane = tid & 31;
    int warp = tid >> 5;
    int lr = lane >> 2, lc = lane & 3;
    int m0 = warp * 16;

    __shared__ __align__(16) __half   qs[64 * 56];
    __shared__ __align__(16) uint32_t ks2[24 * 72];
    __shared__ __align__(16) uint32_t vsh[48 * 36];

#pragma unroll
    for (int it = 0; it < 3; it++) {
        int u = tid + it * 128;
        int row = u / 6, cx = u % 6;
        cp_async16(smem_u32(&qs[row * 56 + cx * 8]),
                   &g_qh[(size_t)(qb + row) * HD + h * DH + cx * 8]);
    }

    float mrow0 = -1e30f, mrow1 = -1e30f, lrow0 = 0.f, lrow1 = 0.f;
    float oacc[6][4];
#pragma unroll
    for (int vt = 0; vt < 6; vt++)
#pragma unroll
        for (int u = 0; u < 4; u++) oacc[vt][u] = 0.f;

    float mq0 = mask[qb + m0 + lr];
    float mq1 = mask[qb + m0 + lr + 8];

    for (int jt = split * 4; jt < split * 4 + 4; jt++) {
        int j0 = jt * 64;
        __syncthreads();
#pragma unroll
        for (int it = 0; it < 3; it++) {
            int u = tid + it * 128;
            int row = u >> 4, cx = u & 15;
            cp_async16(smem_u32(&ks2[row * 72 + cx * 4]),
                       &g_kp[(size_t)(h * (DH / 2) + row) * NTOK + j0 + cx * 4]);
        }
#pragma unroll
        for (int it = 0; it < 3; it++) {
            int u = tid + it * 128;
            int row = u >> 3, cx = u & 7;
            cp_async16(smem_u32(&vsh[row * 36 + cx * 4]),
                       &g_vh[(size_t)(h * DH + row) * NTOK + j0 + cx * 8]);
        }
        cp_async_wait_all();
        __syncthreads();

        float sacc[8][4];
#pragma unroll
        for (int nt = 0; nt < 8; nt++)
#pragma unroll
            for (int u = 0; u < 4; u++) sacc[nt][u] = 0.f;
#pragma unroll
        for (int s = 0; s < 3; s++) {
            int ar = m0 + lr;
            uint32_t a[4];
            a[0] = *(const uint32_t*)&qs[ar * 56 + (s * 8 + lc) * 2];
            a[1] = *(const uint32_t*)&qs[(ar + 8) * 56 + (s * 8 + lc) * 2];
            a[2] = *(const uint32_t*)&qs[ar * 56 + (s * 8 + 4 + lc) * 2];
            a[3] = *(const uint32_t*)&qs[(ar + 8) * 56 + (s * 8 + 4 + lc) * 2];
#pragma unroll
            for (int nt = 0; nt < 8; nt++) {
                uint32_t b[2];
                b[0] = ks2[(s * 8 + lc) * 72 + nt * 8 + lr];
                b[1] = ks2[(s * 8 + 4 + lc) * 72 + nt * 8 + lr];
                mma_f16(sacc[nt], a, b);
            }
        }

        float rmax0 = -1e30f, rmax1 = -1e30f;
        const __half* bias0 = &g_biash[((size_t)h * NTOK + qb + m0 + lr) * NTOK];
        const __half* bias1 = &g_biash[((size_t)h * NTOK + qb + m0 + lr + 8) * NTOK];
#pragma unroll
        for (int nt = 0; nt < 8; nt++) {
            int jc = j0 + nt * 8 + 2 * lc;
            float2 b0 = __half22float2(*(const __half2*)&bias0[jc]);
            float2 b1 = __half22float2(*(const __half2*)&bias1[jc]);
            float mk0 = mask[jc], mk1 = mask[jc + 1];
            sacc[nt][0] += b0.x + INFV * (mq0 * mk0 - 1.f);
            sacc[nt][1] += b0.y + INFV * (mq0 * mk1 - 1.f);
            sacc[nt][2] += b1.x + INFV * (mq1 * mk0 - 1.f);
            sacc[nt][3] += b1.y + INFV * (mq1 * mk1 - 1.f);
            rmax0 = fmaxf(rmax0, fmaxf(sacc[nt][0], sacc[nt][1]));
            rmax1 = fmaxf(rmax1, fmaxf(sacc[nt][2], sacc[nt][3]));
        }
#pragma unroll
        for (int off = 1; off < 4; off <<= 1) {
            rmax0 = fmaxf(rmax0, __shfl_xor_sync(0xffffffffu, rmax0, off));
            rmax1 = fmaxf(rmax1, __shfl_xor_sync(0xffffffffu, rmax1, off));
        }
        float mnew0 = fmaxf(mrow0, rmax0);
        float mnew1 = fmaxf(mrow1, rmax1);
        float scale0 = __expf(mrow0 - mnew0);
        float scale1 = __expf(mrow1 - mnew1);

        float sum0 = 0.f, sum1 = 0.f;
        uint32_t ph[8][2];
#pragma unroll
        for (int nt = 0; nt < 8; nt++) {
            sacc[nt][0] = __expf(sacc[nt][0] - mnew0);
            sacc[nt][1] = __expf(sacc[nt][1] - mnew0);
            sacc[nt][2] = __expf(sacc[nt][2] - mnew1);
            sacc[nt][3] = __expf(sacc[nt][3] - mnew1);
            sum0 += sacc[nt][0] + sacc[nt][1];
            sum1 += sacc[nt][2] + sacc[nt][3];
            ph[nt][0] = packh2(sacc[nt][0], sacc[nt][1]);
            ph[nt][1] = packh2(sacc[nt][2], sacc[nt][3]);
        }
#pragma unroll
        for (int off = 1; off < 4; off <<= 1) {
            sum0 += __shfl_xor_sync(0xffffffffu, sum0, off);
            sum1 += __shfl_xor_sync(0xffffffffu, sum1, off);
        }
        lrow0 = lrow0 * scale0 + sum0;  mrow0 = mnew0;
        lrow1 = lrow1 * scale1 + sum1;  mrow1 = mnew1;
#pragma unroll
        for (int vt = 0; vt < 6; vt++) {
            oacc[vt][0] *= scale0; oacc[vt][1] *= scale0;
            oacc[vt][2] *= scale1; oacc[vt][3] *= scale1;
        }

#pragma unroll
        for (int ks4 = 0; ks4 < 4; ks4++) {
            uint32_t a[4];
            a[0] = ph[ks4 * 2][0];
            a[1] = ph[ks4 * 2][1];
            a[2] = ph[ks4 * 2 + 1][0];
            a[3] = ph[ks4 * 2 + 1][1];
#pragma unroll
            for (int vt = 0; vt < 6; vt++) {
                int d = vt * 8 + lr;
                uint32_t b[2];
                b[0] = vsh[d * 36 + ks4 * 8 + lc];
                b[1] = vsh[d * 36 + ks4 * 8 + 4 + lc];
                mma_f16(oacc[vt], a, b);
            }
        }
    }

    int q0 = qb + m0 + lr, q1 = q0 + 8;
    int pb0 = ((split * NH + h) * NTOK + q0) * DH;
    int pb1 = ((split * NH + h) * NTOK + q1) * DH;
#pragma unroll
    for (int vt = 0; vt < 6; vt++) {
        int d = vt * 8 + 2 * lc;
        *(float2*)&g_po[pb0 + d] = make_float2(oacc[vt][0], oacc[vt][1]);
        *(float2*)&g_po[pb1 + d] = make_float2(oacc[vt][2], oacc[vt][3]);
    }
    if (lc == 0) {
        g_pm[(split * NH + h) * NTOK + q0] = mrow0;
        g_pl[(split * NH + h) * NTOK + q0] = lrow0;
        g_pm[(split * NH + h) * NTOK + q1] = mrow1;
        g_pl[(split * NH + h) * NTOK + q1] = lrow1;
    }
}

// ===========================================================================
// Kernel 4b: merge 4 splits, normalize, apply gate -> g_ogh (fp16).
// ===========================================================================
__global__ __launch_bounds__(256) void merge_kernel()
{
    int q = blockIdx.x;
    int t = threadIdx.x;
    int h = t >> 4;
    int d0 = (t & 15) * 3;

    float m[NSPLIT], l[NSPLIT];
    float M = -1e30f;
#pragma unroll
    for (int s = 0; s < NSPLIT; s++) {
        m[s] = g_pm[(s * NH + h) * NTOK + q];
        l[s] = g_pl[(s * NH + h) * NTOK + q];
        M = fmaxf(M, m[s]);
    }
    float w[NSPLIT], ltot = 0.f;
#pragma unroll
    for (int s = 0; s < NSPLIT; s++) {
        w[s] = __expf(m[s] - M);
        ltot += l[s] * w[s];
    }
    float inv = 1.f / ltot;
    int go = q * HD + h * DH + d0;
#pragma unroll
    for (int u = 0; u < 3; u++) {
        float val = 0.f;
#pragma unroll
        for (int s = 0; s < NSPLIT; s++)
            val += g_po[((s * NH + h) * NTOK + q) * DH + d0 + u] * w[s];
        g_ogh[go + u] = __float2half_rn(val * inv * g_g[go + u]);
    }
}

// ===========================================================================
// Kernel 5: output projection via fp16 m16n8k16. BM=64, BN=64, BK=32.
// A staged raw from fp16 g_ogh via cp.async; B packed to half2 at staging.
// ===========================================================================
__global__ __launch_bounds__(128) void outproj_kernel(const float* __restrict__ W,
                                                      const float* __restrict__ bo,
                                                      float* __restrict__ out)
{
    int n0 = blockIdx.x * 64;
    int m0 = blockIdx.y * 64;

    __shared__ __align__(16) __half   As[64 * 40];   // fp16 [m][k], stride 40
    __shared__ __align__(16) uint32_t Bs[16 * 72];   // half2 k-pairs [k2][n]

    int tid  = threadIdx.x;
    int lane = tid & 31;
    int warp = tid >> 5;
    int wm = warp >> 1, wn = warp & 1;
    int mw0 = wm * 32, nw0 = wn * 32;
    int lr = lane >> 2, lc = lane & 3;

    float acc[2][4][4];
#pragma unroll
    for (int mt = 0; mt < 2; mt++)
#pragma unroll
        for (int nt = 0; nt < 4; nt++)
#pragma unroll
            for (int u = 0; u < 4; u++) acc[mt][nt][u] = 0.f;

    for (int k0 = 0; k0 < HD; k0 += 32) {
#pragma unroll
        for (int it = 0; it < 2; it++) {
            int u = tid + it * 128;
            int r = u >> 2, cx = u & 3;
            cp_async16(smem_u32(&As[r * 40 + cx * 8]),
                       &g_ogh[(size_t)(m0 + r) * HD + k0 + cx * 8]);
        }
        // B: 16 k2 x 16 n4 chunks; 2 per thread
#pragma unroll
        for (int it = 0; it < 2; it++) {
            int cidx = tid + it * 128;
            int k2 = cidx >> 4, n4 = cidx & 15;
            const float* w0 = &W[(size_t)(k0 + 2 * k2) * CQ + n0 + n4 * 4];
            float4 r0 = *(const float4*)w0;
            float4 r1 = *(const float4*)(w0 + CQ);
            uint4 pk;
            pk.x = packh2(r0.x, r1.x); pk.y = packh2(r0.y, r1.y);
            pk.z = packh2(r0.z, r1.z); pk.w = packh2(r0.w, r1.w);
            *(uint4*)&Bs[k2 * 72 + n4 * 4] = pk;
        }
        cp_async_wait_all();
        __syncthreads();
#pragma unroll
        for (int s = 0; s < 2; s++) {
            uint32_t a[2][4];
#pragma unroll
            for (int mt = 0; mt < 2; mt++) {
                int ar = mw0 + mt * 16 + lr;
                a[mt][0] = *(const uint32_t*)&As[ar * 40 + s * 16 + 2 * lc];
                a[mt][1] = *(const uint32_t*)&As[(ar + 8) * 40 + s * 16 + 2 * lc];
                a[mt][2] = *(const uint32_t*)&As[ar * 40 + s * 16 + 8 + 2 * lc];
                a[mt][3] = *(const uint32_t*)&As[(ar + 8) * 40 + s * 16 + 8 + 2 * lc];
            }
#pragma unroll
            for (int nt = 0; nt < 4; nt++) {
                int bn = nw0 + nt * 8 + lr;
                uint32_t b[2];
                b[0] = Bs[(s * 8 + lc) * 72 + bn];
                b[1] = Bs[(s * 8 + 4 + lc) * 72 + bn];
                mma_f16(acc[0][nt], a[0], b);
                mma_f16(acc[1][nt], a[1], b);
            }
        }
        __syncthreads();
    }

#pragma unroll
    for (int mt = 0; mt < 2; mt++) {
#pragma unroll
        for (int nt = 0; nt < 4; nt++) {
            int cc = n0 + nw0 + nt * 8 + 2 * lc;
            float b0 = bo[cc], b1 = bo[cc + 1];
#pragma unroll
            for (int half = 0; half < 2; half++) {
                int r = m0 + mw0 + mt * 16 + lr + half * 8;
                float2 o2;
                o2.x = acc[mt][nt][half * 2 + 0] + b0;
                o2.y = acc[mt][nt][half * 2 + 1] + b1;
                *(float2*)&out[r * CQ + cc] = o2;
            }
        }
    }
}

// ===========================================================================
extern "C" void kernel_launch(void* const* d_in, const int* in_sizes, int n_in,
                              void* d_out, int out_size)
{
    const float* a    = (const float*)d_in[0];
    const float* z    = (const float*)d_in[1];
    const float* mask = (const float*)d_in[2];
    const float* g_a  = (const float*)d_in[3];
    const float* b_a  = (const float*)d_in[4];
    const float* g_z  = (const float*)d_in[5];
    const float* b_z  = (const float*)d_in[6];
    const float* w_z  = (const float*)d_in[7];
    const float* w_q  = (const float*)d_in[8];
    const float* w_k  = (const float*)d_in[9];
    const float* w_v  = (const float*)d_in[10];
    const float* w_g  = (const float*)d_in[11];
    const float* b_g  = (const float*)d_in[12];
    const float* w_o  = (const float*)d_in[13];
    const float* b_o  = (const float*)d_in[14];
    float* out = (float*)d_out;

    ln_a_kernel<<<NTOK + 1, 256>>>(a, g_a, b_a, g_z, b_z, w_z);
    proj_kernel<<<dim3(24, 16), 128>>>(w_q, w_k, w_v, w_g, b_g);
    pairbias_kernel<<<dim3(16, NTOK), 128>>>(z);
    attn_kernel<<<dim3(16, NH, NSPLIT), 128>>>(mask);
    merge_kernel<<<NTOK, 256>>>();
    outproj_kernel<<<dim3(12, 16), 128>>>(w_o, b_o, out);
}

// round 16
// speedup vs baseline: 4.3044x; 1.0549x over previous
#include <cuda_runtime.h>
#include <cuda_fp16.h>
#include <math.h>
#include <stdint.h>

#define NTOK 1024
#define CQ   768
#define CZ   128
#define NH   16
#define DH   48
#define HD   768
#define EPSV 1e-5f
#define INFV 1.0e9f
#define NSPLIT 4
#define PROJ_BLOCKS 384          // 24 n-tiles x 16 m-tiles

// ------------- static device scratch (no allocations allowed) -------------
__device__ __align__(16) __half   g_anh[NTOK * CQ];      // fp16 LN(a)
__device__ __align__(16) __half   g_qh[NTOK * HD];       // fp16 Q (scaled)
__device__ __align__(16) uint32_t g_kp[(HD / 2) * NTOK]; // half2 K (d,d+1) [d2][tok]
__device__ __align__(16) __half   g_vh[HD * NTOK];       // fp16 V^T [h*DH+d][tok]
__device__ float g_g [NTOK * HD];
__device__ __align__(16) __half   g_ogh[NTOK * HD];      // fp16 gated attn out
__device__ __align__(16) __half g_biash[(size_t)NH * NTOK * NTOK];  // 32 MB
__device__ float g_po[NSPLIT * NH * NTOK * DH];
__device__ float g_pm[NSPLIT * NH * NTOK];
__device__ float g_pl[NSPLIT * NH * NTOK];
__device__ __align__(16) uint32_t g_wgt[NH * 144];  // tf32 wg, fragment-quad
__device__ float g_Svec[NH], g_Bcvec[NH];

// ------------------------- mma helpers -------------------------------
__device__ __forceinline__ uint32_t f2tf32(float f) {
    uint32_t r;
    asm("cvt.rna.tf32.f32 %0, %1;" : "=r"(r) : "f"(f));
    return r;
}
__device__ __forceinline__ void mma_tf32(float* d, const uint32_t* a, const uint32_t* b) {
    asm("mma.sync.aligned.m16n8k8.row.col.f32.tf32.tf32.f32 "
        "{%0,%1,%2,%3}, {%4,%5,%6,%7}, {%8,%9}, {%0,%1,%2,%3};"
        : "+f"(d[0]), "+f"(d[1]), "+f"(d[2]), "+f"(d[3])
        : "r"(a[0]), "r"(a[1]), "r"(a[2]), "r"(a[3]), "r"(b[0]), "r"(b[1]));
}
__device__ __forceinline__ void mma_f16(float* d, const uint32_t* a, const uint32_t* b) {
    asm("mma.sync.aligned.m16n8k16.row.col.f32.f16.f16.f32 "
        "{%0,%1,%2,%3}, {%4,%5,%6,%7}, {%8,%9}, {%0,%1,%2,%3};"
        : "+f"(d[0]), "+f"(d[1]), "+f"(d[2]), "+f"(d[3])
        : "r"(a[0]), "r"(a[1]), "r"(a[2]), "r"(a[3]), "r"(b[0]), "r"(b[1]));
}
__device__ __forceinline__ uint32_t packh2(float lo, float hi) {
    __half2 h = __floats2half2_rn(lo, hi);
    return *(uint32_t*)&h;
}
__device__ __forceinline__ uint32_t smem_u32(const void* p) {
    uint32_t r;
    asm("{.reg .u64 t; cvta.to.shared.u64 t, %1; cvt.u32.u64 %0, t;}" : "=r"(r) : "l"(p));
    return r;
}
__device__ __forceinline__ void cp_async16(uint32_t dst, const void* src) {
    asm volatile("cp.async.cg.shared.global [%0], [%1], 16;" :: "r"(dst), "l"(src));
}
__device__ __forceinline__ void cp_async_wait_all() {
    asm volatile("cp.async.commit_group;\n cp.async.wait_group 0;" ::: "memory");
}

// ===========================================================================
// Kernel 1: LayerNorm(a) -> g_anh fp16 (blocks 0..1023); block 1024 = setup.
// ===========================================================================
__global__ __launch_bounds__(256) void ln_a_kernel(const float* __restrict__ a,
                                                   const float* __restrict__ ga,
                                                   const float* __restrict__ ba,
                                                   const float* __restrict__ gz,
                                                   const float* __restrict__ bz,
                                                   const float* __restrict__ wz)
{
    int row = blockIdx.x;
    int tid = threadIdx.x;
    if (row == NTOK) {
        for (int i = tid; i < NH * 144; i += 256) g_wgt[i] = 0u;
        __syncthreads();
        for (int i = tid; i < NH * CZ; i += 256) {
            int h = i >> 7, c = i & 127;
            int g = c >> 4, rem = c & 15;
            int lc = rem & 3, w = rem >> 2;
            g_wgt[h * 144 + lc * 36 + g * 4 + w] = f2tf32(gz[c] * wz[c * NH + h]);
        }
        if (tid < NH) {
            float S = 0.f, Bc = 0.f;
            for (int c = 0; c < CZ; c++) {
                S  += gz[c] * wz[c * NH + tid];
                Bc += bz[c] * wz[c * NH + tid];
            }
            g_Svec[tid] = S; g_Bcvec[tid] = Bc;
        }
        return;
    }
    const float* x = a + row * CQ;
    float v0 = x[tid], v1 = x[tid + 256], v2 = x[tid + 512];
    float s = v0 + v1 + v2;
    float q = v0 * v0 + v1 * v1 + v2 * v2;
#pragma unroll
    for (int o = 16; o > 0; o >>= 1) {
        s += __shfl_xor_sync(0xffffffffu, s, o);
        q += __shfl_xor_sync(0xffffffffu, q, o);
    }
    __shared__ float sw[8], qw[8];
    __shared__ float smu, srv;
    if ((tid & 31) == 0) { sw[tid >> 5] = s; qw[tid >> 5] = q; }
    __syncthreads();
    if (tid == 0) {
        float S = 0.f, Q = 0.f;
#pragma unroll
        for (int w = 0; w < 8; w++) { S += sw[w]; Q += qw[w]; }
        float mu = S * (1.f / (float)CQ);
        float var = Q * (1.f / (float)CQ) - mu * mu;
        smu = mu;
        srv = rsqrtf(fmaxf(var, 0.f) + EPSV);
    }
    __syncthreads();
    float mu = smu, r = srv;
    __half* o = g_anh + row * CQ;
    o[tid]       = __float2half_rn((v0 - mu) * r * ga[tid]       + ba[tid]);
    o[tid + 256] = __float2half_rn((v1 - mu) * r * ga[tid + 256] + ba[tid + 256]);
    o[tid + 512] = __float2half_rn((v2 - mu) * r * ga[tid + 512] + ba[tid + 512]);
}

// ===========================================================================
// Proj body (fp16 m16n8k16, BM=64, BN=128, BK=32). Shared mem carved from raw.
// ===========================================================================
__device__ __forceinline__ void proj_body(unsigned char* smem_raw, int bx,
                                          const float* __restrict__ Wq,
                                          const float* __restrict__ Wk,
                                          const float* __restrict__ Wv,
                                          const float* __restrict__ Wg,
                                          const float* __restrict__ bg)
{
    __half*   As = (__half*)smem_raw;                  // 64*40 fp16 = 5120 B
    uint32_t* Bs = (uint32_t*)(smem_raw + 5120);       // 16*136 u32 = 8704 B

    int n0 = (bx % 24) * 128;
    int m0 = (bx / 24) * 64;
    int sel  = n0 / HD;
    int ncol = n0 - sel * HD;
    const float* W = (sel == 0) ? Wq : (sel == 1) ? Wk : (sel == 2) ? Wv : Wg;

    int tid  = threadIdx.x;
    int lane = tid & 31;
    int warp = tid >> 5;
    int wm = warp >> 1, wn = warp & 1;
    int mw0 = wm * 32, nw0 = wn * 64;
    int lr = lane >> 2, lc = lane & 3;

    float acc[2][8][4];
#pragma unroll
    for (int mt = 0; mt < 2; mt++)
#pragma unroll
        for (int nt = 0; nt < 8; nt++)
#pragma unroll
            for (int u = 0; u < 4; u++) acc[mt][nt][u] = 0.f;

    for (int k0 = 0; k0 < CQ; k0 += 32) {
#pragma unroll
        for (int it = 0; it < 2; it++) {
            int u = tid + it * 128;
            int r = u >> 2, cx = u & 3;
            cp_async16(smem_u32(&As[r * 40 + cx * 8]),
                       &g_anh[(size_t)(m0 + r) * CQ + k0 + cx * 8]);
        }
#pragma unroll
        for (int it = 0; it < 4; it++) {
            int cidx = tid + it * 128;
            int k2 = cidx >> 5, n4 = cidx & 31;
            const float* w0 = &W[(size_t)(k0 + 2 * k2) * HD + ncol + n4 * 4];
            float4 r0 = *(const float4*)w0;
            float4 r1 = *(const float4*)(w0 + HD);
            uint4 pk;
            pk.x = packh2(r0.x, r1.x); pk.y = packh2(r0.y, r1.y);
            pk.z = packh2(r0.z, r1.z); pk.w = packh2(r0.w, r1.w);
            *(uint4*)&Bs[k2 * 136 + n4 * 4] = pk;
        }
        cp_async_wait_all();
        __syncthreads();
#pragma unroll
        for (int s = 0; s < 2; s++) {
            uint32_t a[2][4];
#pragma unroll
            for (int mt = 0; mt < 2; mt++) {
                int ar = mw0 + mt * 16 + lr;
                a[mt][0] = *(const uint32_t*)&As[ar * 40 + s * 16 + 2 * lc];
                a[mt][1] = *(const uint32_t*)&As[(ar + 8) * 40 + s * 16 + 2 * lc];
                a[mt][2] = *(const uint32_t*)&As[ar * 40 + s * 16 + 8 + 2 * lc];
                a[mt][3] = *(const uint32_t*)&As[(ar + 8) * 40 + s * 16 + 8 + 2 * lc];
            }
#pragma unroll
            for (int nt = 0; nt < 8; nt++) {
                int bn = nw0 + nt * 8 + lr;
                uint32_t b[2];
                b[0] = Bs[(s * 8 + lc) * 136 + bn];
                b[1] = Bs[(s * 8 + 4 + lc) * 136 + bn];
                mma_f16(acc[0][nt], a[0], b);
                mma_f16(acc[1][nt], a[1], b);
            }
        }
        __syncthreads();
    }

    const float scaleq = 0.14433756729740643f;
#pragma unroll
    for (int mt = 0; mt < 2; mt++) {
#pragma unroll
        for (int nt = 0; nt < 8; nt++) {
            int cc = ncol + nw0 + nt * 8 + 2 * lc;
#pragma unroll
            for (int half = 0; half < 2; half++) {
                int r = m0 + mw0 + mt * 16 + lr + half * 8;
                float v0 = acc[mt][nt][half * 2 + 0];
                float v1 = acc[mt][nt][half * 2 + 1];
                if (sel == 0) {
                    *(uint32_t*)&g_qh[r * HD + cc] = packh2(v0 * scaleq, v1 * scaleq);
                } else if (sel == 1) {
                    g_kp[(cc >> 1) * NTOK + r] = packh2(v0, v1);
                } else if (sel == 2) {
                    g_vh[cc * NTOK + r]       = __float2half_rn(v0);
                    g_vh[(cc + 1) * NTOK + r] = __float2half_rn(v1);
                } else {
                    float2 o2;
                    o2.x = 1.f / (1.f + __expf(-(v0 + bg[cc])));
                    o2.y = 1.f / (1.f + __expf(-(v1 + bg[cc + 1])));
                    *(float2*)&g_g[r * HD + cc] = o2;
                }
            }
        }
    }
}

// ===========================================================================
// Pairbias body (tf32 mma + fused LN, fp16 bias out). Shared carved from raw.
// ===========================================================================
__device__ __forceinline__ void pairbias_body(unsigned char* smem_raw, int idx,
                                              const float* __restrict__ z)
{
    float*    ztf = (float*)smem_raw;                   // 64*132 f32 = 33792 B
    uint32_t* wgt = (uint32_t*)(smem_raw + 33792);      // 2304 u32  =  9216 B
    float*    Ssh = (float*)(smem_raw + 43008);         // 16
    float*    Bcsh= (float*)(smem_raw + 43072);         // 16
    float*    mus = (float*)(smem_raw + 43136);         // 64
    float*    rvs = (float*)(smem_raw + 43392);         // 64

    int tid  = threadIdx.x;
    int lane = tid & 31;
    int warp = tid >> 5;
    int i  = idx >> 4;
    int j0 = (idx & 15) * 64;

    {
        const uint4* src = (const uint4*)g_wgt;
        for (int t2 = tid; t2 < 576; t2 += 128)
            cp_async16(smem_u32((uint4*)wgt + t2), src + t2);
    }
    const float4* zb = (const float4*)(z + ((size_t)i * NTOK + j0) * CZ);
#pragma unroll
    for (int u = 0; u < 16; u++) {
        int iidx = tid + 128 * u;
        int r = iidx >> 5;
        cp_async16(smem_u32(&ztf[r * 132 + lane * 4]), zb + iidx);
    }
    if (tid < NH) { Ssh[tid] = g_Svec[tid]; Bcsh[tid] = g_Bcvec[tid]; }
    cp_async_wait_all();
    __syncthreads();

    if (tid < 64) {
        float s = 0.f, sq = 0.f;
        const float* zr = &ztf[tid * 132];
#pragma unroll
        for (int cq = 0; cq < 32; cq++) {
            float4 w = *(const float4*)&zr[cq * 4];
            s += w.x + w.y + w.z + w.w;
            sq = fmaf(w.x, w.x, sq); sq = fmaf(w.y, w.y, sq);
            sq = fmaf(w.z, w.z, sq); sq = fmaf(w.w, w.w, sq);
        }
        float mu  = s * (1.f / (float)CZ);
        float var = sq * (1.f / (float)CZ) - mu * mu;
        mus[tid] = mu;
        rvs[tid] = rsqrtf(fmaxf(var, 0.f) + EPSV);
    }

    int m0 = warp * 16;
    int lr = lane >> 2, lc = lane & 3;
    float acc[2][4];
#pragma unroll
    for (int n = 0; n < 2; n++)
#pragma unroll
        for (int u = 0; u < 4; u++) acc[n][u] = 0.f;

    const uint32_t* wgt0 = &wgt[lr * 144 + lc * 36];
    const uint32_t* wgt1 = &wgt[(8 + lr) * 144 + lc * 36];
#pragma unroll
    for (int g = 0; g < 8; g++) {
        uint4 bq0 = *(const uint4*)(wgt0 + g * 4);
        uint4 bq1 = *(const uint4*)(wgt1 + g * 4);
#pragma unroll
        for (int kh = 0; kh < 2; kh++) {
            int kk = (g * 2 + kh) * 8;
            int ar = m0 + lr, ac = kk + lc;
            uint32_t a[4];
            a[0] = f2tf32(ztf[ar * 132 + ac]);
            a[1] = f2tf32(ztf[(ar + 8) * 132 + ac]);
            a[2] = f2tf32(ztf[ar * 132 + ac + 4]);
            a[3] = f2tf32(ztf[(ar + 8) * 132 + ac + 4]);
            uint32_t b0[2], b1[2];
            b0[0] = kh ? bq0.z : bq0.x;  b0[1] = kh ? bq0.w : bq0.y;
            b1[0] = kh ? bq1.z : bq1.x;  b1[1] = kh ? bq1.w : bq1.y;
            mma_tf32(acc[0], a, b0);
            mma_tf32(acc[1], a, b1);
        }
    }
    __syncthreads();

    float* outs = ztf;                    // [h][j], stride 68
#pragma unroll
    for (int n = 0; n < 2; n++) {
        int h0 = n * 8 + 2 * lc;
#pragma unroll
        for (int half = 0; half < 2; half++) {
            int r = m0 + lr + half * 8;
            float mu = mus[r], rv = rvs[r];
            outs[h0 * 68 + r]       = rv * (acc[n][half * 2 + 0] - mu * Ssh[h0])     + Bcsh[h0];
            outs[(h0 + 1) * 68 + r] = rv * (acc[n][half * 2 + 1] - mu * Ssh[h0 + 1]) + Bcsh[h0 + 1];
        }
    }
    __syncthreads();
    {
        int h = tid >> 3, j8 = (tid & 7) * 8;
        const float* src = &outs[h * 68 + j8];
        uint4 pk;
        pk.x = packh2(src[0], src[1]);
        pk.y = packh2(src[2], src[3]);
        pk.z = packh2(src[4], src[5]);
        pk.w = packh2(src[6], src[7]);
        *(uint4*)&g_biash[((size_t)h * NTOK + i) * NTOK + j0 + j8] = pk;
    }
}

// ===========================================================================
// Kernel 2+3 fused: blocks [0, 384) run proj, [384, 16768) run pairbias.
// Independent work; the DRAM-bound pairbias blocks absorb proj's compute.
// ===========================================================================
__global__ __launch_bounds__(128) void fused_pp_kernel(const float* __restrict__ z,
                                                       const float* __restrict__ Wq,
                                                       const float* __restrict__ Wk,
                                                       const float* __restrict__ Wv,
                                                       const float* __restrict__ Wg,
                                                       const float* __restrict__ bg)
{
    __shared__ __align__(16) unsigned char smem_raw[43648];
    int bx = blockIdx.x;
    if (bx < PROJ_BLOCKS) {
        proj_body(smem_raw, bx, Wq, Wk, Wv, Wg, bg);
    } else {
        pairbias_body(smem_raw, bx - PROJ_BLOCKS, z);
    }
}

// ===========================================================================
// Kernel 4: flash attention, all-fp16 tensor path. (R13, unchanged)
// ===========================================================================
__global__ __launch_bounds__(128) void attn_kernel(const float* __restrict__ mask)
{
    int h     = blockIdx.y;
    int qb    = blockIdx.x * 64;
    int split = blockIdx.z;
    int tid  = threadIdx.x;
    int lane = tid & 31;
    int warp = tid >> 5;
    int lr = lane >> 2, lc = lane & 3;
    int m0 = warp * 16;

    __shared__ __align__(16) __half   qs[64 * 56];
    __shared__ __align__(16) uint32_t ks2[24 * 72];
    __shared__ __align__(16) uint32_t vsh[48 * 36];

#pragma unroll
    for (int it = 0; it < 3; it++) {
        int u = tid + it * 128;
        int row = u / 6, cx = u % 6;
        cp_async16(smem_u32(&qs[row * 56 + cx * 8]),
                   &g_qh[(size_t)(qb + row) * HD + h * DH + cx * 8]);
    }

    float mrow0 = -1e30f, mrow1 = -1e30f, lrow0 = 0.f, lrow1 = 0.f;
    float oacc[6][4];
#pragma unroll
    for (int vt = 0; vt < 6; vt++)
#pragma unroll
        for (int u = 0; u < 4; u++) oacc[vt][u] = 0.f;

    float mq0 = mask[qb + m0 + lr];
    float mq1 = mask[qb + m0 + lr + 8];

    for (int jt = split * 4; jt < split * 4 + 4; jt++) {
        int j0 = jt * 64;
        __syncthreads();
#pragma unroll
        for (int it = 0; it < 3; it++) {
            int u = tid + it * 128;
            int row = u >> 4, cx = u & 15;
            cp_async16(smem_u32(&ks2[row * 72 + cx * 4]),
                       &g_kp[(size_t)(h * (DH / 2) + row) * NTOK + j0 + cx * 4]);
        }
#pragma unroll
        for (int it = 0; it < 3; it++) {
            int u = tid + it * 128;
            int row = u >> 3, cx = u & 7;
            cp_async16(smem_u32(&vsh[row * 36 + cx * 4]),
                       &g_vh[(size_t)(h * DH + row) * NTOK + j0 + cx * 8]);
        }
        cp_async_wait_all();
        __syncthreads();

        float sacc[8][4];
#pragma unroll
        for (int nt = 0; nt < 8; nt++)
#pragma unroll
            for (int u = 0; u < 4; u++) sacc[nt][u] = 0.f;
#pragma unroll
        for (int s = 0; s < 3; s++) {
            int ar = m0 + lr;
            uint32_t a[4];
            a[0] = *(const uint32_t*)&qs[ar * 56 + (s * 8 + lc) * 2];
            a[1] = *(const uint32_t*)&qs[(ar + 8) * 56 + (s * 8 + lc) * 2];
            a[2] = *(const uint32_t*)&qs[ar * 56 + (s * 8 + 4 + lc) * 2];
            a[3] = *(const uint32_t*)&qs[(ar + 8) * 56 + (s * 8 + 4 + lc) * 2];
#pragma unroll
            for (int nt = 0; nt < 8; nt++) {
                uint32_t b[2];
                b[0] = ks2[(s * 8 + lc) * 72 + nt * 8 + lr];
                b[1] = ks2[(s * 8 + 4 + lc) * 72 + nt * 8 + lr];
                mma_f16(sacc[nt], a, b);
            }
        }

        float rmax0 = -1e30f, rmax1 = -1e30f;
        const __half* bias0 = &g_biash[((size_t)h * NTOK + qb + m0 + lr) * NTOK];
        const __half* bias1 = &g_biash[((size_t)h * NTOK + qb + m0 + lr + 8) * NTOK];
#pragma unroll
        for (int nt = 0; nt < 8; nt++) {
            int jc = j0 + nt * 8 + 2 * lc;
            float2 b0 = __half22float2(*(const __half2*)&bias0[jc]);
            float2 b1 = __half22float2(*(const __half2*)&bias1[jc]);
            float mk0 = mask[jc], mk1 = mask[jc + 1];
            sacc[nt][0] += b0.x + INFV * (mq0 * mk0 - 1.f);
            sacc[nt][1] += b0.y + INFV * (mq0 * mk1 - 1.f);
            sacc[nt][2] += b1.x + INFV * (mq1 * mk0 - 1.f);
            sacc[nt][3] += b1.y + INFV * (mq1 * mk1 - 1.f);
            rmax0 = fmaxf(rmax0, fmaxf(sacc[nt][0], sacc[nt][1]));
            rmax1 = fmaxf(rmax1, fmaxf(sacc[nt][2], sacc[nt][3]));
        }
#pragma unroll
        for (int off = 1; off < 4; off <<= 1) {
            rmax0 = fmaxf(rmax0, __shfl_xor_sync(0xffffffffu, rmax0, off));
            rmax1 = fmaxf(rmax1, __shfl_xor_sync(0xffffffffu, rmax1, off));
        }
        float mnew0 = fmaxf(mrow0, rmax0);
        float mnew1 = fmaxf(mrow1, rmax1);
        float scale0 = __expf(mrow0 - mnew0);
        float scale1 = __expf(mrow1 - mnew1);

        float sum0 = 0.f, sum1 = 0.f;
        uint32_t ph[8][2];
#pragma unroll
        for (int nt = 0; nt < 8; nt++) {
            sacc[nt][0] = __expf(sacc[nt][0] - mnew0);
            sacc[nt][1] = __expf(sacc[nt][1] - mnew0);
            sacc[nt][2] = __expf(sacc[nt][2] - mnew1);
            sacc[nt][3] = __expf(sacc[nt][3] - mnew1);
            sum0 += sacc[nt][0] + sacc[nt][1];
            sum1 += sacc[nt][2] + sacc[nt][3];
            ph[nt][0] = packh2(sacc[nt][0], sacc[nt][1]);
            ph[nt][1] = packh2(sacc[nt][2], sacc[nt][3]);
        }
#pragma unroll
        for (int off = 1; off < 4; off <<= 1) {
            sum0 += __shfl_xor_sync(0xffffffffu, sum0, off);
            sum1 += __shfl_xor_sync(0xffffffffu, sum1, off);
        }
        lrow0 = lrow0 * scale0 + sum0;  mrow0 = mnew0;
        lrow1 = lrow1 * scale1 + sum1;  mrow1 = mnew1;
#pragma unroll
        for (int vt = 0; vt < 6; vt++) {
            oacc[vt][0] *= scale0; oacc[vt][1] *= scale0;
            oacc[vt][2] *= scale1; oacc[vt][3] *= scale1;
        }

#pragma unroll
        for (int ks4 = 0; ks4 < 4; ks4++) {
            uint32_t a[4];
            a[0] = ph[ks4 * 2][0];
            a[1] = ph[ks4 * 2][1];
            a[2] = ph[ks4 * 2 + 1][0];
            a[3] = ph[ks4 * 2 + 1][1];
#pragma unroll
            for (int vt = 0; vt < 6; vt++) {
                int d = vt * 8 + lr;
                uint32_t b[2];
                b[0] = vsh[d * 36 + ks4 * 8 + lc];
                b[1] = vsh[d * 36 + ks4 * 8 + 4 + lc];
                mma_f16(oacc[vt], a, b);
            }
        }
    }

    int q0 = qb + m0 + lr, q1 = q0 + 8;
    int pb0 = ((split * NH + h) * NTOK + q0) * DH;
    int pb1 = ((split * NH + h) * NTOK + q1) * DH;
#pragma unroll
    for (int vt = 0; vt < 6; vt++) {
        int d = vt * 8 + 2 * lc;
        *(float2*)&g_po[pb0 + d] = make_float2(oacc[vt][0], oacc[vt][1]);
        *(float2*)&g_po[pb1 + d] = make_float2(oacc[vt][2], oacc[vt][3]);
    }
    if (lc == 0) {
        g_pm[(split * NH + h) * NTOK + q0] = mrow0;
        g_pl[(split * NH + h) * NTOK + q0] = lrow0;
        g_pm[(split * NH + h) * NTOK + q1] = mrow1;
        g_pl[(split * NH + h) * NTOK + q1] = lrow1;
    }
}

// ===========================================================================
// Kernel 4b: merge 4 splits, normalize, apply gate -> g_ogh (fp16).
// ===========================================================================
__global__ __launch_bounds__(256) void merge_kernel()
{
    int q = blockIdx.x;
    int t = threadIdx.x;
    int h = t >> 4;
    int d0 = (t & 15) * 3;

    float m[NSPLIT], l[NSPLIT];
    float M = -1e30f;
#pragma unroll
    for (int s = 0; s < NSPLIT; s++) {
        m[s] = g_pm[(s * NH + h) * NTOK + q];
        l[s] = g_pl[(s * NH + h) * NTOK + q];
        M = fmaxf(M, m[s]);
    }
    float w[NSPLIT], ltot = 0.f;
#pragma unroll
    for (int s = 0; s < NSPLIT; s++) {
        w[s] = __expf(m[s] - M);
        ltot += l[s] * w[s];
    }
    float inv = 1.f / ltot;
    int go = q * HD + h * DH + d0;
#pragma unroll
    for (int u = 0; u < 3; u++) {
        float val = 0.f;
#pragma unroll
        for (int s = 0; s < NSPLIT; s++)
            val += g_po[((s * NH + h) * NTOK + q) * DH + d0 + u] * w[s];
        g_ogh[go + u] = __float2half_rn(val * inv * g_g[go + u]);
    }
}

// ===========================================================================
// Kernel 5: output projection via fp16 m16n8k16. BM=64, BN=64, BK=32. (R14)
// ===========================================================================
__global__ __launch_bounds__(128) void outproj_kernel(const float* __restrict__ W,
                                                      const float* __restrict__ bo,
                                                      float* __restrict__ out)
{
    int n0 = blockIdx.x * 64;
    int m0 = blockIdx.y * 64;

    __shared__ __align__(16) __half   As[64 * 40];
    __shared__ __align__(16) uint32_t Bs[16 * 72];

    int tid  = threadIdx.x;
    int lane = tid & 31;
    int warp = tid >> 5;
    int wm = warp >> 1, wn = warp & 1;
    int mw0 = wm * 32, nw0 = wn * 32;
    int lr = lane >> 2, lc = lane & 3;

    float acc[2][4][4];
#pragma unroll
    for (int mt = 0; mt < 2; mt++)
#pragma unroll
        for (int nt = 0; nt < 4; nt++)
#pragma unroll
            for (int u = 0; u < 4; u++) acc[mt][nt][u] = 0.f;

    for (int k0 = 0; k0 < HD; k0 += 32) {
#pragma unroll
        for (int it = 0; it < 2; it++) {
            int u = tid + it * 128;
            int r = u >> 2, cx = u & 3;
            cp_async16(smem_u32(&As[r * 40 + cx * 8]),
                       &g_ogh[(size_t)(m0 + r) * HD + k0 + cx * 8]);
        }
#pragma unroll
        for (int it = 0; it < 2; it++) {
            int cidx = tid + it * 128;
            int k2 = cidx >> 4, n4 = cidx & 15;
            const float* w0 = &W[(size_t)(k0 + 2 * k2) * CQ + n0 + n4 * 4];
            float4 r0 = *(const float4*)w0;
            float4 r1 = *(const float4*)(w0 + CQ);
            uint4 pk;
            pk.x = packh2(r0.x, r1.x); pk.y = packh2(r0.y, r1.y);
            pk.z = packh2(r0.z, r1.z); pk.w = packh2(r0.w, r1.w);
            *(uint4*)&Bs[k2 * 72 + n4 * 4] = pk;
        }
        cp_async_wait_all();
        __syncthreads();
#pragma unroll
        for (int s = 0; s < 2; s++) {
            uint32_t a[2][4];
#pragma unroll
            for (int mt = 0; mt < 2; mt++) {
                int ar = mw0 + mt * 16 + lr;
                a[mt][0] = *(const uint32_t*)&As[ar * 40 + s * 16 + 2 * lc];
                a[mt][1] = *(const uint32_t*)&As[(ar + 8) * 40 + s * 16 + 2 * lc];
                a[mt][2] = *(const uint32_t*)&As[ar * 40 + s * 16 + 8 + 2 * lc];
                a[mt][3] = *(const uint32_t*)&As[(ar + 8) * 40 + s * 16 + 8 + 2 * lc];
            }
#pragma unroll
            for (int nt = 0; nt < 4; nt++) {
                int bn = nw0 + nt * 8 + lr;
                uint32_t b[2];
                b[0] = Bs[(s * 8 + lc) * 72 + bn];
                b[1] = Bs[(s * 8 + 4 + lc) * 72 + bn];
                mma_f16(acc[0][nt], a[0], b);
                mma_f16(acc[1][nt], a[1], b);
            }
        }
        __syncthreads();
    }

#pragma unroll
    for (int mt = 0; mt < 2; mt++) {
#pragma unroll
        for (int nt = 0; nt < 4; nt++) {
            int cc = n0 + nw0 + nt * 8 + 2 * lc;
            float b0 = bo[cc], b1 = bo[cc + 1];
#pragma unroll
            for (int half = 0; half < 2; half++) {
                int r = m0 + mw0 + mt * 16 + lr + half * 8;
                float2 o2;
                o2.x = acc[mt][nt][half * 2 + 0] + b0;
                o2.y = acc[mt][nt][half * 2 + 1] + b1;
                *(float2*)&out[r * CQ + cc] = o2;
            }
        }
    }
}

// ===========================================================================
extern "C" void kernel_launch(void* const* d_in, const int* in_sizes, int n_in,
                              void* d_out, int out_size)
{
    const float* a    = (const float*)d_in[0];
    const float* z    = (const float*)d_in[1];
    const float* mask = (const float*)d_in[2];
    const float* g_a  = (const float*)d_in[3];
    const float* b_a  = (const float*)d_in[4];
    const float* g_z  = (const float*)d_in[5];
    const float* b_z  = (const float*)d_in[6];
    const float* w_z  = (const float*)d_in[7];
    const float* w_q  = (const float*)d_in[8];
    const float* w_k  = (const float*)d_in[9];
    const float* w_v  = (const float*)d_in[10];
    const float* w_g  = (const float*)d_in[11];
    const float* b_g  = (const float*)d_in[12];
    const float* w_o  = (const float*)d_in[13];
    const float* b_o  = (const float*)d_in[14];
    float* out = (float*)d_out;

    ln_a_kernel<<<NTOK + 1, 256>>>(a, g_a, b_a, g_z, b_z, w_z);
    fused_pp_kernel<<<PROJ_BLOCKS + 16384, 128>>>(z, w_q, w_k, w_v, w_g, b_g);
    attn_kernel<<<dim3(16, NH, NSPLIT), 128>>>(mask);
    merge_kernel<<<NTOK, 256>>>();
    outproj_kernel<<<dim3(12, 16), 128>>>(w_o, b_o, out);
}

// round 17
// speedup vs baseline: 4.3679x; 1.0148x over previous
#include <cuda_runtime.h>
#include <cuda_fp16.h>
#include <math.h>
#include <stdint.h>

#define NTOK 1024
#define CQ   768
#define CZ   128
#define NH   16
#define DH   48
#define HD   768
#define EPSV 1e-5f
#define INFV 1.0e9f
#define NSPLIT 4
#define PROJ_BLOCKS 384          // 24 n-tiles x 16 m-tiles

// ------------- static device scratch (no allocations allowed) -------------
__device__ __align__(16) __half   g_anh[NTOK * CQ];      // fp16 LN(a)
__device__ __align__(16) __half   g_qh[NTOK * HD];       // fp16 Q (scaled)
__device__ __align__(16) uint32_t g_kp[(HD / 2) * NTOK]; // half2 K (d,d+1) [d2][tok]
__device__ __align__(16) __half   g_vh[HD * NTOK];       // fp16 V^T [h*DH+d][tok]
__device__ float g_g [NTOK * HD];
__device__ __align__(16) __half   g_ogh[NTOK * HD];      // fp16 gated attn out
__device__ __align__(16) __half g_biash[(size_t)NH * NTOK * NTOK];  // 32 MB
__device__ float g_po[NSPLIT * NH * NTOK * DH];
__device__ float g_pm[NSPLIT * NH * NTOK];
__device__ float g_pl[NSPLIT * NH * NTOK];
__device__ __align__(16) uint32_t g_wgt[NH * 144];  // tf32 wg, fragment-quad
__device__ float g_Svec[NH], g_Bcvec[NH];

// ------------------------- mma helpers -------------------------------
__device__ __forceinline__ uint32_t f2tf32(float f) {
    uint32_t r;
    asm("cvt.rna.tf32.f32 %0, %1;" : "=r"(r) : "f"(f));
    return r;
}
__device__ __forceinline__ void mma_tf32(float* d, const uint32_t* a, const uint32_t* b) {
    asm("mma.sync.aligned.m16n8k8.row.col.f32.tf32.tf32.f32 "
        "{%0,%1,%2,%3}, {%4,%5,%6,%7}, {%8,%9}, {%0,%1,%2,%3};"
        : "+f"(d[0]), "+f"(d[1]), "+f"(d[2]), "+f"(d[3])
        : "r"(a[0]), "r"(a[1]), "r"(a[2]), "r"(a[3]), "r"(b[0]), "r"(b[1]));
}
__device__ __forceinline__ void mma_f16(float* d, const uint32_t* a, const uint32_t* b) {
    asm("mma.sync.aligned.m16n8k16.row.col.f32.f16.f16.f32 "
        "{%0,%1,%2,%3}, {%4,%5,%6,%7}, {%8,%9}, {%0,%1,%2,%3};"
        : "+f"(d[0]), "+f"(d[1]), "+f"(d[2]), "+f"(d[3])
        : "r"(a[0]), "r"(a[1]), "r"(a[2]), "r"(a[3]), "r"(b[0]), "r"(b[1]));
}
__device__ __forceinline__ uint32_t packh2(float lo, float hi) {
    __half2 h = __floats2half2_rn(lo, hi);
    return *(uint32_t*)&h;
}
__device__ __forceinline__ uint32_t smem_u32(const void* p) {
    uint32_t r;
    asm("{.reg .u64 t; cvta.to.shared.u64 t, %1; cvt.u32.u64 %0, t;}" : "=r"(r) : "l"(p));
    return r;
}
__device__ __forceinline__ void cp_async16(uint32_t dst, const void* src) {
    asm volatile("cp.async.cg.shared.global [%0], [%1], 16;" :: "r"(dst), "l"(src));
}
__device__ __forceinline__ void cp_async_wait_all() {
    asm volatile("cp.async.commit_group;\n cp.async.wait_group 0;" ::: "memory");
}

// ===========================================================================
// Kernel 1: LayerNorm(a) -> g_anh fp16. Warp-per-row, no barriers.
// Grid 129: blocks 0..127 handle 8 rows each; block 128 = pb setup.
// ===========================================================================
__global__ __launch_bounds__(256) void ln_a_kernel(const float* __restrict__ a,
                                                   const float* __restrict__ ga,
                                                   const float* __restrict__ ba,
                                                   const float* __restrict__ gz,
                                                   const float* __restrict__ bz,
                                                   const float* __restrict__ wz)
{
    int tid = threadIdx.x;
    if (blockIdx.x == 128) {
        for (int i = tid; i < NH * 144; i += 256) g_wgt[i] = 0u;
        __syncthreads();
        for (int i = tid; i < NH * CZ; i += 256) {
            int h = i >> 7, c = i & 127;
            int g = c >> 4, rem = c & 15;
            int lc = rem & 3, w = rem >> 2;
            g_wgt[h * 144 + lc * 36 + g * 4 + w] = f2tf32(gz[c] * wz[c * NH + h]);
        }
        if (tid < NH) {
            float S = 0.f, Bc = 0.f;
            for (int c = 0; c < CZ; c++) {
                S  += gz[c] * wz[c * NH + tid];
                Bc += bz[c] * wz[c * NH + tid];
            }
            g_Svec[tid] = S; g_Bcvec[tid] = Bc;
        }
        return;
    }
    int warp = tid >> 5, lane = tid & 31;
    int row = blockIdx.x * 8 + warp;
    const float4* x4 = (const float4*)(a + (size_t)row * CQ);

    float4 v[6];
    float s = 0.f, sq = 0.f;
#pragma unroll
    for (int i = 0; i < 6; i++) {
        v[i] = x4[lane + i * 32];
        s  += v[i].x + v[i].y + v[i].z + v[i].w;
        sq = fmaf(v[i].x, v[i].x, sq); sq = fmaf(v[i].y, v[i].y, sq);
        sq = fmaf(v[i].z, v[i].z, sq); sq = fmaf(v[i].w, v[i].w, sq);
    }
#pragma unroll
    for (int o = 16; o > 0; o >>= 1) {
        s  += __shfl_xor_sync(0xffffffffu, s, o);
        sq += __shfl_xor_sync(0xffffffffu, sq, o);
    }
    float mu  = s * (1.f / (float)CQ);
    float var = sq * (1.f / (float)CQ) - mu * mu;
    float rv  = rsqrtf(fmaxf(var, 0.f) + EPSV);

    const float4* ga4 = (const float4*)ga;
    const float4* ba4 = (const float4*)ba;
    uint2* o8 = (uint2*)(g_anh + (size_t)row * CQ);
#pragma unroll
    for (int i = 0; i < 6; i++) {
        int c4 = lane + i * 32;
        float4 g4 = ga4[c4], b4 = ba4[c4];
        uint2 pk;
        pk.x = packh2((v[i].x - mu) * rv * g4.x + b4.x,
                      (v[i].y - mu) * rv * g4.y + b4.y);
        pk.y = packh2((v[i].z - mu) * rv * g4.z + b4.z,
                      (v[i].w - mu) * rv * g4.w + b4.w);
        o8[c4] = pk;
    }
}

// ===========================================================================
// Proj body (fp16 m16n8k16, BM=64, BN=128, BK=32). Shared mem carved from raw.
// ===========================================================================
__device__ __forceinline__ void proj_body(unsigned char* smem_raw, int bx,
                                          const float* __restrict__ Wq,
                                          const float* __restrict__ Wk,
                                          const float* __restrict__ Wv,
                                          const float* __restrict__ Wg,
                                          const float* __restrict__ bg)
{
    __half*   As = (__half*)smem_raw;                  // 64*40 fp16 = 5120 B
    uint32_t* Bs = (uint32_t*)(smem_raw + 5120);       // 16*136 u32 = 8704 B

    int n0 = (bx % 24) * 128;
    int m0 = (bx / 24) * 64;
    int sel  = n0 / HD;
    int ncol = n0 - sel * HD;
    const float* W = (sel == 0) ? Wq : (sel == 1) ? Wk : (sel == 2) ? Wv : Wg;

    int tid  = threadIdx.x;
    int lane = tid & 31;
    int warp = tid >> 5;
    int wm = warp >> 1, wn = warp & 1;
    int mw0 = wm * 32, nw0 = wn * 64;
    int lr = lane >> 2, lc = lane & 3;

    float acc[2][8][4];
#pragma unroll
    for (int mt = 0; mt < 2; mt++)
#pragma unroll
        for (int nt = 0; nt < 8; nt++)
#pragma unroll
            for (int u = 0; u < 4; u++) acc[mt][nt][u] = 0.f;

    for (int k0 = 0; k0 < CQ; k0 += 32) {
#pragma unroll
        for (int it = 0; it < 2; it++) {
            int u = tid + it * 128;
            int r = u >> 2, cx = u & 3;
            cp_async16(smem_u32(&As[r * 40 + cx * 8]),
                       &g_anh[(size_t)(m0 + r) * CQ + k0 + cx * 8]);
        }
#pragma unroll
        for (int it = 0; it < 4; it++) {
            int cidx = tid + it * 128;
            int k2 = cidx >> 5, n4 = cidx & 31;
            const float* w0 = &W[(size_t)(k0 + 2 * k2) * HD + ncol + n4 * 4];
            float4 r0 = *(const float4*)w0;
            float4 r1 = *(const float4*)(w0 + HD);
            uint4 pk;
            pk.x = packh2(r0.x, r1.x); pk.y = packh2(r0.y, r1.y);
            pk.z = packh2(r0.z, r1.z); pk.w = packh2(r0.w, r1.w);
            *(uint4*)&Bs[k2 * 136 + n4 * 4] = pk;
        }
        cp_async_wait_all();
        __syncthreads();
#pragma unroll
        for (int s = 0; s < 2; s++) {
            uint32_t a[2][4];
#pragma unroll
            for (int mt = 0; mt < 2; mt++) {
                int ar = mw0 + mt * 16 + lr;
                a[mt][0] = *(const uint32_t*)&As[ar * 40 + s * 16 + 2 * lc];
                a[mt][1] = *(const uint32_t*)&As[(ar + 8) * 40 + s * 16 + 2 * lc];
                a[mt][2] = *(const uint32_t*)&As[ar * 40 + s * 16 + 8 + 2 * lc];
                a[mt][3] = *(const uint32_t*)&As[(ar + 8) * 40 + s * 16 + 8 + 2 * lc];
            }
#pragma unroll
            for (int nt = 0; nt < 8; nt++) {
                int bn = nw0 + nt * 8 + lr;
                uint32_t b[2];
                b[0] = Bs[(s * 8 + lc) * 136 + bn];
                b[1] = Bs[(s * 8 + 4 + lc) * 136 + bn];
                mma_f16(acc[0][nt], a[0], b);
                mma_f16(acc[1][nt], a[1], b);
            }
        }
        __syncthreads();
    }

    const float scaleq = 0.14433756729740643f;
#pragma unroll
    for (int mt = 0; mt < 2; mt++) {
#pragma unroll
        for (int nt = 0; nt < 8; nt++) {
            int cc = ncol + nw0 + nt * 8 + 2 * lc;
#pragma unroll
            for (int half = 0; half < 2; half++) {
                int r = m0 + mw0 + mt * 16 + lr + half * 8;
                float v0 = acc[mt][nt][half * 2 + 0];
                float v1 = acc[mt][nt][half * 2 + 1];
                if (sel == 0) {
                    *(uint32_t*)&g_qh[r * HD + cc] = packh2(v0 * scaleq, v1 * scaleq);
                } else if (sel == 1) {
                    g_kp[(cc >> 1) * NTOK + r] = packh2(v0, v1);
                } else if (sel == 2) {
                    g_vh[cc * NTOK + r]       = __float2half_rn(v0);
                    g_vh[(cc + 1) * NTOK + r] = __float2half_rn(v1);
                } else {
                    float2 o2;
                    o2.x = 1.f / (1.f + __expf(-(v0 + bg[cc])));
                    o2.y = 1.f / (1.f + __expf(-(v1 + bg[cc + 1])));
                    *(float2*)&g_g[r * HD + cc] = o2;
                }
            }
        }
    }
}

// ===========================================================================
// Pairbias body (tf32 mma + fused LN, fp16 bias out). Shared carved from raw.
// ===========================================================================
__device__ __forceinline__ void pairbias_body(unsigned char* smem_raw, int idx,
                                              const float* __restrict__ z)
{
    float*    ztf = (float*)smem_raw;                   // 64*132 f32 = 33792 B
    uint32_t* wgt = (uint32_t*)(smem_raw + 33792);      // 2304 u32  =  9216 B
    float*    Ssh = (float*)(smem_raw + 43008);         // 16
    float*    Bcsh= (float*)(smem_raw + 43072);         // 16
    float*    mus = (float*)(smem_raw + 43136);         // 64
    float*    rvs = (float*)(smem_raw + 43392);         // 64

    int tid  = threadIdx.x;
    int lane = tid & 31;
    int warp = tid >> 5;
    int i  = idx >> 4;
    int j0 = (idx & 15) * 64;

    {
        const uint4* src = (const uint4*)g_wgt;
        for (int t2 = tid; t2 < 576; t2 += 128)
            cp_async16(smem_u32((uint4*)wgt + t2), src + t2);
    }
    const float4* zb = (const float4*)(z + ((size_t)i * NTOK + j0) * CZ);
#pragma unroll
    for (int u = 0; u < 16; u++) {
        int iidx = tid + 128 * u;
        int r = iidx >> 5;
        cp_async16(smem_u32(&ztf[r * 132 + lane * 4]), zb + iidx);
    }
    if (tid < NH) { Ssh[tid] = g_Svec[tid]; Bcsh[tid] = g_Bcvec[tid]; }
    cp_async_wait_all();
    __syncthreads();

    if (tid < 64) {
        float s = 0.f, sq = 0.f;
        const float* zr = &ztf[tid * 132];
#pragma unroll
        for (int cq = 0; cq < 32; cq++) {
            float4 w = *(const float4*)&zr[cq * 4];
            s += w.x + w.y + w.z + w.w;
            sq = fmaf(w.x, w.x, sq); sq = fmaf(w.y, w.y, sq);
            sq = fmaf(w.z, w.z, sq); sq = fmaf(w.w, w.w, sq);
        }
        float mu  = s * (1.f / (float)CZ);
        float var = sq * (1.f / (float)CZ) - mu * mu;
        mus[tid] = mu;
        rvs[tid] = rsqrtf(fmaxf(var, 0.f) + EPSV);
    }

    int m0 = warp * 16;
    int lr = lane >> 2, lc = lane & 3;
    float acc[2][4];
#pragma unroll
    for (int n = 0; n < 2; n++)
#pragma unroll
        for (int u = 0; u < 4; u++) acc[n][u] = 0.f;

    const uint32_t* wgt0 = &wgt[lr * 144 + lc * 36];
    const uint32_t* wgt1 = &wgt[(8 + lr) * 144 + lc * 36];
#pragma unroll
    for (int g = 0; g < 8; g++) {
        uint4 bq0 = *(const uint4*)(wgt0 + g * 4);
        uint4 bq1 = *(const uint4*)(wgt1 + g * 4);
#pragma unroll
        for (int kh = 0; kh < 2; kh++) {
            int kk = (g * 2 + kh) * 8;
            int ar = m0 + lr, ac = kk + lc;
            uint32_t a[4];
            a[0] = f2tf32(ztf[ar * 132 + ac]);
            a[1] = f2tf32(ztf[(ar + 8) * 132 + ac]);
            a[2] = f2tf32(ztf[ar * 132 + ac + 4]);
            a[3] = f2tf32(ztf[(ar + 8) * 132 + ac + 4]);
            uint32_t b0[2], b1[2];
            b0[0] = kh ? bq0.z : bq0.x;  b0[1] = kh ? bq0.w : bq0.y;
            b1[0] = kh ? bq1.z : bq1.x;  b1[1] = kh ? bq1.w : bq1.y;
            mma_tf32(acc[0], a, b0);
            mma_tf32(acc[1], a, b1);
        }
    }
    __syncthreads();

    float* outs = ztf;                    // [h][j], stride 68
#pragma unroll
    for (int n = 0; n < 2; n++) {
        int h0 = n * 8 + 2 * lc;
#pragma unroll
        for (int half = 0; half < 2; half++) {
            int r = m0 + lr + half * 8;
            float mu = mus[r], rv = rvs[r];
            outs[h0 * 68 + r]       = rv * (acc[n][half * 2 + 0] - mu * Ssh[h0])     + Bcsh[h0];
            outs[(h0 + 1) * 68 + r] = rv * (acc[n][half * 2 + 1] - mu * Ssh[h0 + 1]) + Bcsh[h0 + 1];
        }
    }
    __syncthreads();
    {
        int h = tid >> 3, j8 = (tid & 7) * 8;
        const float* src = &outs[h * 68 + j8];
        uint4 pk;
        pk.x = packh2(src[0], src[1]);
        pk.y = packh2(src[2], src[3]);
        pk.z = packh2(src[4], src[5]);
        pk.w = packh2(src[6], src[7]);
        *(uint4*)&g_biash[((size_t)h * NTOK + i) * NTOK + j0 + j8] = pk;
    }
}

// ===========================================================================
// Kernel 2+3 fused: blocks [0, 384) run proj, [384, 16768) run pairbias.
// __launch_bounds__(128, 5): cap regs ~102 so pairbias gets 5 blocks/SM
// (smem 43.6KB x 5 = 218KB <= 228KB). proj branch may spill slightly (2.3%
// of blocks) — pairbias DRAM overlap dominates.
// ===========================================================================
__global__ __launch_bounds__(128, 5) void fused_pp_kernel(const float* __restrict__ z,
                                                          const float* __restrict__ Wq,
                                                          const float* __restrict__ Wk,
                                                          const float* __restrict__ Wv,
                                                          const float* __restrict__ Wg,
                                                          const float* __restrict__ bg)
{
    __shared__ __align__(16) unsigned char smem_raw[43648];
    int bx = blockIdx.x;
    if (bx < PROJ_BLOCKS) {
        proj_body(smem_raw, bx, Wq, Wk, Wv, Wg, bg);
    } else {
        pairbias_body(smem_raw, bx - PROJ_BLOCKS, z);
    }
}

// ===========================================================================
// Kernel 4: flash attention, all-fp16 tensor path. (R13, unchanged)
// ===========================================================================
__global__ __launch_bounds__(128) void attn_kernel(const float* __restrict__ mask)
{
    int h     = blockIdx.y;
    int qb    = blockIdx.x * 64;
    int split = blockIdx.z;
    int tid  = threadIdx.x;
    int lane = tid & 31;
    int warp = tid >> 5;
    int lr = lane >> 2, lc = lane & 3;
    int m0 = warp * 16;

    __shared__ __align__(16) __half   qs[64 * 56];
    __shared__ __align__(16) uint32_t ks2[24 * 72];
    __shared__ __align__(16) uint32_t vsh[48 * 36];

#pragma unroll
    for (int it = 0; it < 3; it++) {
        int u = tid + it * 128;
        int row = u / 6, cx = u % 6;
        cp_async16(smem_u32(&qs[row * 56 + cx * 8]),
                   &g_qh[(size_t)(qb + row) * HD + h * DH + cx * 8]);
    }

    float mrow0 = -1e30f, mrow1 = -1e30f, lrow0 = 0.f, lrow1 = 0.f;
    float oacc[6][4];
#pragma unroll
    for (int vt = 0; vt < 6; vt++)
#pragma unroll
        for (int u = 0; u < 4; u++) oacc[vt][u] = 0.f;

    float mq0 = mask[qb + m0 + lr];
    float mq1 = mask[qb + m0 + lr + 8];

    for (int jt = split * 4; jt < split * 4 + 4; jt++) {
        int j0 = jt * 64;
        __syncthreads();
#pragma unroll
        for (int it = 0; it < 3; it++) {
            int u = tid + it * 128;
            int row = u >> 4, cx = u & 15;
            cp_async16(smem_u32(&ks2[row * 72 + cx * 4]),
                       &g_kp[(size_t)(h * (DH / 2) + row) * NTOK + j0 + cx * 4]);
        }
#pragma unroll
        for (int it = 0; it < 3; it++) {
            int u = tid + it * 128;
            int row = u >> 3, cx = u & 7;
            cp_async16(smem_u32(&vsh[row * 36 + cx * 4]),
                       &g_vh[(size_t)(h * DH + row) * NTOK + j0 + cx * 8]);
        }
        cp_async_wait_all();
        __syncthreads();

        float sacc[8][4];
#pragma unroll
        for (int nt = 0; nt < 8; nt++)
#pragma unroll
            for (int u = 0; u < 4; u++) sacc[nt][u] = 0.f;
#pragma unroll
        for (int s = 0; s < 3; s++) {
            int ar = m0 + lr;
            uint32_t a[4];
            a[0] = *(const uint32_t*)&qs[ar * 56 + (s * 8 + lc) * 2];
            a[1] = *(const uint32_t*)&qs[(ar + 8) * 56 + (s * 8 + lc) * 2];
            a[2] = *(const uint32_t*)&qs[ar * 56 + (s * 8 + 4 + lc) * 2];
            a[3] = *(const uint32_t*)&qs[(ar + 8) * 56 + (s * 8 + 4 + lc) * 2];
#pragma unroll
            for (int nt = 0; nt < 8; nt++) {
                uint32_t b[2];
                b[0] = ks2[(s * 8 + lc) * 72 + nt * 8 + lr];
                b[1] = ks2[(s * 8 + 4 + lc) * 72 + nt * 8 + lr];
                mma_f16(sacc[nt], a, b);
            }
        }

        float rmax0 = -1e30f, rmax1 = -1e30f;
        const __half* bias0 = &g_biash[((size_t)h * NTOK + qb + m0 + lr) * NTOK];
        const __half* bias1 = &g_biash[((size_t)h * NTOK + qb + m0 + lr + 8) * NTOK];
#pragma unroll
        for (int nt = 0; nt < 8; nt++) {
            int jc = j0 + nt * 8 + 2 * lc;
            float2 b0 = __half22float2(*(const __half2*)&bias0[jc]);
            float2 b1 = __half22float2(*(const __half2*)&bias1[jc]);
            float mk0 = mask[jc], mk1 = mask[jc + 1];
            sacc[nt][0] += b0.x + INFV * (mq0 * mk0 - 1.f);
            sacc[nt][1] += b0.y + INFV * (mq0 * mk1 - 1.f);
            sacc[nt][2] += b1.x + INFV * (mq1 * mk0 - 1.f);
            sacc[nt][3] += b1.y + INFV * (mq1 * mk1 - 1.f);
            rmax0 = fmaxf(rmax0, fmaxf(sacc[nt][0], sacc[nt][1]));
            rmax1 = fmaxf(rmax1, fmaxf(sacc[nt][2], sacc[nt][3]));
        }
#pragma unroll
        for (int off = 1; off < 4; off <<= 1) {
            rmax0 = fmaxf(rmax0, __shfl_xor_sync(0xffffffffu, rmax0, off));
            rmax1 = fmaxf(rmax1, __shfl_xor_sync(0xffffffffu, rmax1, off));
        }
        float mnew0 = fmaxf(mrow0, rmax0);
        float mnew1 = fmaxf(mrow1, rmax1);
        float scale0 = __expf(mrow0 - mnew0);
        float scale1 = __expf(mrow1 - mnew1);

        float sum0 = 0.f, sum1 = 0.f;
        uint32_t ph[8][2];
#pragma unroll
        for (int nt = 0; nt < 8; nt++) {
            sacc[nt][0] = __expf(sacc[nt][0] - mnew0);
            sacc[nt][1] = __expf(sacc[nt][1] - mnew0);
            sacc[nt][2] = __expf(sacc[nt][2] - mnew1);
            sacc[nt][3] = __expf(sacc[nt][3] - mnew1);
            sum0 += sacc[nt][0] + sacc[nt][1];
            sum1 += sacc[nt][2] + sacc[nt][3];
            ph[nt][0] = packh2(sacc[nt][0], sacc[nt][1]);
            ph[nt][1] = packh2(sacc[nt][2], sacc[nt][3]);
        }
#pragma unroll
        for (int off = 1; off < 4; off <<= 1) {
            sum0 += __shfl_xor_sync(0xffffffffu, sum0, off);
            sum1 += __shfl_xor_sync(0xffffffffu, sum1, off);
        }
        lrow0 = lrow0 * scale0 + sum0;  mrow0 = mnew0;
        lrow1 = lrow1 * scale1 + sum1;  mrow1 = mnew1;
#pragma unroll
        for (int vt = 0; vt < 6; vt++) {
            oacc[vt][0] *= scale0; oacc[vt][1] *= scale0;
            oacc[vt][2] *= scale1; oacc[vt][3] *= scale1;
        }

#pragma unroll
        for (int ks4 = 0; ks4 < 4; ks4++) {
            uint32_t a[4];
            a[0] = ph[ks4 * 2][0];
            a[1] = ph[ks4 * 2][1];
            a[2] = ph[ks4 * 2 + 1][0];
            a[3] = ph[ks4 * 2 + 1][1];
#pragma unroll
            for (int vt = 0; vt < 6; vt++) {
                int d = vt * 8 + lr;
                uint32_t b[2];
                b[0] = vsh[d * 36 + ks4 * 8 + lc];
                b[1] = vsh[d * 36 + ks4 * 8 + 4 + lc];
                mma_f16(oacc[vt], a, b);
            }
        }
    }

    int q0 = qb + m0 + lr, q1 = q0 + 8;
    int pb0 = ((split * NH + h) * NTOK + q0) * DH;
    int pb1 = ((split * NH + h) * NTOK + q1) * DH;
#pragma unroll
    for (int vt = 0; vt < 6; vt++) {
        int d = vt * 8 + 2 * lc;
        *(float2*)&g_po[pb0 + d] = make_float2(oacc[vt][0], oacc[vt][1]);
        *(float2*)&g_po[pb1 + d] = make_float2(oacc[vt][2], oacc[vt][3]);
    }
    if (lc == 0) {
        g_pm[(split * NH + h) * NTOK + q0] = mrow0;
        g_pl[(split * NH + h) * NTOK + q0] = lrow0;
        g_pm[(split * NH + h) * NTOK + q1] = mrow1;
        g_pl[(split * NH + h) * NTOK + q1] = lrow1;
    }
}

// ===========================================================================
// Kernel 4b: merge 4 splits, normalize, apply gate -> g_ogh (fp16).
// ===========================================================================
__global__ __launch_bounds__(256) void merge_kernel()
{
    int q = blockIdx.x;
    int t = threadIdx.x;
    int h = t >> 4;
    int d0 = (t & 15) * 3;

    float m[NSPLIT], l[NSPLIT];
    float M = -1e30f;
#pragma unroll
    for (int s = 0; s < NSPLIT; s++) {
        m[s] = g_pm[(s * NH + h) * NTOK + q];
        l[s] = g_pl[(s * NH + h) * NTOK + q];
        M = fmaxf(M, m[s]);
    }
    float w[NSPLIT], ltot = 0.f;
#pragma unroll
    for (int s = 0; s < NSPLIT; s++) {
        w[s] = __expf(m[s] - M);
        ltot += l[s] * w[s];
    }
    float inv = 1.f / ltot;
    int go = q * HD + h * DH + d0;
#pragma unroll
    for (int u = 0; u < 3; u++) {
        float val = 0.f;
#pragma unroll
        for (int s = 0; s < NSPLIT; s++)
            val += g_po[((s * NH + h) * NTOK + q) * DH + d0 + u] * w[s];
        g_ogh[go + u] = __float2half_rn(val * inv * g_g[go + u]);
    }
}

// ===========================================================================
// Kernel 5: output projection via fp16 m16n8k16. BM=64, BN=64, BK=32. (R14)
// ===========================================================================
__global__ __launch_bounds__(128) void outproj_kernel(const float* __restrict__ W,
                                                      const float* __restrict__ bo,
                                                      float* __restrict__ out)
{
    int n0 = blockIdx.x * 64;
    int m0 = blockIdx.y * 64;

    __shared__ __align__(16) __half   As[64 * 40];
    __shared__ __align__(16) uint32_t Bs[16 * 72];

    int tid  = threadIdx.x;
    int lane = tid & 31;
    int warp = tid >> 5;
    int wm = warp >> 1, wn = warp & 1;
    int mw0 = wm * 32, nw0 = wn * 32;
    int lr = lane >> 2, lc = lane & 3;

    float acc[2][4][4];
#pragma unroll
    for (int mt = 0; mt < 2; mt++)
#pragma unroll
        for (int nt = 0; nt < 4; nt++)
#pragma unroll
            for (int u = 0; u < 4; u++) acc[mt][nt][u] = 0.f;

    for (int k0 = 0; k0 < HD; k0 += 32) {
#pragma unroll
        for (int it = 0; it < 2; it++) {
            int u = tid + it * 128;
            int r = u >> 2, cx = u & 3;
            cp_async16(smem_u32(&As[r * 40 + cx * 8]),
                       &g_ogh[(size_t)(m0 + r) * HD + k0 + cx * 8]);
        }
#pragma unroll
        for (int it = 0; it < 2; it++) {
            int cidx = tid + it * 128;
            int k2 = cidx >> 4, n4 = cidx & 15;
            const float* w0 = &W[(size_t)(k0 + 2 * k2) * CQ + n0 + n4 * 4];
            float4 r0 = *(const float4*)w0;
            float4 r1 = *(const float4*)(w0 + CQ);
            uint4 pk;
            pk.x = packh2(r0.x, r1.x); pk.y = packh2(r0.y, r1.y);
            pk.z = packh2(r0.z, r1.z); pk.w = packh2(r0.w, r1.w);
            *(uint4*)&Bs[k2 * 72 + n4 * 4] = pk;
        }
        cp_async_wait_all();
        __syncthreads();
#pragma unroll
        for (int s = 0; s < 2; s++) {
            uint32_t a[2][4];
#pragma unroll
            for (int mt = 0; mt < 2; mt++) {
                int ar = mw0 + mt * 16 + lr;
                a[mt][0] = *(const uint32_t*)&As[ar * 40 + s * 16 + 2 * lc];
                a[mt][1] = *(const uint32_t*)&As[(ar + 8) * 40 + s * 16 + 2 * lc];
                a[mt][2] = *(const uint32_t*)&As[ar * 40 + s * 16 + 8 + 2 * lc];
                a[mt][3] = *(const uint32_t*)&As[(ar + 8) * 40 + s * 16 + 8 + 2 * lc];
            }
#pragma unroll
            for (int nt = 0; nt < 4; nt++) {
                int bn = nw0 + nt * 8 + lr;
                uint32_t b[2];
                b[0] = Bs[(s * 8 + lc) * 72 + bn];
                b[1] = Bs[(s * 8 + 4 + lc) * 72 + bn];
                mma_f16(acc[0][nt], a[0], b);
                mma_f16(acc[1][nt], a[1], b);
            }
        }
        __syncthreads();
    }

#pragma unroll
    for (int mt = 0; mt < 2; mt++) {
#pragma unroll
        for (int nt = 0; nt < 4; nt++) {
            int cc = n0 + nw0 + nt * 8 + 2 * lc;
            float b0 = bo[cc], b1 = bo[cc + 1];
#pragma unroll
            for (int half = 0; half < 2; half++) {
                int r = m0 + mw0 + mt * 16 + lr + half * 8;
                float2 o2;
                o2.x = acc[mt][nt][half * 2 + 0] + b0;
                o2.y = acc[mt][nt][half * 2 + 1] + b1;
                *(float2*)&out[r * CQ + cc] = o2;
            }
        }
    }
}

// ===========================================================================
extern "C" void kernel_launch(void* const* d_in, const int* in_sizes, int n_in,
                              void* d_out, int out_size)
{
    const float* a    = (const float*)d_in[0];
    const float* z    = (const float*)d_in[1];
    const float* mask = (const float*)d_in[2];
    const float* g_a  = (const float*)d_in[3];
    const float* b_a  = (const float*)d_in[4];
    const float* g_z  = (const float*)d_in[5];
    const float* b_z  = (const float*)d_in[6];
    const float* w_z  = (const float*)d_in[7];
    const float* w_q  = (const float*)d_in[8];
    const float* w_k  = (const float*)d_in[9];
    const float* w_v  = (const float*)d_in[10];
    const float* w_g  = (const float*)d_in[11];
    const float* b_g  = (const float*)d_in[12];
    const float* w_o  = (const float*)d_in[13];
    const float* b_o  = (const float*)d_in[14];
    float* out = (float*)d_out;

    ln_a_kernel<<<129, 256>>>(a, g_a, b_a, g_z, b_z, w_z);
    fused_pp_kernel<<<PROJ_BLOCKS + 16384, 128>>>(z, w_q, w_k, w_v, w_g, b_g);
    attn_kernel<<<dim3(16, NH, NSPLIT), 128>>>(mask);
    merge_kernel<<<NTOK, 256>>>();
    outproj_kernel<<<dim3(12, 16), 128>>>(w_o, b_o, out);
}